// round 9
// baseline (speedup 1.0000x reference)
#include <cuda_runtime.h>
#include <cuda_bf16.h>
#include <math.h>

#define BB 8
#define LL 2048
#define DD 1024
#define FF 4096
#define MM 16384
#define TOPK 7
#define LMASK 2047

typedef unsigned short u16;
typedef unsigned int   u32;

// ---------------- device scratch (row-major bf16 hi/lo) -------------------
__device__ u16 t_x_hi[(size_t)MM*DD],  t_x_lo[(size_t)MM*DD];
__device__ u16 t_q_hi[(size_t)MM*DD],  t_q_lo[(size_t)MM*DD];
__device__ u16 t_k_hi[(size_t)MM*DD],  t_k_lo[(size_t)MM*DD];
__device__ u16 t_r_hi[(size_t)MM*DD],  t_r_lo[(size_t)MM*DD];
__device__ u16 t_x1_hi[(size_t)MM*DD], t_x1_lo[(size_t)MM*DD];
__device__ u16 t_h_hi[(size_t)MM*FF],  t_h_lo[(size_t)MM*FF];
__device__ u16 t_wq_hi[DD*DD], t_wq_lo[DD*DD];
__device__ u16 t_wk_hi[DD*DD], t_wk_lo[DD*DD];
__device__ u16 t_wv_hi[DD*DD], t_wv_lo[DD*DD];
__device__ u16 t_wo_hi[DD*DD], t_wo_lo[DD*DD];
__device__ u16 t_c1_hi[(size_t)FF*DD], t_c1_lo[(size_t)FF*DD];
__device__ u16 t_c2_hi[(size_t)DD*FF], t_c2_lo[(size_t)DD*FF];

__device__ float g_v[(size_t)MM*DD];     // v; later reused for y
__device__ float g_G[(size_t)BB*LL*LL];  // Gram; later reused for attn
__device__ float g_x1[(size_t)MM*DD];
__device__ float g_part[BB*8*LL];
__device__ float g_mv[BB*LL];
__device__ float g_w[BB*8];
__device__ int   g_delay[8];

// ---------------- helpers --------------------------------------------------
__device__ __forceinline__ u32 smem_u32(const void* p) {
    u32 a;
    asm("{ .reg .u64 t; cvta.to.shared.u64 t, %1; cvt.u32.u64 %0, t; }"
        : "=r"(a) : "l"(p));
    return a;
}

__device__ __forceinline__ void split2(float v0, float v1, u32& h, u32& l) {
    __nv_bfloat16 h0 = __float2bfloat16(v0), h1 = __float2bfloat16(v1);
    __nv_bfloat16 l0 = __float2bfloat16(v0 - __bfloat162float(h0));
    __nv_bfloat16 l1 = __float2bfloat16(v1 - __bfloat162float(h1));
    h = (u32)__bfloat16_as_ushort(h0) | ((u32)__bfloat16_as_ushort(h1) << 16);
    l = (u32)__bfloat16_as_ushort(l0) | ((u32)__bfloat16_as_ushort(l1) << 16);
}

__device__ __forceinline__ void split_pack8(const float* v, uint4& hv, uint4& lv) {
    u32 h[4], l[4];
    #pragma unroll
    for (int p = 0; p < 4; p++) split2(v[2*p], v[2*p+1], h[p], l[p]);
    hv = make_uint4(h[0], h[1], h[2], h[3]);
    lv = make_uint4(l[0], l[1], l[2], l[3]);
}

#define CPA(sa, gp) \
    asm volatile("cp.async.cg.shared.global [%0], [%1], 16;" \
        :: "r"(sa), "l"(gp))

#define MMA(c, a, b) \
    asm volatile("mma.sync.aligned.m16n8k16.row.col.f32.bf16.bf16.f32 " \
        "{%0,%1,%2,%3},{%4,%5,%6,%7},{%8,%9},{%0,%1,%2,%3};" \
        : "+f"((c)[0]), "+f"((c)[1]), "+f"((c)[2]), "+f"((c)[3]) \
        : "r"((a)[0]), "r"((a)[1]), "r"((a)[2]), "r"((a)[3]), \
          "r"((b)[0]), "r"((b)[1]))

#define LDSM4(r0, r1, r2, r3, a) \
    asm volatile("ldmatrix.sync.aligned.m8n8.x4.shared.b16 {%0,%1,%2,%3}, [%4];" \
        : "=r"(r0), "=r"(r1), "=r"(r2), "=r"(r3) : "r"(a))

// ---------------- GEMM: C[M,N] = A[M,K] @ B[N,K]^T (+bias, +relu) ---------
// A,B = bf16 hi/lo row-major. 3-term compensated product, fp32 accum.
// CTA 256x128, 8 warps (4x2) x (64x64), K-chunk 32, 3-stage cp.async pipeline.
#define KC 32
#define PADH 40
#define OFF_AL 20480u   // 256*40*2
#define OFF_BH 40960u
#define OFF_BL 51200u
#define STAGE_B 61440u
#define GSMEM (3*61440)

template<int OMODE>  // 0 = fp32 out, 1 = split out, 2 = split+relu out
__global__ __launch_bounds__(256, 1) void gemm_mma(
    const u16* __restrict__ Ahi, const u16* __restrict__ Alo,
    const u16* __restrict__ Bhi, const u16* __restrict__ Blo,
    const float* __restrict__ bias, float* __restrict__ C,
    u16* __restrict__ Ohi, u16* __restrict__ Olo,
    int K, int ldc, int aRows, int bRows, size_t cBatch)
{
    extern __shared__ u16 sm[];
    const int tid = threadIdx.x;
    const int lane = tid & 31, warp = tid >> 5;   // warp 0..7
    const int wm = warp >> 1, wn = warp & 1;      // 4 x 2
    const int bx = blockIdx.x, by = blockIdx.y, bz = blockIdx.z;

    const u16* Ah = Ahi + (size_t)(bz * aRows + by * 256) * K;
    const u16* Al = Alo + (size_t)(bz * aRows + by * 256) * K;
    const u16* Bh = Bhi + (size_t)(bz * bRows + bx * 128) * K;
    const u16* Bl = Blo + (size_t)(bz * bRows + bx * 128) * K;

    const u32 smBase = smem_u32(sm);
    const int nC = K >> 5;

    float acc[4][8][4];
    #pragma unroll
    for (int i = 0; i < 4; i++)
        #pragma unroll
        for (int j = 0; j < 8; j++)
            #pragma unroll
            for (int p = 0; p < 4; p++) acc[i][j][p] = 0.f;

    auto load_chunk = [&](int c, int s) {
        u32 st = smBase + s * STAGE_B;
        int k0 = c * KC;
        // A: 256 rows x 4 x 16B -> 1024 ops, 4 iters of 256 thr
        #pragma unroll
        for (int t = 0; t < 4; t++) {
            int idx = (t << 8) + tid;
            int row = idx >> 2, c16 = idx & 3;
            size_t go = (size_t)row * K + k0 + c16 * 8;
            u32 so = st + (u32)(row * PADH + c16 * 8) * 2;
            CPA(so, Ah + go);
            CPA(so + OFF_AL, Al + go);
        }
        // B: 128 rows x 4 -> 512 ops, 2 iters
        #pragma unroll
        for (int t = 0; t < 2; t++) {
            int idx = (t << 8) + tid;
            int row = idx >> 2, c16 = idx & 3;
            size_t go = (size_t)row * K + k0 + c16 * 8;
            u32 so = st + OFF_BH + (u32)(row * PADH + c16 * 8) * 2;
            CPA(so, Bh + go);
            CPA(so + (OFF_BL - OFF_BH), Bl + go);
        }
        asm volatile("cp.async.commit_group;" ::: "memory");
    };

    load_chunk(0, 0);
    if (nC > 1) load_chunk(1, 1);

    for (int c = 0; c < nC; c++) {
        if (c == nC - 1) asm volatile("cp.async.wait_group 0;" ::: "memory");
        else             asm volatile("cp.async.wait_group 1;" ::: "memory");
        __syncthreads();
        if (c + 2 < nC) load_chunk(c + 2, (c + 2) % 3);

        u32 st = smBase + (u32)(c % 3) * STAGE_B;
        #pragma unroll
        for (int ks = 0; ks < 2; ks++) {
            int ko = ks * 16;
            int kk = ko + ((lane >> 4) << 3);
            // B fragments: 8 n-tiles, loaded as 4 x4-ldmatrix pairs (hi+lo)
            u32 b_h[8][2], b_l[8][2];
            #pragma unroll
            for (int p = 0; p < 4; p++) {
                int r = wn * 64 + p * 16 + (lane & 15);
                u32 ba = st + OFF_BH + (u32)(r * PADH + kk) * 2;
                LDSM4(b_h[2*p][0], b_h[2*p+1][0], b_h[2*p][1], b_h[2*p+1][1], ba);
                LDSM4(b_l[2*p][0], b_l[2*p+1][0], b_l[2*p][1], b_l[2*p+1][1],
                      ba + (OFF_BL - OFF_BH));
            }
            // A fragments per mi; 24 MMAs each
            #pragma unroll
            for (int mi = 0; mi < 4; mi++) {
                int r = wm * 64 + mi * 16 + (lane & 15);
                u32 aa = st + (u32)(r * PADH + kk) * 2;
                u32 a_h[4], a_l[4];
                LDSM4(a_h[0], a_h[1], a_h[2], a_h[3], aa);
                LDSM4(a_l[0], a_l[1], a_l[2], a_l[3], aa + OFF_AL);
                #pragma unroll
                for (int ni = 0; ni < 8; ni++) {
                    MMA(acc[mi][ni], a_h, b_h[ni]);
                    MMA(acc[mi][ni], a_h, b_l[ni]);
                    MMA(acc[mi][ni], a_l, b_h[ni]);
                }
            }
        }
    }

    // epilogue
    const int r0 = by * 256 + wm * 64;
    const int c0b = bx * 128 + wn * 64;
    #pragma unroll
    for (int mi = 0; mi < 4; mi++) {
        #pragma unroll
        for (int ni = 0; ni < 8; ni++) {
            int rA = r0 + mi * 16 + (lane >> 2);
            int cc = c0b + ni * 8 + (lane & 3) * 2;
            float v0 = acc[mi][ni][0], v1 = acc[mi][ni][1];
            float v2 = acc[mi][ni][2], v3 = acc[mi][ni][3];
            if (bias) {
                float bb0 = __ldg(bias + cc), bb1 = __ldg(bias + cc + 1);
                v0 += bb0; v1 += bb1; v2 += bb0; v3 += bb1;
            }
            if (OMODE == 2) {
                v0 = fmaxf(v0, 0.f); v1 = fmaxf(v1, 0.f);
                v2 = fmaxf(v2, 0.f); v3 = fmaxf(v3, 0.f);
            }
            if (OMODE == 0) {
                float* Cz = C + bz * cBatch;
                *(float2*)(Cz + (size_t)rA * ldc + cc)       = make_float2(v0, v1);
                *(float2*)(Cz + (size_t)(rA + 8) * ldc + cc) = make_float2(v2, v3);
            } else {
                u32 h0, l0, h1, l1;
                split2(v0, v1, h0, l0);
                split2(v2, v3, h1, l1);
                *(u32*)(Ohi + (size_t)rA * ldc + cc)       = h0;
                *(u32*)(Olo + (size_t)rA * ldc + cc)       = l0;
                *(u32*)(Ohi + (size_t)(rA + 8) * ldc + cc) = h1;
                *(u32*)(Olo + (size_t)(rA + 8) * ldc + cc) = l1;
            }
        }
    }
}

// ---------------- splits ---------------------------------------------------
__global__ __launch_bounds__(256) void split_x(
    const float* __restrict__ s, u16* __restrict__ hi, u16* __restrict__ lo)
{
    size_t i = ((size_t)blockIdx.x * 256 + threadIdx.x) * 4;
    float4 v = *(const float4*)(s + i);
    u32 h0, l0, h1, l1;
    split2(v.x, v.y, h0, l0);
    split2(v.z, v.w, h1, l1);
    *(uint2*)(hi + i) = make_uint2(h0, h1);
    *(uint2*)(lo + i) = make_uint2(l0, l1);
}

// W[K,N] row-major -> out[N,K] hi/lo (transpose + split)
__global__ __launch_bounds__(256) void wsplit(
    const float* __restrict__ W, u16* __restrict__ hi, u16* __restrict__ lo,
    int K, int N)
{
    __shared__ float t[32][33];
    int n0 = blockIdx.x * 32, k0 = blockIdx.y * 32;
    int tx = threadIdx.x & 31, ty = threadIdx.x >> 5;
    #pragma unroll
    for (int j = 0; j < 32; j += 8)
        t[ty + j][tx] = W[(size_t)(k0 + ty + j) * N + n0 + tx];
    __syncthreads();
    #pragma unroll
    for (int j = 0; j < 32; j += 8) {
        float v = t[tx][ty + j];
        __nv_bfloat16 h = __float2bfloat16(v);
        __nv_bfloat16 l = __float2bfloat16(v - __bfloat162float(h));
        size_t o = (size_t)(n0 + ty + j) * K + k0 + tx;
        hi[o] = __bfloat16_as_ushort(h);
        lo[o] = __bfloat16_as_ushort(l);
    }
}

// ---------------- lag / topk / roll / layernorm ---------------------------
__global__ void lag_partial()
{
    int b = blockIdx.z, tc = blockIdx.y;
    int l = blockIdx.x * 256 + threadIdx.x;
    const float* Gb = g_G + (size_t)b * LL * LL;
    int t0 = tc * 256;
    float s = 0.f;
    #pragma unroll 4
    for (int t = t0; t < t0 + 256; ++t)
        s += Gb[(size_t)t * LL + ((t - l) & LMASK)];
    g_part[(b * 8 + tc) * LL + l] = s;
}

__global__ void lag_reduce()
{
    int idx = blockIdx.x * 256 + threadIdx.x;
    int b = idx >> 11;
    float s = 0.f;
    #pragma unroll
    for (int tc = 0; tc < 8; tc++) s += g_part[(b * 8 + tc) * LL + (idx & LMASK)];
    g_mv[idx] = s * (1.f / (float)DD);
}

__global__ void topk_softmax()
{
    int b = blockIdx.x, tid = threadIdx.x;
    __shared__ float vals[LL];
    __shared__ float rv[256];
    __shared__ int   ri[256];
    __shared__ float topv[TOPK];
    __shared__ int   topi[TOPK];

    for (int i = tid; i < LL; i += 256) vals[i] = g_mv[b * LL + i];
    __syncthreads();
    for (int it = 0; it < TOPK; ++it) {
        float bv = -INFINITY; int bi = 0;
        for (int i = tid; i < LL; i += 256) {
            float v = vals[i];
            if (v > bv) { bv = v; bi = i; }
        }
        rv[tid] = bv; ri[tid] = bi;
        __syncthreads();
        for (int s = 128; s > 0; s >>= 1) {
            if (tid < s) {
                if (rv[tid+s] > rv[tid] ||
                    (rv[tid+s] == rv[tid] && ri[tid+s] < ri[tid])) {
                    rv[tid] = rv[tid+s]; ri[tid] = ri[tid+s];
                }
            }
            __syncthreads();
        }
        if (tid == 0) { topv[it] = rv[0]; topi[it] = ri[0]; vals[ri[0]] = -INFINITY; }
        __syncthreads();
    }
    if (tid == 0) {
        float mx = topv[0], e[TOPK], s = 0.f;
        #pragma unroll
        for (int i = 0; i < TOPK; i++) { e[i] = expf(topv[i] - mx); s += e[i]; }
        float inv = 1.f / s;
        #pragma unroll
        for (int i = 0; i < TOPK; i++) g_w[b * 8 + i] = e[i] * inv;
        if (b == 0)
            #pragma unroll
            for (int i = 0; i < TOPK; i++) g_delay[i] = topi[i];
    }
}

// rolled[b,l,:] = sum_i w[b,i]*v[b,(l+d_i)%L,:] -> split row-major
__global__ __launch_bounds__(128) void roll_combine()
{
    int l = blockIdx.x, b = blockIdx.y, tid = threadIdx.x;
    float w[TOPK]; int rows[TOPK];
    #pragma unroll
    for (int i = 0; i < TOPK; i++) {
        w[i] = g_w[b * 8 + i];
        rows[i] = (l + g_delay[i]) & LMASK;
    }
    int d0 = tid * 8;
    float acc[8] = {0,0,0,0,0,0,0,0};
    #pragma unroll
    for (int i = 0; i < TOPK; i++) {
        const float* vp = g_v + ((size_t)(b * LL + rows[i])) * DD + d0;
        float4 p0 = *(const float4*)vp, p1 = *(const float4*)(vp + 4);
        acc[0] = fmaf(w[i], p0.x, acc[0]); acc[1] = fmaf(w[i], p0.y, acc[1]);
        acc[2] = fmaf(w[i], p0.z, acc[2]); acc[3] = fmaf(w[i], p0.w, acc[3]);
        acc[4] = fmaf(w[i], p1.x, acc[4]); acc[5] = fmaf(w[i], p1.y, acc[5]);
        acc[6] = fmaf(w[i], p1.z, acc[6]); acc[7] = fmaf(w[i], p1.w, acc[7]);
    }
    size_t base = (size_t)(b * LL + l) * DD + d0;
    uint4 hv, lv; split_pack8(acc, hv, lv);
    *(uint4*)(t_r_hi + base) = hv;
    *(uint4*)(t_r_lo + base) = lv;
}

// out = LN(A + B); SPLIT also emits bf16 hi/lo row-major
template<int SPLIT>
__global__ __launch_bounds__(128) void add_ln(
    const float* __restrict__ A, const float* __restrict__ Bv,
    const float* __restrict__ g, const float* __restrict__ bt,
    float* __restrict__ out, u16* __restrict__ Ohi, u16* __restrict__ Olo)
{
    int row = blockIdx.x, tid = threadIdx.x;
    const float* pa = A  + (size_t)row * DD;
    const float* pb = Bv + (size_t)row * DD;
    __shared__ float red[128];
    int c0 = tid * 8;

    float v[8];
    float4 a0 = *(const float4*)(pa + c0), a1 = *(const float4*)(pa + c0 + 4);
    float4 b0 = *(const float4*)(pb + c0), b1 = *(const float4*)(pb + c0 + 4);
    v[0]=a0.x+b0.x; v[1]=a0.y+b0.y; v[2]=a0.z+b0.z; v[3]=a0.w+b0.w;
    v[4]=a1.x+b1.x; v[5]=a1.y+b1.y; v[6]=a1.z+b1.z; v[7]=a1.w+b1.w;
    float s = 0.f;
    #pragma unroll
    for (int j = 0; j < 8; j++) s += v[j];
    red[tid] = s; __syncthreads();
    for (int st = 64; st > 0; st >>= 1) {
        if (tid < st) red[tid] += red[tid + st];
        __syncthreads();
    }
    float mean = red[0] * (1.f / (float)DD);
    __syncthreads();
    float vs = 0.f;
    #pragma unroll
    for (int j = 0; j < 8; j++) { float d = v[j] - mean; vs += d * d; }
    red[tid] = vs; __syncthreads();
    for (int st = 64; st > 0; st >>= 1) {
        if (tid < st) red[tid] += red[tid + st];
        __syncthreads();
    }
    float rstd = rsqrtf(red[0] * (1.f / (float)DD) + 1e-6f);

    float o[8];
    #pragma unroll
    for (int j = 0; j < 8; j++)
        o[j] = (v[j] - mean) * rstd * g[c0 + j] + bt[c0 + j];
    float* po = out + (size_t)row * DD;
    *(float4*)(po + c0)     = make_float4(o[0], o[1], o[2], o[3]);
    *(float4*)(po + c0 + 4) = make_float4(o[4], o[5], o[6], o[7]);

    if (SPLIT) {
        size_t base = (size_t)row * DD + c0;
        uint4 hv, lv; split_pack8(o, hv, lv);
        *(uint4*)(Ohi + base) = hv;
        *(uint4*)(Olo + base) = lv;
    }
}

// -------------------------------------------------------------------------
#define SYM(p, s) cudaGetSymbolAddress((void**)&p, s)

extern "C" void kernel_launch(void* const* d_in, const int* in_sizes, int n_in,
                              void* d_out, int out_size)
{
    const float* x    = (const float*)d_in[0];
    const float* Wq   = (const float*)d_in[1];
    const float* bq   = (const float*)d_in[2];
    const float* Wk   = (const float*)d_in[3];
    const float* bk   = (const float*)d_in[4];
    const float* Wv   = (const float*)d_in[5];
    const float* bv   = (const float*)d_in[6];
    const float* Wo   = (const float*)d_in[7];
    const float* bo   = (const float*)d_in[8];
    const float* ln1g = (const float*)d_in[9];
    const float* ln1b = (const float*)d_in[10];
    const float* c1w  = (const float*)d_in[11];
    const float* c1b  = (const float*)d_in[12];
    const float* c2w  = (const float*)d_in[13];
    const float* c2b  = (const float*)d_in[14];
    const float* ln2g = (const float*)d_in[15];
    const float* ln2b = (const float*)d_in[16];
    float* out = (float*)d_out;

    cudaFuncSetAttribute(gemm_mma<0>, cudaFuncAttributeMaxDynamicSharedMemorySize, GSMEM);
    cudaFuncSetAttribute(gemm_mma<1>, cudaFuncAttributeMaxDynamicSharedMemorySize, GSMEM);
    cudaFuncSetAttribute(gemm_mma<2>, cudaFuncAttributeMaxDynamicSharedMemorySize, GSMEM);

    u16 *xh,*xl,*qh,*ql,*kh,*kl,*rh,*rl,*x1h,*x1l,*hh,*hl;
    u16 *wqh,*wql,*wkh,*wkl,*wvh,*wvl,*woh,*wol,*c1h,*c1l,*c2h,*c2l;
    float *v, *G, *x1;
    SYM(xh, t_x_hi);   SYM(xl, t_x_lo);
    SYM(qh, t_q_hi);   SYM(ql, t_q_lo);
    SYM(kh, t_k_hi);   SYM(kl, t_k_lo);
    SYM(rh, t_r_hi);   SYM(rl, t_r_lo);
    SYM(x1h, t_x1_hi); SYM(x1l, t_x1_lo);
    SYM(hh, t_h_hi);   SYM(hl, t_h_lo);
    SYM(wqh, t_wq_hi); SYM(wql, t_wq_lo);
    SYM(wkh, t_wk_hi); SYM(wkl, t_wk_lo);
    SYM(wvh, t_wv_hi); SYM(wvl, t_wv_lo);
    SYM(woh, t_wo_hi); SYM(wol, t_wo_lo);
    SYM(c1h, t_c1_hi); SYM(c1l, t_c1_lo);
    SYM(c2h, t_c2_hi); SYM(c2l, t_c2_lo);
    SYM(v, g_v); SYM(G, g_G); SYM(x1, g_x1);

    // split x; transpose+split weights
    split_x<<<(MM*DD)/1024, 256>>>(x, xh, xl);
    wsplit<<<dim3(DD/32, DD/32), 256>>>(Wq, wqh, wql, DD, DD);
    wsplit<<<dim3(DD/32, DD/32), 256>>>(Wk, wkh, wkl, DD, DD);
    wsplit<<<dim3(DD/32, DD/32), 256>>>(Wv, wvh, wvl, DD, DD);
    wsplit<<<dim3(DD/32, DD/32), 256>>>(Wo, woh, wol, DD, DD);
    wsplit<<<dim3(FF/32, DD/32), 256>>>(c1w, c1h, c1l, DD, FF);
    wsplit<<<dim3(DD/32, FF/32), 256>>>(c2w, c2h, c2l, FF, DD);

    // QKV  (M=16384 -> 64 row blocks of 256)
    gemm_mma<1><<<dim3(8,64,1), 256, GSMEM>>>(xh, xl, wqh, wql, bq,
        nullptr, qh, ql, DD, DD, 0, 0, 0);
    gemm_mma<1><<<dim3(8,64,1), 256, GSMEM>>>(xh, xl, wkh, wkl, bk,
        nullptr, kh, kl, DD, DD, 0, 0, 0);
    gemm_mma<0><<<dim3(8,64,1), 256, GSMEM>>>(xh, xl, wvh, wvl, bv,
        v, nullptr, nullptr, DD, DD, 0, 0, 0);

    // Gram G[b] = q[b] @ k[b]^T  (M=N=2048 per batch)
    gemm_mma<0><<<dim3(16,8,8), 256, GSMEM>>>(qh, ql, kh, kl, nullptr,
        G, nullptr, nullptr, DD, LL, LL, LL, (size_t)LL*LL);

    lag_partial<<<dim3(LL/256, 8, BB), 256>>>();
    lag_reduce<<<(BB*LL)/256, 256>>>();
    topk_softmax<<<BB, 256>>>();
    roll_combine<<<dim3(LL, BB), 128>>>();

    // attn = rolled @ Wo + bo  (fp32 into G, reused)
    gemm_mma<0><<<dim3(8,64,1), 256, GSMEM>>>(rh, rl, woh, wol, bo,
        G, nullptr, nullptr, DD, DD, 0, 0, 0);

    // x1 = LN(x + attn) (+ split)
    add_ln<1><<<MM, 128>>>(x, G, ln1g, ln1b, x1, x1h, x1l);

    // h = relu(x1 @ c1 + b)
    gemm_mma<2><<<dim3(32,64,1), 256, GSMEM>>>(x1h, x1l, c1h, c1l, c1b,
        nullptr, hh, hl, DD, FF, 0, 0, 0);

    // y = h @ c2 + b  (fp32 into v, reused)
    gemm_mma<0><<<dim3(8,64,1), 256, GSMEM>>>(hh, hl, c2h, c2l, c2b,
        v, nullptr, nullptr, FF, DD, 0, 0, 0);

    // out = LN(x1 + y)
    add_ln<0><<<MM, 128>>>(x1, v, ln2g, ln2b, out, nullptr, nullptr);
}

// round 10
// speedup vs baseline: 1.3106x; 1.3106x over previous
#include <cuda_runtime.h>
#include <cuda_bf16.h>
#include <math.h>

#define BB 8
#define LL 2048
#define DD 1024
#define FF 4096
#define MM 16384
#define TOPK 7
#define LMASK 2047

typedef unsigned short u16;
typedef unsigned int   u32;

// ---------------- device scratch (row-major bf16 hi/lo) -------------------
__device__ u16 t_x_hi[(size_t)MM*DD],  t_x_lo[(size_t)MM*DD];
__device__ u16 t_q_hi[(size_t)MM*DD],  t_q_lo[(size_t)MM*DD];
__device__ u16 t_k_hi[(size_t)MM*DD],  t_k_lo[(size_t)MM*DD];
__device__ u16 t_r_hi[(size_t)MM*DD],  t_r_lo[(size_t)MM*DD];
__device__ u16 t_x1_hi[(size_t)MM*DD], t_x1_lo[(size_t)MM*DD];
__device__ u16 t_h_hi[(size_t)MM*FF],  t_h_lo[(size_t)MM*FF];
__device__ u16 t_wq_hi[DD*DD], t_wq_lo[DD*DD];
__device__ u16 t_wk_hi[DD*DD], t_wk_lo[DD*DD];
__device__ u16 t_wv_hi[DD*DD], t_wv_lo[DD*DD];
__device__ u16 t_wo_hi[DD*DD], t_wo_lo[DD*DD];
__device__ u16 t_c1_hi[(size_t)FF*DD], t_c1_lo[(size_t)FF*DD];
__device__ u16 t_c2_hi[(size_t)DD*FF], t_c2_lo[(size_t)DD*FF];

__device__ float g_v[(size_t)MM*DD];     // v; later reused for y
__device__ float g_G[(size_t)BB*LL*LL];  // Gram; later reused for attn
__device__ float g_x1[(size_t)MM*DD];
__device__ float g_part[BB*8*LL];
__device__ float g_mv[BB*LL];
__device__ float g_w[BB*8];
__device__ int   g_delay[8];

// ---------------- helpers --------------------------------------------------
__device__ __forceinline__ u32 smem_u32(const void* p) {
    u32 a;
    asm("{ .reg .u64 t; cvta.to.shared.u64 t, %1; cvt.u32.u64 %0, t; }"
        : "=r"(a) : "l"(p));
    return a;
}

__device__ __forceinline__ void split2(float v0, float v1, u32& h, u32& l) {
    __nv_bfloat16 h0 = __float2bfloat16(v0), h1 = __float2bfloat16(v1);
    __nv_bfloat16 l0 = __float2bfloat16(v0 - __bfloat162float(h0));
    __nv_bfloat16 l1 = __float2bfloat16(v1 - __bfloat162float(h1));
    h = (u32)__bfloat16_as_ushort(h0) | ((u32)__bfloat16_as_ushort(h1) << 16);
    l = (u32)__bfloat16_as_ushort(l0) | ((u32)__bfloat16_as_ushort(l1) << 16);
}

__device__ __forceinline__ void split_pack8(const float* v, uint4& hv, uint4& lv) {
    u32 h[4], l[4];
    #pragma unroll
    for (int p = 0; p < 4; p++) split2(v[2*p], v[2*p+1], h[p], l[p]);
    hv = make_uint4(h[0], h[1], h[2], h[3]);
    lv = make_uint4(l[0], l[1], l[2], l[3]);
}

#define CPA(sa, gp) \
    asm volatile("cp.async.cg.shared.global [%0], [%1], 16;" \
        :: "r"(sa), "l"(gp))

#define MMA(c, a, b) \
    asm volatile("mma.sync.aligned.m16n8k16.row.col.f32.bf16.bf16.f32 " \
        "{%0,%1,%2,%3},{%4,%5,%6,%7},{%8,%9},{%0,%1,%2,%3};" \
        : "+f"((c)[0]), "+f"((c)[1]), "+f"((c)[2]), "+f"((c)[3]) \
        : "r"((a)[0]), "r"((a)[1]), "r"((a)[2]), "r"((a)[3]), \
          "r"((b)[0]), "r"((b)[1]))

#define LDSM4(r, a) \
    asm volatile("ldmatrix.sync.aligned.m8n8.x4.shared.b16 {%0,%1,%2,%3}, [%4];" \
        : "=r"((r)[0]), "=r"((r)[1]), "=r"((r)[2]), "=r"((r)[3]) : "r"(a))
#define LDSM2(r, a) \
    asm volatile("ldmatrix.sync.aligned.m8n8.x2.shared.b16 {%0,%1}, [%2];" \
        : "=r"((r)[0]), "=r"((r)[1]) : "r"(a))

// ---------------- GEMM: C[M,N] = A[M,K] @ B[N,K]^T (+bias, +relu) ---------
// A,B = bf16 hi/lo row-major. 3-term compensated product, fp32 accum.
// CTA 128x128, 8 warps (2x4) x (64x32), KC=32, 2-stage cp.async pipeline,
// 2 CTAs/SM for bubble hiding.
#define KC 32
#define PADH 40
#define OFF_AL 10240u   // 128*40*2
#define OFF_BH 20480u
#define OFF_BL 30720u
#define STAGE_B 40960u
#define GSMEM (2*40960)

template<int OMODE>  // 0 = fp32 out, 1 = split out, 2 = split+relu out
__global__ __launch_bounds__(256, 2) void gemm_mma(
    const u16* __restrict__ Ahi, const u16* __restrict__ Alo,
    const u16* __restrict__ Bhi, const u16* __restrict__ Blo,
    const float* __restrict__ bias, float* __restrict__ C,
    u16* __restrict__ Ohi, u16* __restrict__ Olo,
    int K, int ldc, int aRows, int bRows, size_t cBatch)
{
    extern __shared__ u16 sm[];
    const int tid = threadIdx.x;
    const int lane = tid & 31, warp = tid >> 5;   // warp 0..7
    const int wm = warp >> 2, wn = warp & 3;      // 2 x 4
    const int bx = blockIdx.x, by = blockIdx.y, bz = blockIdx.z;

    const u16* Ah = Ahi + (size_t)(bz * aRows + by * 128) * K;
    const u16* Al = Alo + (size_t)(bz * aRows + by * 128) * K;
    const u16* Bh = Bhi + (size_t)(bz * bRows + bx * 128) * K;
    const u16* Bl = Blo + (size_t)(bz * bRows + bx * 128) * K;

    const u32 smBase = smem_u32(sm);
    const int nC = K >> 5;

    float acc[4][4][4];
    #pragma unroll
    for (int i = 0; i < 4; i++)
        #pragma unroll
        for (int j = 0; j < 4; j++)
            #pragma unroll
            for (int p = 0; p < 4; p++) acc[i][j][p] = 0.f;

    auto load_chunk = [&](int c, int s) {
        u32 st = smBase + s * STAGE_B;
        int k0 = c * KC;
        // A: 128 rows x 4 x 16B -> 512 ops, 2 iters of 256 thr
        #pragma unroll
        for (int t = 0; t < 2; t++) {
            int idx = (t << 8) + tid;
            int row = idx >> 2, c16 = idx & 3;
            size_t go = (size_t)row * K + k0 + c16 * 8;
            u32 so = st + (u32)(row * PADH + c16 * 8) * 2;
            CPA(so, Ah + go);
            CPA(so + OFF_AL, Al + go);
        }
        // B: 128 rows x 4 -> 512 ops, 2 iters
        #pragma unroll
        for (int t = 0; t < 2; t++) {
            int idx = (t << 8) + tid;
            int row = idx >> 2, c16 = idx & 3;
            size_t go = (size_t)row * K + k0 + c16 * 8;
            u32 so = st + OFF_BH + (u32)(row * PADH + c16 * 8) * 2;
            CPA(so, Bh + go);
            CPA(so + (OFF_BL - OFF_BH), Bl + go);
        }
        asm volatile("cp.async.commit_group;" ::: "memory");
    };

    load_chunk(0, 0);

    for (int c = 0; c < nC; c++) {
        bool more = (c + 1 < nC);
        if (more) load_chunk(c + 1, (c + 1) & 1);
        if (more) asm volatile("cp.async.wait_group 1;" ::: "memory");
        else      asm volatile("cp.async.wait_group 0;" ::: "memory");
        __syncthreads();

        u32 st = smBase + (u32)(c & 1) * STAGE_B;
        #pragma unroll
        for (int ks = 0; ks < 2; ks++) {
            int ko = ks * 16;
            // B fragments (16 regs)
            u32 b_h[4][2], b_l[4][2];
            #pragma unroll
            for (int ni = 0; ni < 4; ni++) {
                int r = wn * 32 + ni * 8 + (lane & 7);
                int kk = ko + (((lane >> 3) & 1) << 3);
                u32 ba = st + OFF_BH + (u32)(r * PADH + kk) * 2;
                LDSM2(b_h[ni], ba);
                LDSM2(b_l[ni], ba + (OFF_BL - OFF_BH));
            }
            // A fragments per mi (8 regs live at a time)
            #pragma unroll
            for (int mi = 0; mi < 4; mi++) {
                int r = wm * 64 + mi * 16 + (lane & 15);
                int kk = ko + ((lane >> 4) << 3);
                u32 aa = st + (u32)(r * PADH + kk) * 2;
                u32 a_h[4], a_l[4];
                LDSM4(a_h, aa);
                LDSM4(a_l, aa + OFF_AL);
                #pragma unroll
                for (int ni = 0; ni < 4; ni++) {
                    MMA(acc[mi][ni], a_h, b_h[ni]);
                    MMA(acc[mi][ni], a_h, b_l[ni]);
                    MMA(acc[mi][ni], a_l, b_h[ni]);
                }
            }
        }
        __syncthreads();   // protect stage (c&1) from next load_chunk overwrite
    }

    // epilogue
    const int r0 = by * 128 + wm * 64;
    const int c0b = bx * 128 + wn * 32;
    #pragma unroll
    for (int mi = 0; mi < 4; mi++) {
        #pragma unroll
        for (int ni = 0; ni < 4; ni++) {
            int rA = r0 + mi * 16 + (lane >> 2);
            int cc = c0b + ni * 8 + (lane & 3) * 2;
            float v0 = acc[mi][ni][0], v1 = acc[mi][ni][1];
            float v2 = acc[mi][ni][2], v3 = acc[mi][ni][3];
            if (bias) {
                float bb0 = __ldg(bias + cc), bb1 = __ldg(bias + cc + 1);
                v0 += bb0; v1 += bb1; v2 += bb0; v3 += bb1;
            }
            if (OMODE == 2) {
                v0 = fmaxf(v0, 0.f); v1 = fmaxf(v1, 0.f);
                v2 = fmaxf(v2, 0.f); v3 = fmaxf(v3, 0.f);
            }
            if (OMODE == 0) {
                float* Cz = C + bz * cBatch;
                *(float2*)(Cz + (size_t)rA * ldc + cc)       = make_float2(v0, v1);
                *(float2*)(Cz + (size_t)(rA + 8) * ldc + cc) = make_float2(v2, v3);
            } else {
                u32 h0, l0, h1, l1;
                split2(v0, v1, h0, l0);
                split2(v2, v3, h1, l1);
                *(u32*)(Ohi + (size_t)rA * ldc + cc)       = h0;
                *(u32*)(Olo + (size_t)rA * ldc + cc)       = l0;
                *(u32*)(Ohi + (size_t)(rA + 8) * ldc + cc) = h1;
                *(u32*)(Olo + (size_t)(rA + 8) * ldc + cc) = l1;
            }
        }
    }
}

// ---------------- splits ---------------------------------------------------
__global__ __launch_bounds__(256) void split_x(
    const float* __restrict__ s, u16* __restrict__ hi, u16* __restrict__ lo)
{
    size_t i = ((size_t)blockIdx.x * 256 + threadIdx.x) * 4;
    float4 v = *(const float4*)(s + i);
    u32 h0, l0, h1, l1;
    split2(v.x, v.y, h0, l0);
    split2(v.z, v.w, h1, l1);
    *(uint2*)(hi + i) = make_uint2(h0, h1);
    *(uint2*)(lo + i) = make_uint2(l0, l1);
}

// W[K,N] row-major -> out[N,K] hi/lo (transpose + split)
__global__ __launch_bounds__(256) void wsplit(
    const float* __restrict__ W, u16* __restrict__ hi, u16* __restrict__ lo,
    int K, int N)
{
    __shared__ float t[32][33];
    int n0 = blockIdx.x * 32, k0 = blockIdx.y * 32;
    int tx = threadIdx.x & 31, ty = threadIdx.x >> 5;
    #pragma unroll
    for (int j = 0; j < 32; j += 8)
        t[ty + j][tx] = W[(size_t)(k0 + ty + j) * N + n0 + tx];
    __syncthreads();
    #pragma unroll
    for (int j = 0; j < 32; j += 8) {
        float v = t[tx][ty + j];
        __nv_bfloat16 h = __float2bfloat16(v);
        __nv_bfloat16 l = __float2bfloat16(v - __bfloat162float(h));
        size_t o = (size_t)(n0 + ty + j) * K + k0 + tx;
        hi[o] = __bfloat16_as_ushort(h);
        lo[o] = __bfloat16_as_ushort(l);
    }
}

// ---------------- lag / topk / roll / layernorm ---------------------------
__global__ void lag_partial()
{
    int b = blockIdx.z, tc = blockIdx.y;
    int l = blockIdx.x * 256 + threadIdx.x;
    const float* Gb = g_G + (size_t)b * LL * LL;
    int t0 = tc * 256;
    float s = 0.f;
    #pragma unroll 4
    for (int t = t0; t < t0 + 256; ++t)
        s += Gb[(size_t)t * LL + ((t - l) & LMASK)];
    g_part[(b * 8 + tc) * LL + l] = s;
}

__global__ void lag_reduce()
{
    int idx = blockIdx.x * 256 + threadIdx.x;
    int b = idx >> 11;
    float s = 0.f;
    #pragma unroll
    for (int tc = 0; tc < 8; tc++) s += g_part[(b * 8 + tc) * LL + (idx & LMASK)];
    g_mv[idx] = s * (1.f / (float)DD);
}

__global__ void topk_softmax()
{
    int b = blockIdx.x, tid = threadIdx.x;
    __shared__ float vals[LL];
    __shared__ float rv[256];
    __shared__ int   ri[256];
    __shared__ float topv[TOPK];
    __shared__ int   topi[TOPK];

    for (int i = tid; i < LL; i += 256) vals[i] = g_mv[b * LL + i];
    __syncthreads();
    for (int it = 0; it < TOPK; ++it) {
        float bv = -INFINITY; int bi = 0;
        for (int i = tid; i < LL; i += 256) {
            float v = vals[i];
            if (v > bv) { bv = v; bi = i; }
        }
        rv[tid] = bv; ri[tid] = bi;
        __syncthreads();
        for (int s = 128; s > 0; s >>= 1) {
            if (tid < s) {
                if (rv[tid+s] > rv[tid] ||
                    (rv[tid+s] == rv[tid] && ri[tid+s] < ri[tid])) {
                    rv[tid] = rv[tid+s]; ri[tid] = ri[tid+s];
                }
            }
            __syncthreads();
        }
        if (tid == 0) { topv[it] = rv[0]; topi[it] = ri[0]; vals[ri[0]] = -INFINITY; }
        __syncthreads();
    }
    if (tid == 0) {
        float mx = topv[0], e[TOPK], s = 0.f;
        #pragma unroll
        for (int i = 0; i < TOPK; i++) { e[i] = expf(topv[i] - mx); s += e[i]; }
        float inv = 1.f / s;
        #pragma unroll
        for (int i = 0; i < TOPK; i++) g_w[b * 8 + i] = e[i] * inv;
        if (b == 0)
            #pragma unroll
            for (int i = 0; i < TOPK; i++) g_delay[i] = topi[i];
    }
}

// rolled[b,l,:] = sum_i w[b,i]*v[b,(l+d_i)%L,:] -> split row-major
__global__ __launch_bounds__(128) void roll_combine()
{
    int l = blockIdx.x, b = blockIdx.y, tid = threadIdx.x;
    float w[TOPK]; int rows[TOPK];
    #pragma unroll
    for (int i = 0; i < TOPK; i++) {
        w[i] = g_w[b * 8 + i];
        rows[i] = (l + g_delay[i]) & LMASK;
    }
    int d0 = tid * 8;
    float acc[8] = {0,0,0,0,0,0,0,0};
    #pragma unroll
    for (int i = 0; i < TOPK; i++) {
        const float* vp = g_v + ((size_t)(b * LL + rows[i])) * DD + d0;
        float4 p0 = *(const float4*)vp, p1 = *(const float4*)(vp + 4);
        acc[0] = fmaf(w[i], p0.x, acc[0]); acc[1] = fmaf(w[i], p0.y, acc[1]);
        acc[2] = fmaf(w[i], p0.z, acc[2]); acc[3] = fmaf(w[i], p0.w, acc[3]);
        acc[4] = fmaf(w[i], p1.x, acc[4]); acc[5] = fmaf(w[i], p1.y, acc[5]);
        acc[6] = fmaf(w[i], p1.z, acc[6]); acc[7] = fmaf(w[i], p1.w, acc[7]);
    }
    size_t base = (size_t)(b * LL + l) * DD + d0;
    uint4 hv, lv; split_pack8(acc, hv, lv);
    *(uint4*)(t_r_hi + base) = hv;
    *(uint4*)(t_r_lo + base) = lv;
}

// out = LN(A + B); SPLIT also emits bf16 hi/lo row-major
template<int SPLIT>
__global__ __launch_bounds__(128) void add_ln(
    const float* __restrict__ A, const float* __restrict__ Bv,
    const float* __restrict__ g, const float* __restrict__ bt,
    float* __restrict__ out, u16* __restrict__ Ohi, u16* __restrict__ Olo)
{
    int row = blockIdx.x, tid = threadIdx.x;
    const float* pa = A  + (size_t)row * DD;
    const float* pb = Bv + (size_t)row * DD;
    __shared__ float red[128];
    int c0 = tid * 8;

    float v[8];
    float4 a0 = *(const float4*)(pa + c0), a1 = *(const float4*)(pa + c0 + 4);
    float4 b0 = *(const float4*)(pb + c0), b1 = *(const float4*)(pb + c0 + 4);
    v[0]=a0.x+b0.x; v[1]=a0.y+b0.y; v[2]=a0.z+b0.z; v[3]=a0.w+b0.w;
    v[4]=a1.x+b1.x; v[5]=a1.y+b1.y; v[6]=a1.z+b1.z; v[7]=a1.w+b1.w;
    float s = 0.f;
    #pragma unroll
    for (int j = 0; j < 8; j++) s += v[j];
    red[tid] = s; __syncthreads();
    for (int st = 64; st > 0; st >>= 1) {
        if (tid < st) red[tid] += red[tid + st];
        __syncthreads();
    }
    float mean = red[0] * (1.f / (float)DD);
    __syncthreads();
    float vs = 0.f;
    #pragma unroll
    for (int j = 0; j < 8; j++) { float d = v[j] - mean; vs += d * d; }
    red[tid] = vs; __syncthreads();
    for (int st = 64; st > 0; st >>= 1) {
        if (tid < st) red[tid] += red[tid + st];
        __syncthreads();
    }
    float rstd = rsqrtf(red[0] * (1.f / (float)DD) + 1e-6f);

    float o[8];
    #pragma unroll
    for (int j = 0; j < 8; j++)
        o[j] = (v[j] - mean) * rstd * g[c0 + j] + bt[c0 + j];
    float* po = out + (size_t)row * DD;
    *(float4*)(po + c0)     = make_float4(o[0], o[1], o[2], o[3]);
    *(float4*)(po + c0 + 4) = make_float4(o[4], o[5], o[6], o[7]);

    if (SPLIT) {
        size_t base = (size_t)row * DD + c0;
        uint4 hv, lv; split_pack8(o, hv, lv);
        *(uint4*)(Ohi + base) = hv;
        *(uint4*)(Olo + base) = lv;
    }
}

// -------------------------------------------------------------------------
#define SYM(p, s) cudaGetSymbolAddress((void**)&p, s)

extern "C" void kernel_launch(void* const* d_in, const int* in_sizes, int n_in,
                              void* d_out, int out_size)
{
    const float* x    = (const float*)d_in[0];
    const float* Wq   = (const float*)d_in[1];
    const float* bq   = (const float*)d_in[2];
    const float* Wk   = (const float*)d_in[3];
    const float* bk   = (const float*)d_in[4];
    const float* Wv   = (const float*)d_in[5];
    const float* bv   = (const float*)d_in[6];
    const float* Wo   = (const float*)d_in[7];
    const float* bo   = (const float*)d_in[8];
    const float* ln1g = (const float*)d_in[9];
    const float* ln1b = (const float*)d_in[10];
    const float* c1w  = (const float*)d_in[11];
    const float* c1b  = (const float*)d_in[12];
    const float* c2w  = (const float*)d_in[13];
    const float* c2b  = (const float*)d_in[14];
    const float* ln2g = (const float*)d_in[15];
    const float* ln2b = (const float*)d_in[16];
    float* out = (float*)d_out;

    cudaFuncSetAttribute(gemm_mma<0>, cudaFuncAttributeMaxDynamicSharedMemorySize, GSMEM);
    cudaFuncSetAttribute(gemm_mma<1>, cudaFuncAttributeMaxDynamicSharedMemorySize, GSMEM);
    cudaFuncSetAttribute(gemm_mma<2>, cudaFuncAttributeMaxDynamicSharedMemorySize, GSMEM);

    u16 *xh,*xl,*qh,*ql,*kh,*kl,*rh,*rl,*x1h,*x1l,*hh,*hl;
    u16 *wqh,*wql,*wkh,*wkl,*wvh,*wvl,*woh,*wol,*c1h,*c1l,*c2h,*c2l;
    float *v, *G, *x1;
    SYM(xh, t_x_hi);   SYM(xl, t_x_lo);
    SYM(qh, t_q_hi);   SYM(ql, t_q_lo);
    SYM(kh, t_k_hi);   SYM(kl, t_k_lo);
    SYM(rh, t_r_hi);   SYM(rl, t_r_lo);
    SYM(x1h, t_x1_hi); SYM(x1l, t_x1_lo);
    SYM(hh, t_h_hi);   SYM(hl, t_h_lo);
    SYM(wqh, t_wq_hi); SYM(wql, t_wq_lo);
    SYM(wkh, t_wk_hi); SYM(wkl, t_wk_lo);
    SYM(wvh, t_wv_hi); SYM(wvl, t_wv_lo);
    SYM(woh, t_wo_hi); SYM(wol, t_wo_lo);
    SYM(c1h, t_c1_hi); SYM(c1l, t_c1_lo);
    SYM(c2h, t_c2_hi); SYM(c2l, t_c2_lo);
    SYM(v, g_v); SYM(G, g_G); SYM(x1, g_x1);

    // split x; transpose+split weights
    split_x<<<(MM*DD)/1024, 256>>>(x, xh, xl);
    wsplit<<<dim3(DD/32, DD/32), 256>>>(Wq, wqh, wql, DD, DD);
    wsplit<<<dim3(DD/32, DD/32), 256>>>(Wk, wkh, wkl, DD, DD);
    wsplit<<<dim3(DD/32, DD/32), 256>>>(Wv, wvh, wvl, DD, DD);
    wsplit<<<dim3(DD/32, DD/32), 256>>>(Wo, woh, wol, DD, DD);
    wsplit<<<dim3(FF/32, DD/32), 256>>>(c1w, c1h, c1l, DD, FF);
    wsplit<<<dim3(DD/32, FF/32), 256>>>(c2w, c2h, c2l, FF, DD);

    // QKV  (M=16384 -> 128 row blocks of 128)
    gemm_mma<1><<<dim3(8,128,1), 256, GSMEM>>>(xh, xl, wqh, wql, bq,
        nullptr, qh, ql, DD, DD, 0, 0, 0);
    gemm_mma<1><<<dim3(8,128,1), 256, GSMEM>>>(xh, xl, wkh, wkl, bk,
        nullptr, kh, kl, DD, DD, 0, 0, 0);
    gemm_mma<0><<<dim3(8,128,1), 256, GSMEM>>>(xh, xl, wvh, wvl, bv,
        v, nullptr, nullptr, DD, DD, 0, 0, 0);

    // Gram G[b] = q[b] @ k[b]^T  (M=N=2048 per batch)
    gemm_mma<0><<<dim3(16,16,8), 256, GSMEM>>>(qh, ql, kh, kl, nullptr,
        G, nullptr, nullptr, DD, LL, LL, LL, (size_t)LL*LL);

    lag_partial<<<dim3(LL/256, 8, BB), 256>>>();
    lag_reduce<<<(BB*LL)/256, 256>>>();
    topk_softmax<<<BB, 256>>>();
    roll_combine<<<dim3(LL, BB), 128>>>();

    // attn = rolled @ Wo + bo  (fp32 into G, reused)
    gemm_mma<0><<<dim3(8,128,1), 256, GSMEM>>>(rh, rl, woh, wol, bo,
        G, nullptr, nullptr, DD, DD, 0, 0, 0);

    // x1 = LN(x + attn) (+ split)
    add_ln<1><<<MM, 128>>>(x, G, ln1g, ln1b, x1, x1h, x1l);

    // h = relu(x1 @ c1 + b)
    gemm_mma<2><<<dim3(32,128,1), 256, GSMEM>>>(x1h, x1l, c1h, c1l, c1b,
        nullptr, hh, hl, DD, FF, 0, 0, 0);

    // y = h @ c2 + b  (fp32 into v, reused)
    gemm_mma<0><<<dim3(8,128,1), 256, GSMEM>>>(hh, hl, c2h, c2l, c2b,
        v, nullptr, nullptr, FF, DD, 0, 0, 0);

    // out = LN(x1 + y)
    add_ln<0><<<MM, 128>>>(x1, v, ln2g, ln2b, out, nullptr, nullptr);
}

// round 11
// speedup vs baseline: 1.3883x; 1.0593x over previous
#include <cuda_runtime.h>
#include <cuda_bf16.h>
#include <math.h>

#define BB 8
#define LL 2048
#define DD 1024
#define FF 4096
#define MM 16384
#define TOPK 7
#define LMASK 2047

typedef unsigned short u16;
typedef unsigned int   u32;

// ---------------- device scratch (no allocation) --------------------------
__device__ u16 t_x_hi[(size_t)MM*DD],  t_x_lo[(size_t)MM*DD];
__device__ u16 t_r_hi[(size_t)MM*DD],  t_r_lo[(size_t)MM*DD];
__device__ u16 t_x1_hi[(size_t)MM*DD], t_x1_lo[(size_t)MM*DD];
__device__ u16 t_h_hi[(size_t)MM*FF],  t_h_lo[(size_t)MM*FF];   // also qT/kT fp32
__device__ u16 t_wq_hi[DD*DD], t_wq_lo[DD*DD];
__device__ u16 t_wk_hi[DD*DD], t_wk_lo[DD*DD];
__device__ u16 t_wv_hi[DD*DD], t_wv_lo[DD*DD];
__device__ u16 t_wo_hi[DD*DD], t_wo_lo[DD*DD];
__device__ u16 t_c1_hi[(size_t)FF*DD], t_c1_lo[(size_t)FF*DD];
__device__ u16 t_c2_hi[(size_t)DD*FF], t_c2_lo[(size_t)DD*FF];

__device__ float g_v[(size_t)MM*DD];     // v fp32; later attn
__device__ float g_G[(size_t)BB*LL*LL];  // fq | fk fp32; later y
__device__ float g_x1[(size_t)MM*DD];    // FFT partials early; x1 later
__device__ float g_part[BB*8*LL];        // reduced spectrum S (float2 cast)
__device__ float g_mv[BB*LL];
__device__ float g_w[BB*8];
__device__ int   g_delay[8];

// ---------------- helpers --------------------------------------------------
__device__ __forceinline__ u32 smem_u32(const void* p) {
    u32 a;
    asm("{ .reg .u64 t; cvta.to.shared.u64 t, %1; cvt.u32.u64 %0, t; }"
        : "=r"(a) : "l"(p));
    return a;
}

__device__ __forceinline__ void split2(float v0, float v1, u32& h, u32& l) {
    __nv_bfloat16 h0 = __float2bfloat16(v0), h1 = __float2bfloat16(v1);
    __nv_bfloat16 l0 = __float2bfloat16(v0 - __bfloat162float(h0));
    __nv_bfloat16 l1 = __float2bfloat16(v1 - __bfloat162float(h1));
    h = (u32)__bfloat16_as_ushort(h0) | ((u32)__bfloat16_as_ushort(h1) << 16);
    l = (u32)__bfloat16_as_ushort(l0) | ((u32)__bfloat16_as_ushort(l1) << 16);
}

__device__ __forceinline__ void split_pack8(const float* v, uint4& hv, uint4& lv) {
    u32 h[4], l[4];
    #pragma unroll
    for (int p = 0; p < 4; p++) split2(v[2*p], v[2*p+1], h[p], l[p]);
    hv = make_uint4(h[0], h[1], h[2], h[3]);
    lv = make_uint4(l[0], l[1], l[2], l[3]);
}

#define CPA(sa, gp) \
    asm volatile("cp.async.cg.shared.global [%0], [%1], 16;" \
        :: "r"(sa), "l"(gp))

#define MMA(c, a, b) \
    asm volatile("mma.sync.aligned.m16n8k16.row.col.f32.bf16.bf16.f32 " \
        "{%0,%1,%2,%3},{%4,%5,%6,%7},{%8,%9},{%0,%1,%2,%3};" \
        : "+f"((c)[0]), "+f"((c)[1]), "+f"((c)[2]), "+f"((c)[3]) \
        : "r"((a)[0]), "r"((a)[1]), "r"((a)[2]), "r"((a)[3]), \
          "r"((b)[0]), "r"((b)[1]))

#define LDSM4(r, a) \
    asm volatile("ldmatrix.sync.aligned.m8n8.x4.shared.b16 {%0,%1,%2,%3}, [%4];" \
        : "=r"((r)[0]), "=r"((r)[1]), "=r"((r)[2]), "=r"((r)[3]) : "r"(a))
#define LDSM2(r, a) \
    asm volatile("ldmatrix.sync.aligned.m8n8.x2.shared.b16 {%0,%1}, [%2];" \
        : "=r"((r)[0]), "=r"((r)[1]) : "r"(a))

// ---------------- GEMM (round-10 proven: 128x128 CTA, 2-stage, 2 CTA/SM) --
#define KC 32
#define PADH 40
#define OFF_AL 10240u
#define OFF_BH 20480u
#define OFF_BL 30720u
#define STAGE_B 40960u
#define GSMEM (2*40960)

template<int OMODE>  // 0 = fp32 out, 1 = split out, 2 = split+relu out
__global__ __launch_bounds__(256, 2) void gemm_mma(
    const u16* __restrict__ Ahi, const u16* __restrict__ Alo,
    const u16* __restrict__ Bhi, const u16* __restrict__ Blo,
    const float* __restrict__ bias, float* __restrict__ C,
    u16* __restrict__ Ohi, u16* __restrict__ Olo,
    int K, int ldc, int aRows, int bRows, size_t cBatch)
{
    extern __shared__ u16 sm[];
    const int tid = threadIdx.x;
    const int lane = tid & 31, warp = tid >> 5;
    const int wm = warp >> 2, wn = warp & 3;
    const int bx = blockIdx.x, by = blockIdx.y, bz = blockIdx.z;

    const u16* Ah = Ahi + (size_t)(bz * aRows + by * 128) * K;
    const u16* Al = Alo + (size_t)(bz * aRows + by * 128) * K;
    const u16* Bh = Bhi + (size_t)(bz * bRows + bx * 128) * K;
    const u16* Bl = Blo + (size_t)(bz * bRows + bx * 128) * K;

    const u32 smBase = smem_u32(sm);
    const int nC = K >> 5;

    float acc[4][4][4];
    #pragma unroll
    for (int i = 0; i < 4; i++)
        #pragma unroll
        for (int j = 0; j < 4; j++)
            #pragma unroll
            for (int p = 0; p < 4; p++) acc[i][j][p] = 0.f;

    auto load_chunk = [&](int c, int s) {
        u32 st = smBase + s * STAGE_B;
        int k0 = c * KC;
        #pragma unroll
        for (int t = 0; t < 2; t++) {
            int idx = (t << 8) + tid;
            int row = idx >> 2, c16 = idx & 3;
            size_t go = (size_t)row * K + k0 + c16 * 8;
            u32 so = st + (u32)(row * PADH + c16 * 8) * 2;
            CPA(so, Ah + go);
            CPA(so + OFF_AL, Al + go);
        }
        #pragma unroll
        for (int t = 0; t < 2; t++) {
            int idx = (t << 8) + tid;
            int row = idx >> 2, c16 = idx & 3;
            size_t go = (size_t)row * K + k0 + c16 * 8;
            u32 so = st + OFF_BH + (u32)(row * PADH + c16 * 8) * 2;
            CPA(so, Bh + go);
            CPA(so + (OFF_BL - OFF_BH), Bl + go);
        }
        asm volatile("cp.async.commit_group;" ::: "memory");
    };

    load_chunk(0, 0);

    for (int c = 0; c < nC; c++) {
        bool more = (c + 1 < nC);
        if (more) load_chunk(c + 1, (c + 1) & 1);
        if (more) asm volatile("cp.async.wait_group 1;" ::: "memory");
        else      asm volatile("cp.async.wait_group 0;" ::: "memory");
        __syncthreads();

        u32 st = smBase + (u32)(c & 1) * STAGE_B;
        #pragma unroll
        for (int ks = 0; ks < 2; ks++) {
            int ko = ks * 16;
            u32 b_h[4][2], b_l[4][2];
            #pragma unroll
            for (int ni = 0; ni < 4; ni++) {
                int r = wn * 32 + ni * 8 + (lane & 7);
                int kk = ko + (((lane >> 3) & 1) << 3);
                u32 ba = st + OFF_BH + (u32)(r * PADH + kk) * 2;
                LDSM2(b_h[ni], ba);
                LDSM2(b_l[ni], ba + (OFF_BL - OFF_BH));
            }
            #pragma unroll
            for (int mi = 0; mi < 4; mi++) {
                int r = wm * 64 + mi * 16 + (lane & 15);
                int kk = ko + ((lane >> 4) << 3);
                u32 aa = st + (u32)(r * PADH + kk) * 2;
                u32 a_h[4], a_l[4];
                LDSM4(a_h, aa);
                LDSM4(a_l, aa + OFF_AL);
                #pragma unroll
                for (int ni = 0; ni < 4; ni++) {
                    MMA(acc[mi][ni], a_h, b_h[ni]);
                    MMA(acc[mi][ni], a_h, b_l[ni]);
                    MMA(acc[mi][ni], a_l, b_h[ni]);
                }
            }
        }
        __syncthreads();
    }

    const int r0 = by * 128 + wm * 64;
    const int c0b = bx * 128 + wn * 32;
    #pragma unroll
    for (int mi = 0; mi < 4; mi++) {
        #pragma unroll
        for (int ni = 0; ni < 4; ni++) {
            int rA = r0 + mi * 16 + (lane >> 2);
            int cc = c0b + ni * 8 + (lane & 3) * 2;
            float v0 = acc[mi][ni][0], v1 = acc[mi][ni][1];
            float v2 = acc[mi][ni][2], v3 = acc[mi][ni][3];
            if (bias) {
                float bb0 = __ldg(bias + cc), bb1 = __ldg(bias + cc + 1);
                v0 += bb0; v1 += bb1; v2 += bb0; v3 += bb1;
            }
            if (OMODE == 2) {
                v0 = fmaxf(v0, 0.f); v1 = fmaxf(v1, 0.f);
                v2 = fmaxf(v2, 0.f); v3 = fmaxf(v3, 0.f);
            }
            if (OMODE == 0) {
                float* Cz = C + bz * cBatch;
                *(float2*)(Cz + (size_t)rA * ldc + cc)       = make_float2(v0, v1);
                *(float2*)(Cz + (size_t)(rA + 8) * ldc + cc) = make_float2(v2, v3);
            } else {
                u32 h0, l0, h1, l1;
                split2(v0, v1, h0, l0);
                split2(v2, v3, h1, l1);
                *(u32*)(Ohi + (size_t)rA * ldc + cc)       = h0;
                *(u32*)(Olo + (size_t)rA * ldc + cc)       = l0;
                *(u32*)(Ohi + (size_t)(rA + 8) * ldc + cc) = h1;
                *(u32*)(Olo + (size_t)(rA + 8) * ldc + cc) = l1;
            }
        }
    }
}

// ---------------- splits ---------------------------------------------------
__global__ __launch_bounds__(256) void split_x(
    const float* __restrict__ s, u16* __restrict__ hi, u16* __restrict__ lo)
{
    size_t i = ((size_t)blockIdx.x * 256 + threadIdx.x) * 4;
    float4 v = *(const float4*)(s + i);
    u32 h0, l0, h1, l1;
    split2(v.x, v.y, h0, l0);
    split2(v.z, v.w, h1, l1);
    *(uint2*)(hi + i) = make_uint2(h0, h1);
    *(uint2*)(lo + i) = make_uint2(l0, l1);
}

__global__ __launch_bounds__(256) void wsplit(
    const float* __restrict__ W, u16* __restrict__ hi, u16* __restrict__ lo,
    int K, int N)
{
    __shared__ float t[32][33];
    int n0 = blockIdx.x * 32, k0 = blockIdx.y * 32;
    int tx = threadIdx.x & 31, ty = threadIdx.x >> 5;
    #pragma unroll
    for (int j = 0; j < 32; j += 8)
        t[ty + j][tx] = W[(size_t)(k0 + ty + j) * N + n0 + tx];
    __syncthreads();
    #pragma unroll
    for (int j = 0; j < 32; j += 8) {
        float v = t[tx][ty + j];
        __nv_bfloat16 h = __float2bfloat16(v);
        __nv_bfloat16 l = __float2bfloat16(v - __bfloat162float(h));
        size_t o = (size_t)(n0 + ty + j) * K + k0 + tx;
        hi[o] = __bfloat16_as_ushort(h);
        lo[o] = __bfloat16_as_ushort(l);
    }
}

// ---------------- FFT path: mean_value via spectral correlation -----------
// fp32 transpose per batch: in[b][t][d] -> out[b][d][t]
__global__ __launch_bounds__(256) void transpose_bt(
    const float* __restrict__ in, float* __restrict__ out)
{
    __shared__ float t[32][33];
    int b = blockIdx.z;
    int d0 = blockIdx.x * 32, t0 = blockIdx.y * 32;
    int tx = threadIdx.x & 31, ty = threadIdx.x >> 5;
    #pragma unroll
    for (int j = 0; j < 32; j += 8)
        t[ty + j][tx] = in[((size_t)b * LL + t0 + ty + j) * DD + d0 + tx];
    __syncthreads();
    #pragma unroll
    for (int j = 0; j < 32; j += 8)
        out[((size_t)b * DD + d0 + ty + j) * LL + t0 + tx] = t[tx][ty + j];
}

// in-smem radix-2 DIT FFT, N=2048, 256 threads, bit-reversed input order
__device__ __forceinline__ void fft2048(float2* z, const float2* tw, int tid)
{
    #pragma unroll
    for (int s = 1; s <= 11; s++) {
        int half = 1 << (s - 1);
        for (int i = tid; i < 1024; i += 256) {
            int pos  = i & (half - 1);
            int idx0 = ((i >> (s - 1)) << s) + pos;
            int idx1 = idx0 + half;
            float2 w = tw[pos << (11 - s)];
            float2 u = z[idx0], v = z[idx1];
            float vr = v.x * w.x - v.y * w.y;
            float vi = v.x * w.y + v.y * w.x;
            z[idx0] = make_float2(u.x + vr, u.y + vi);
            z[idx1] = make_float2(u.x - vr, u.y - vi);
        }
        __syncthreads();
    }
}

// per (b, group of 8 channels): FFT(q + i k), accumulate T = conj(Qf)*Kf
__global__ __launch_bounds__(256) void fft_corr(
    const float* __restrict__ qT, const float* __restrict__ kT,
    float2* __restrict__ partial)
{
    extern __shared__ float2 smf[];
    float2* z   = smf;          // 2048
    float2* tw  = smf + 2048;   // 1024
    float2* acc = smf + 3072;   // 2048
    int tid = threadIdx.x, dg = blockIdx.x, b = blockIdx.y;

    for (int j = tid; j < 1024; j += 256) {
        float sv, cv;
        sincosf(-6.283185307179586f * (float)j / 2048.0f, &sv, &cv);
        tw[j] = make_float2(cv, sv);
    }
    for (int f = tid; f < 2048; f += 256) acc[f] = make_float2(0.f, 0.f);
    __syncthreads();

    for (int j = 0; j < 8; j++) {
        int d = dg * 8 + j;
        const float* qr = qT + ((size_t)b * DD + d) * LL;
        const float* kr = kT + ((size_t)b * DD + d) * LL;
        for (int t = tid; t < 2048; t += 256) {
            int r = __brev((u32)t) >> 21;
            z[r] = make_float2(qr[t], kr[t]);
        }
        __syncthreads();
        fft2048(z, tw, tid);
        for (int f = tid; f < 2048; f += 256) {
            int m = (2048 - f) & 2047;
            float a = z[f].x, bb = z[f].y, c = z[m].x, d2 = z[m].y;
            float re = ((a + c) * (bb + d2) - (bb - d2) * (a - c)) * 0.25f;
            float im = -((a * a - c * c) + (bb * bb - d2 * d2)) * 0.25f;
            acc[f].x += re; acc[f].y += im;
        }
        __syncthreads();
    }
    float2* out = partial + ((size_t)b * 128 + dg) * 2048;
    for (int f = tid; f < 2048; f += 256) out[f] = acc[f];
}

__global__ void reduce_spec(const float2* __restrict__ partial, float2* __restrict__ S)
{
    int idx = blockIdx.x * 256 + threadIdx.x;   // 16384
    int b = idx >> 11, f = idx & 2047;
    float sx = 0.f, sy = 0.f;
    for (int dg = 0; dg < 128; dg++) {
        float2 p = partial[((size_t)b * 128 + dg) * 2048 + f];
        sx += p.x; sy += p.y;
    }
    S[idx] = make_float2(sx, sy);
}

// mean_value[b][l] = Re(FFT(T))[l] / (N*D)
__global__ __launch_bounds__(256) void ifft_mv(const float2* __restrict__ S)
{
    extern __shared__ float2 smf[];
    float2* z  = smf;          // 2048
    float2* tw = smf + 2048;   // 1024
    int tid = threadIdx.x, b = blockIdx.x;
    for (int j = tid; j < 1024; j += 256) {
        float sv, cv;
        sincosf(-6.283185307179586f * (float)j / 2048.0f, &sv, &cv);
        tw[j] = make_float2(cv, sv);
    }
    for (int f = tid; f < 2048; f += 256) {
        int r = __brev((u32)f) >> 21;
        z[r] = S[b * 2048 + f];
    }
    __syncthreads();
    fft2048(z, tw, tid);
    const float sc = 1.0f / (2048.0f * 1024.0f);
    for (int l = tid; l < 2048; l += 256)
        g_mv[b * 2048 + l] = z[l].x * sc;
}

// ---------------- topk / roll / layernorm ---------------------------------
__global__ void topk_softmax()
{
    int b = blockIdx.x, tid = threadIdx.x;
    __shared__ float vals[LL];
    __shared__ float rv[256];
    __shared__ int   ri[256];
    __shared__ float topv[TOPK];
    __shared__ int   topi[TOPK];

    for (int i = tid; i < LL; i += 256) vals[i] = g_mv[b * LL + i];
    __syncthreads();
    for (int it = 0; it < TOPK; ++it) {
        float bv = -INFINITY; int bi = 0;
        for (int i = tid; i < LL; i += 256) {
            float v = vals[i];
            if (v > bv) { bv = v; bi = i; }
        }
        rv[tid] = bv; ri[tid] = bi;
        __syncthreads();
        for (int s = 128; s > 0; s >>= 1) {
            if (tid < s) {
                if (rv[tid+s] > rv[tid] ||
                    (rv[tid+s] == rv[tid] && ri[tid+s] < ri[tid])) {
                    rv[tid] = rv[tid+s]; ri[tid] = ri[tid+s];
                }
            }
            __syncthreads();
        }
        if (tid == 0) { topv[it] = rv[0]; topi[it] = ri[0]; vals[ri[0]] = -INFINITY; }
        __syncthreads();
    }
    if (tid == 0) {
        float mx = topv[0], e[TOPK], s = 0.f;
        #pragma unroll
        for (int i = 0; i < TOPK; i++) { e[i] = expf(topv[i] - mx); s += e[i]; }
        float inv = 1.f / s;
        #pragma unroll
        for (int i = 0; i < TOPK; i++) g_w[b * 8 + i] = e[i] * inv;
        if (b == 0)
            #pragma unroll
            for (int i = 0; i < TOPK; i++) g_delay[i] = topi[i];
    }
}

__global__ __launch_bounds__(128) void roll_combine()
{
    int l = blockIdx.x, b = blockIdx.y, tid = threadIdx.x;
    float w[TOPK]; int rows[TOPK];
    #pragma unroll
    for (int i = 0; i < TOPK; i++) {
        w[i] = g_w[b * 8 + i];
        rows[i] = (l + g_delay[i]) & LMASK;
    }
    int d0 = tid * 8;
    float acc[8] = {0,0,0,0,0,0,0,0};
    #pragma unroll
    for (int i = 0; i < TOPK; i++) {
        const float* vp = g_v + ((size_t)(b * LL + rows[i])) * DD + d0;
        float4 p0 = *(const float4*)vp, p1 = *(const float4*)(vp + 4);
        acc[0] = fmaf(w[i], p0.x, acc[0]); acc[1] = fmaf(w[i], p0.y, acc[1]);
        acc[2] = fmaf(w[i], p0.z, acc[2]); acc[3] = fmaf(w[i], p0.w, acc[3]);
        acc[4] = fmaf(w[i], p1.x, acc[4]); acc[5] = fmaf(w[i], p1.y, acc[5]);
        acc[6] = fmaf(w[i], p1.z, acc[6]); acc[7] = fmaf(w[i], p1.w, acc[7]);
    }
    size_t base = (size_t)(b * LL + l) * DD + d0;
    uint4 hv, lv; split_pack8(acc, hv, lv);
    *(uint4*)(t_r_hi + base) = hv;
    *(uint4*)(t_r_lo + base) = lv;
}

template<int SPLIT>
__global__ __launch_bounds__(128) void add_ln(
    const float* __restrict__ A, const float* __restrict__ Bv,
    const float* __restrict__ g, const float* __restrict__ bt,
    float* __restrict__ out, u16* __restrict__ Ohi, u16* __restrict__ Olo)
{
    int row = blockIdx.x, tid = threadIdx.x;
    const float* pa = A  + (size_t)row * DD;
    const float* pb = Bv + (size_t)row * DD;
    __shared__ float red[128];
    int c0 = tid * 8;

    float v[8];
    float4 a0 = *(const float4*)(pa + c0), a1 = *(const float4*)(pa + c0 + 4);
    float4 b0 = *(const float4*)(pb + c0), b1 = *(const float4*)(pb + c0 + 4);
    v[0]=a0.x+b0.x; v[1]=a0.y+b0.y; v[2]=a0.z+b0.z; v[3]=a0.w+b0.w;
    v[4]=a1.x+b1.x; v[5]=a1.y+b1.y; v[6]=a1.z+b1.z; v[7]=a1.w+b1.w;
    float s = 0.f;
    #pragma unroll
    for (int j = 0; j < 8; j++) s += v[j];
    red[tid] = s; __syncthreads();
    for (int st = 64; st > 0; st >>= 1) {
        if (tid < st) red[tid] += red[tid + st];
        __syncthreads();
    }
    float mean = red[0] * (1.f / (float)DD);
    __syncthreads();
    float vs = 0.f;
    #pragma unroll
    for (int j = 0; j < 8; j++) { float d = v[j] - mean; vs += d * d; }
    red[tid] = vs; __syncthreads();
    for (int st = 64; st > 0; st >>= 1) {
        if (tid < st) red[tid] += red[tid + st];
        __syncthreads();
    }
    float rstd = rsqrtf(red[0] * (1.f / (float)DD) + 1e-6f);

    float o[8];
    #pragma unroll
    for (int j = 0; j < 8; j++)
        o[j] = (v[j] - mean) * rstd * g[c0 + j] + bt[c0 + j];
    float* po = out + (size_t)row * DD;
    *(float4*)(po + c0)     = make_float4(o[0], o[1], o[2], o[3]);
    *(float4*)(po + c0 + 4) = make_float4(o[4], o[5], o[6], o[7]);

    if (SPLIT) {
        size_t base = (size_t)row * DD + c0;
        uint4 hv, lv; split_pack8(o, hv, lv);
        *(uint4*)(Ohi + base) = hv;
        *(uint4*)(Olo + base) = lv;
    }
}

// -------------------------------------------------------------------------
#define SYM(p, s) cudaGetSymbolAddress((void**)&p, s)

extern "C" void kernel_launch(void* const* d_in, const int* in_sizes, int n_in,
                              void* d_out, int out_size)
{
    const float* x    = (const float*)d_in[0];
    const float* Wq   = (const float*)d_in[1];
    const float* bq   = (const float*)d_in[2];
    const float* Wk   = (const float*)d_in[3];
    const float* bk   = (const float*)d_in[4];
    const float* Wv   = (const float*)d_in[5];
    const float* bv   = (const float*)d_in[6];
    const float* Wo   = (const float*)d_in[7];
    const float* bo   = (const float*)d_in[8];
    const float* ln1g = (const float*)d_in[9];
    const float* ln1b = (const float*)d_in[10];
    const float* c1w  = (const float*)d_in[11];
    const float* c1b  = (const float*)d_in[12];
    const float* c2w  = (const float*)d_in[13];
    const float* c2b  = (const float*)d_in[14];
    const float* ln2g = (const float*)d_in[15];
    const float* ln2b = (const float*)d_in[16];
    float* out = (float*)d_out;

    cudaFuncSetAttribute(gemm_mma<0>, cudaFuncAttributeMaxDynamicSharedMemorySize, GSMEM);
    cudaFuncSetAttribute(gemm_mma<1>, cudaFuncAttributeMaxDynamicSharedMemorySize, GSMEM);
    cudaFuncSetAttribute(gemm_mma<2>, cudaFuncAttributeMaxDynamicSharedMemorySize, GSMEM);

    u16 *xh,*xl,*rh,*rl,*x1h,*x1l,*hh,*hl;
    u16 *wqh,*wql,*wkh,*wkl,*wvh,*wvl,*woh,*wol,*c1h,*c1l,*c2h,*c2l;
    float *v, *G, *x1, *part;
    SYM(xh, t_x_hi);   SYM(xl, t_x_lo);
    SYM(rh, t_r_hi);   SYM(rl, t_r_lo);
    SYM(x1h, t_x1_hi); SYM(x1l, t_x1_lo);
    SYM(hh, t_h_hi);   SYM(hl, t_h_lo);
    SYM(wqh, t_wq_hi); SYM(wql, t_wq_lo);
    SYM(wkh, t_wk_hi); SYM(wkl, t_wk_lo);
    SYM(wvh, t_wv_hi); SYM(wvl, t_wv_lo);
    SYM(woh, t_wo_hi); SYM(wol, t_wo_lo);
    SYM(c1h, t_c1_hi); SYM(c1l, t_c1_lo);
    SYM(c2h, t_c2_hi); SYM(c2l, t_c2_lo);
    SYM(v, g_v); SYM(G, g_G); SYM(x1, g_x1); SYM(part, g_part);

    float* fq = G;                              // fp32 q
    float* fk = G + (size_t)MM * DD;            // fp32 k
    float* qT = (float*)hh;                     // transposed q (aliases t_h_hi)
    float* kT = (float*)hl;                     // transposed k (aliases t_h_lo)
    float2* partials = (float2*)x1;             // FFT partials (aliases g_x1)
    float2* S = (float2*)part;                  // reduced spectrum

    // split x; transpose+split weights
    split_x<<<(MM*DD)/1024, 256>>>(x, xh, xl);
    wsplit<<<dim3(DD/32, DD/32), 256>>>(Wq, wqh, wql, DD, DD);
    wsplit<<<dim3(DD/32, DD/32), 256>>>(Wk, wkh, wkl, DD, DD);
    wsplit<<<dim3(DD/32, DD/32), 256>>>(Wv, wvh, wvl, DD, DD);
    wsplit<<<dim3(DD/32, DD/32), 256>>>(Wo, woh, wol, DD, DD);
    wsplit<<<dim3(FF/32, DD/32), 256>>>(c1w, c1h, c1l, DD, FF);
    wsplit<<<dim3(DD/32, FF/32), 256>>>(c2w, c2h, c2l, FF, DD);

    // QKV (q,k to fp32 for FFT; v to fp32 for roll)
    gemm_mma<0><<<dim3(8,128,1), 256, GSMEM>>>(xh, xl, wqh, wql, bq,
        fq, nullptr, nullptr, DD, DD, 0, 0, 0);
    gemm_mma<0><<<dim3(8,128,1), 256, GSMEM>>>(xh, xl, wkh, wkl, bk,
        fk, nullptr, nullptr, DD, DD, 0, 0, 0);
    gemm_mma<0><<<dim3(8,128,1), 256, GSMEM>>>(xh, xl, wvh, wvl, bv,
        v, nullptr, nullptr, DD, DD, 0, 0, 0);

    // mean_value via FFT correlation (replaces the Gram GEMM)
    transpose_bt<<<dim3(DD/32, LL/32, BB), 256>>>(fq, qT);
    transpose_bt<<<dim3(DD/32, LL/32, BB), 256>>>(fk, kT);
    fft_corr<<<dim3(128, BB), 256, 5120 * sizeof(float2)>>>(qT, kT, partials);
    reduce_spec<<<(BB*LL)/256, 256>>>(partials, S);
    ifft_mv<<<BB, 256, 3072 * sizeof(float2)>>>(S);

    topk_softmax<<<BB, 256>>>();
    roll_combine<<<dim3(LL, BB), 128>>>();

    // attn = rolled @ Wo + bo  (fp32 into g_v, reused)
    gemm_mma<0><<<dim3(8,128,1), 256, GSMEM>>>(rh, rl, woh, wol, bo,
        v, nullptr, nullptr, DD, DD, 0, 0, 0);

    // x1 = LN(x + attn) (+ split)
    add_ln<1><<<MM, 128>>>(x, v, ln1g, ln1b, x1, x1h, x1l);

    // h = relu(x1 @ c1 + b)  (split out; overwrites dead qT/kT region)
    gemm_mma<2><<<dim3(32,128,1), 256, GSMEM>>>(x1h, x1l, c1h, c1l, c1b,
        nullptr, hh, hl, DD, FF, 0, 0, 0);

    // y = h @ c2 + b  (fp32 into G, dead after transpose)
    gemm_mma<0><<<dim3(8,128,1), 256, GSMEM>>>(hh, hl, c2h, c2l, c2b,
        G, nullptr, nullptr, FF, DD, 0, 0, 0);

    // out = LN(x1 + y)
    add_ln<0><<<MM, 128>>>(x1, G, ln2g, ln2b, out, nullptr, nullptr);
}

// round 12
// speedup vs baseline: 1.7079x; 1.2302x over previous
#include <cuda_runtime.h>
#include <cuda_bf16.h>
#include <cuda_fp16.h>
#include <math.h>

#define BB 8
#define LL 2048
#define DD 1024
#define FF 4096
#define MM 16384
#define TOPK 7
#define LMASK 2047

typedef unsigned short u16;
typedef unsigned int   u32;

// ---------------- device scratch (no allocation) --------------------------
__device__ u16 t_x_hi[(size_t)MM*DD],  t_x_lo[(size_t)MM*DD];   // bf16 (q,k)
__device__ u16 t_r_hi[(size_t)MM*DD],  t_r_lo[(size_t)MM*DD];   // r fp16 | x fp16
__device__ u16 t_x1_hi[(size_t)MM*DD], t_x1_lo[(size_t)MM*DD];  // x1 fp16 (hi only)
__device__ u16 t_h_hi[(size_t)MM*FF],  t_h_lo[(size_t)MM*FF];   // h fp16 / qT,kT fp32
__device__ u16 t_wq_hi[DD*DD], t_wq_lo[DD*DD];                  // bf16
__device__ u16 t_wk_hi[DD*DD], t_wk_lo[DD*DD];                  // bf16
__device__ u16 t_wv_hi[DD*DD], t_wv_lo[DD*DD];                  // fp16
__device__ u16 t_wo_hi[DD*DD], t_wo_lo[DD*DD];                  // fp16
__device__ u16 t_c1_hi[(size_t)FF*DD], t_c1_lo[(size_t)FF*DD];  // fp16
__device__ u16 t_c2_hi[(size_t)DD*FF], t_c2_lo[(size_t)DD*FF];  // fp16

__device__ float g_v[(size_t)MM*DD];     // v fp32; later attn
__device__ float g_G[(size_t)BB*LL*LL];  // fq | fk fp32; later y
__device__ float g_x1[(size_t)MM*DD];    // FFT partials early; x1 fp32 later
__device__ float g_part[BB*8*LL];        // reduced spectrum (float2)
__device__ float g_mv[BB*LL];
__device__ float g_w[BB*8];
__device__ int   g_delay[8];

// ---------------- helpers --------------------------------------------------
__device__ __forceinline__ u32 smem_u32(const void* p) {
    u32 a;
    asm("{ .reg .u64 t; cvta.to.shared.u64 t, %1; cvt.u32.u64 %0, t; }"
        : "=r"(a) : "l"(p));
    return a;
}

__device__ __forceinline__ void split2(float v0, float v1, u32& h, u32& l) {
    __nv_bfloat16 h0 = __float2bfloat16(v0), h1 = __float2bfloat16(v1);
    __nv_bfloat16 l0 = __float2bfloat16(v0 - __bfloat162float(h0));
    __nv_bfloat16 l1 = __float2bfloat16(v1 - __bfloat162float(h1));
    h = (u32)__bfloat16_as_ushort(h0) | ((u32)__bfloat16_as_ushort(h1) << 16);
    l = (u32)__bfloat16_as_ushort(l0) | ((u32)__bfloat16_as_ushort(l1) << 16);
}

__device__ __forceinline__ void split2h(float v0, float v1, u32& h, u32& l) {
    __half h0 = __float2half_rn(v0), h1 = __float2half_rn(v1);
    __half l0 = __float2half_rn(v0 - __half2float(h0));
    __half l1 = __float2half_rn(v1 - __half2float(h1));
    h = (u32)__half_as_ushort(h0) | ((u32)__half_as_ushort(h1) << 16);
    l = (u32)__half_as_ushort(l0) | ((u32)__half_as_ushort(l1) << 16);
}

__device__ __forceinline__ u32 pack_h2(float v0, float v1) {
    __half2 p = __floats2half2_rn(v0, v1);
    return *reinterpret_cast<u32*>(&p);
}

#define CPA(sa, gp) \
    asm volatile("cp.async.cg.shared.global [%0], [%1], 16;" \
        :: "r"(sa), "l"(gp))

#define MMA_BF(c, a, b) \
    asm volatile("mma.sync.aligned.m16n8k16.row.col.f32.bf16.bf16.f32 " \
        "{%0,%1,%2,%3},{%4,%5,%6,%7},{%8,%9},{%0,%1,%2,%3};" \
        : "+f"((c)[0]), "+f"((c)[1]), "+f"((c)[2]), "+f"((c)[3]) \
        : "r"((a)[0]), "r"((a)[1]), "r"((a)[2]), "r"((a)[3]), \
          "r"((b)[0]), "r"((b)[1]))

#define MMA_H(c, a, b) \
    asm volatile("mma.sync.aligned.m16n8k16.row.col.f32.f16.f16.f32 " \
        "{%0,%1,%2,%3},{%4,%5,%6,%7},{%8,%9},{%0,%1,%2,%3};" \
        : "+f"((c)[0]), "+f"((c)[1]), "+f"((c)[2]), "+f"((c)[3]) \
        : "r"((a)[0]), "r"((a)[1]), "r"((a)[2]), "r"((a)[3]), \
          "r"((b)[0]), "r"((b)[1]))

#define LDSM4(r, a) \
    asm volatile("ldmatrix.sync.aligned.m8n8.x4.shared.b16 {%0,%1,%2,%3}, [%4];" \
        : "=r"((r)[0]), "=r"((r)[1]), "=r"((r)[2]), "=r"((r)[3]) : "r"(a))
#define LDSM2(r, a) \
    asm volatile("ldmatrix.sync.aligned.m8n8.x2.shared.b16 {%0,%1}, [%2];" \
        : "=r"((r)[0]), "=r"((r)[1]) : "r"(a))

#define KC 32
#define PADH 40

// ---------------- bf16 3-term GEMM (q,k only; round-10 proven) ------------
#define OFF_AL 10240u
#define OFF_BH 20480u
#define OFF_BL 30720u
#define STAGE_B 40960u
#define GSMEM (2*40960)

__global__ __launch_bounds__(256, 2) void gemm_bf3(
    const u16* __restrict__ Ahi, const u16* __restrict__ Alo,
    const u16* __restrict__ Bhi, const u16* __restrict__ Blo,
    const float* __restrict__ bias, float* __restrict__ C, int K, int ldc)
{
    extern __shared__ u16 sm[];
    const int tid = threadIdx.x;
    const int lane = tid & 31, warp = tid >> 5;
    const int wm = warp >> 2, wn = warp & 3;
    const int bx = blockIdx.x, by = blockIdx.y;

    const u16* Ah = Ahi + (size_t)(by * 128) * K;
    const u16* Al = Alo + (size_t)(by * 128) * K;
    const u16* Bh = Bhi + (size_t)(bx * 128) * K;
    const u16* Bl = Blo + (size_t)(bx * 128) * K;

    const u32 smBase = smem_u32(sm);
    const int nC = K >> 5;

    float acc[4][4][4];
    #pragma unroll
    for (int i = 0; i < 4; i++)
        #pragma unroll
        for (int j = 0; j < 4; j++)
            #pragma unroll
            for (int p = 0; p < 4; p++) acc[i][j][p] = 0.f;

    auto load_chunk = [&](int c, int s) {
        u32 st = smBase + s * STAGE_B;
        int k0 = c * KC;
        #pragma unroll
        for (int t = 0; t < 2; t++) {
            int idx = (t << 8) + tid;
            int row = idx >> 2, c16 = idx & 3;
            size_t go = (size_t)row * K + k0 + c16 * 8;
            u32 so = st + (u32)(row * PADH + c16 * 8) * 2;
            CPA(so, Ah + go);
            CPA(so + OFF_AL, Al + go);
        }
        #pragma unroll
        for (int t = 0; t < 2; t++) {
            int idx = (t << 8) + tid;
            int row = idx >> 2, c16 = idx & 3;
            size_t go = (size_t)row * K + k0 + c16 * 8;
            u32 so = st + OFF_BH + (u32)(row * PADH + c16 * 8) * 2;
            CPA(so, Bh + go);
            CPA(so + (OFF_BL - OFF_BH), Bl + go);
        }
        asm volatile("cp.async.commit_group;" ::: "memory");
    };

    load_chunk(0, 0);
    for (int c = 0; c < nC; c++) {
        bool more = (c + 1 < nC);
        if (more) load_chunk(c + 1, (c + 1) & 1);
        if (more) asm volatile("cp.async.wait_group 1;" ::: "memory");
        else      asm volatile("cp.async.wait_group 0;" ::: "memory");
        __syncthreads();

        u32 st = smBase + (u32)(c & 1) * STAGE_B;
        #pragma unroll
        for (int ks = 0; ks < 2; ks++) {
            int ko = ks * 16;
            u32 b_h[4][2], b_l[4][2];
            #pragma unroll
            for (int ni = 0; ni < 4; ni++) {
                int r = wn * 32 + ni * 8 + (lane & 7);
                int kk = ko + (((lane >> 3) & 1) << 3);
                u32 ba = st + OFF_BH + (u32)(r * PADH + kk) * 2;
                LDSM2(b_h[ni], ba);
                LDSM2(b_l[ni], ba + (OFF_BL - OFF_BH));
            }
            #pragma unroll
            for (int mi = 0; mi < 4; mi++) {
                int r = wm * 64 + mi * 16 + (lane & 15);
                int kk = ko + ((lane >> 4) << 3);
                u32 aa = st + (u32)(r * PADH + kk) * 2;
                u32 a_h[4], a_l[4];
                LDSM4(a_h, aa);
                LDSM4(a_l, aa + OFF_AL);
                #pragma unroll
                for (int ni = 0; ni < 4; ni++) {
                    MMA_BF(acc[mi][ni], a_h, b_h[ni]);
                    MMA_BF(acc[mi][ni], a_h, b_l[ni]);
                    MMA_BF(acc[mi][ni], a_l, b_h[ni]);
                }
            }
        }
        __syncthreads();
    }

    const int r0 = by * 128 + wm * 64;
    const int c0b = bx * 128 + wn * 32;
    #pragma unroll
    for (int mi = 0; mi < 4; mi++) {
        #pragma unroll
        for (int ni = 0; ni < 4; ni++) {
            int rA = r0 + mi * 16 + (lane >> 2);
            int cc = c0b + ni * 8 + (lane & 3) * 2;
            float v0 = acc[mi][ni][0], v1 = acc[mi][ni][1];
            float v2 = acc[mi][ni][2], v3 = acc[mi][ni][3];
            if (bias) {
                float bb0 = __ldg(bias + cc), bb1 = __ldg(bias + cc + 1);
                v0 += bb0; v1 += bb1; v2 += bb0; v3 += bb1;
            }
            *(float2*)(C + (size_t)rA * ldc + cc)       = make_float2(v0, v1);
            *(float2*)(C + (size_t)(rA + 8) * ldc + cc) = make_float2(v2, v3);
        }
    }
}

// ---------------- fp16 2-term GEMM: C = A16 @ (Bhi+Blo)^T -----------------
// A single fp16; B fp16 hi/lo. Stage: A 10240 | Bhi 10240 | Blo 10240.
#define H_OFF_BH 10240u
#define H_OFF_BL 20480u
#define H_STAGE 30720u
#define GSMEM_H (2*30720)

template<int OMODE>  // 0 = fp32 out, 1 = fp16 out, 2 = fp16+relu out
__global__ __launch_bounds__(256, 2) void gemm_h2(
    const u16* __restrict__ A16,
    const u16* __restrict__ Bhi, const u16* __restrict__ Blo,
    const float* __restrict__ bias, float* __restrict__ C,
    u16* __restrict__ O16, int K, int ldc)
{
    extern __shared__ u16 sm[];
    const int tid = threadIdx.x;
    const int lane = tid & 31, warp = tid >> 5;
    const int wm = warp >> 2, wn = warp & 3;
    const int bx = blockIdx.x, by = blockIdx.y;

    const u16* Ap = A16 + (size_t)(by * 128) * K;
    const u16* Bh = Bhi + (size_t)(bx * 128) * K;
    const u16* Bl = Blo + (size_t)(bx * 128) * K;

    const u32 smBase = smem_u32(sm);
    const int nC = K >> 5;

    float acc[4][4][4];
    #pragma unroll
    for (int i = 0; i < 4; i++)
        #pragma unroll
        for (int j = 0; j < 4; j++)
            #pragma unroll
            for (int p = 0; p < 4; p++) acc[i][j][p] = 0.f;

    auto load_chunk = [&](int c, int s) {
        u32 st = smBase + s * H_STAGE;
        int k0 = c * KC;
        #pragma unroll
        for (int t = 0; t < 2; t++) {
            int idx = (t << 8) + tid;
            int row = idx >> 2, c16 = idx & 3;
            size_t go = (size_t)row * K + k0 + c16 * 8;
            u32 off = (u32)(row * PADH + c16 * 8) * 2;
            CPA(st + off, Ap + go);
            CPA(st + H_OFF_BH + off, Bh + go);
            CPA(st + H_OFF_BL + off, Bl + go);
        }
        asm volatile("cp.async.commit_group;" ::: "memory");
    };

    load_chunk(0, 0);
    for (int c = 0; c < nC; c++) {
        bool more = (c + 1 < nC);
        if (more) load_chunk(c + 1, (c + 1) & 1);
        if (more) asm volatile("cp.async.wait_group 1;" ::: "memory");
        else      asm volatile("cp.async.wait_group 0;" ::: "memory");
        __syncthreads();

        u32 st = smBase + (u32)(c & 1) * H_STAGE;
        #pragma unroll
        for (int ks = 0; ks < 2; ks++) {
            int ko = ks * 16;
            u32 b_h[4][2], b_l[4][2];
            #pragma unroll
            for (int ni = 0; ni < 4; ni++) {
                int r = wn * 32 + ni * 8 + (lane & 7);
                int kk = ko + (((lane >> 3) & 1) << 3);
                u32 ba = st + H_OFF_BH + (u32)(r * PADH + kk) * 2;
                LDSM2(b_h[ni], ba);
                LDSM2(b_l[ni], ba + (H_OFF_BL - H_OFF_BH));
            }
            #pragma unroll
            for (int mi = 0; mi < 4; mi++) {
                int r = wm * 64 + mi * 16 + (lane & 15);
                int kk = ko + ((lane >> 4) << 3);
                u32 a[4];
                LDSM4(a, st + (u32)(r * PADH + kk) * 2);
                #pragma unroll
                for (int ni = 0; ni < 4; ni++) {
                    MMA_H(acc[mi][ni], a, b_h[ni]);
                    MMA_H(acc[mi][ni], a, b_l[ni]);
                }
            }
        }
        __syncthreads();
    }

    const int r0 = by * 128 + wm * 64;
    const int c0b = bx * 128 + wn * 32;
    #pragma unroll
    for (int mi = 0; mi < 4; mi++) {
        #pragma unroll
        for (int ni = 0; ni < 4; ni++) {
            int rA = r0 + mi * 16 + (lane >> 2);
            int cc = c0b + ni * 8 + (lane & 3) * 2;
            float v0 = acc[mi][ni][0], v1 = acc[mi][ni][1];
            float v2 = acc[mi][ni][2], v3 = acc[mi][ni][3];
            if (bias) {
                float bb0 = __ldg(bias + cc), bb1 = __ldg(bias + cc + 1);
                v0 += bb0; v1 += bb1; v2 += bb0; v3 += bb1;
            }
            if (OMODE == 2) {
                v0 = fmaxf(v0, 0.f); v1 = fmaxf(v1, 0.f);
                v2 = fmaxf(v2, 0.f); v3 = fmaxf(v3, 0.f);
            }
            if (OMODE == 0) {
                *(float2*)(C + (size_t)rA * ldc + cc)       = make_float2(v0, v1);
                *(float2*)(C + (size_t)(rA + 8) * ldc + cc) = make_float2(v2, v3);
            } else {
                *(u32*)(O16 + (size_t)rA * ldc + cc)       = pack_h2(v0, v1);
                *(u32*)(O16 + (size_t)(rA + 8) * ldc + cc) = pack_h2(v2, v3);
            }
        }
    }
}

// ---------------- splits ---------------------------------------------------
// x -> bf16 hi/lo (for q,k) + fp16 single (for v)
__global__ __launch_bounds__(256) void split_x(
    const float* __restrict__ s, u16* __restrict__ hi, u16* __restrict__ lo,
    u16* __restrict__ x16)
{
    size_t i = ((size_t)blockIdx.x * 256 + threadIdx.x) * 4;
    float4 v = *(const float4*)(s + i);
    u32 h0, l0, h1, l1;
    split2(v.x, v.y, h0, l0);
    split2(v.z, v.w, h1, l1);
    *(uint2*)(hi + i) = make_uint2(h0, h1);
    *(uint2*)(lo + i) = make_uint2(l0, l1);
    *(uint2*)(x16 + i) = make_uint2(pack_h2(v.x, v.y), pack_h2(v.z, v.w));
}

template<int FP16>
__global__ __launch_bounds__(256) void wsplit(
    const float* __restrict__ W, u16* __restrict__ hi, u16* __restrict__ lo,
    int K, int N)
{
    __shared__ float t[32][33];
    int n0 = blockIdx.x * 32, k0 = blockIdx.y * 32;
    int tx = threadIdx.x & 31, ty = threadIdx.x >> 5;
    #pragma unroll
    for (int j = 0; j < 32; j += 8)
        t[ty + j][tx] = W[(size_t)(k0 + ty + j) * N + n0 + tx];
    __syncthreads();
    #pragma unroll
    for (int j = 0; j < 32; j += 8) {
        float v = t[tx][ty + j];
        size_t o = (size_t)(n0 + ty + j) * K + k0 + tx;
        if (FP16) {
            __half h = __float2half_rn(v);
            __half l = __float2half_rn(v - __half2float(h));
            hi[o] = __half_as_ushort(h);
            lo[o] = __half_as_ushort(l);
        } else {
            __nv_bfloat16 h = __float2bfloat16(v);
            __nv_bfloat16 l = __float2bfloat16(v - __bfloat162float(h));
            hi[o] = __bfloat16_as_ushort(h);
            lo[o] = __bfloat16_as_ushort(l);
        }
    }
}

// ---------------- FFT path (round-11 proven) ------------------------------
__global__ __launch_bounds__(256) void transpose_bt(
    const float* __restrict__ in, float* __restrict__ out)
{
    __shared__ float t[32][33];
    int b = blockIdx.z;
    int d0 = blockIdx.x * 32, t0 = blockIdx.y * 32;
    int tx = threadIdx.x & 31, ty = threadIdx.x >> 5;
    #pragma unroll
    for (int j = 0; j < 32; j += 8)
        t[ty + j][tx] = in[((size_t)b * LL + t0 + ty + j) * DD + d0 + tx];
    __syncthreads();
    #pragma unroll
    for (int j = 0; j < 32; j += 8)
        out[((size_t)b * DD + d0 + ty + j) * LL + t0 + tx] = t[tx][ty + j];
}

__device__ __forceinline__ void fft2048(float2* z, const float2* tw, int tid)
{
    #pragma unroll
    for (int s = 1; s <= 11; s++) {
        int half = 1 << (s - 1);
        for (int i = tid; i < 1024; i += 256) {
            int pos  = i & (half - 1);
            int idx0 = ((i >> (s - 1)) << s) + pos;
            int idx1 = idx0 + half;
            float2 w = tw[pos << (11 - s)];
            float2 u = z[idx0], v = z[idx1];
            float vr = v.x * w.x - v.y * w.y;
            float vi = v.x * w.y + v.y * w.x;
            z[idx0] = make_float2(u.x + vr, u.y + vi);
            z[idx1] = make_float2(u.x - vr, u.y - vi);
        }
        __syncthreads();
    }
}

__global__ __launch_bounds__(256) void fft_corr(
    const float* __restrict__ qT, const float* __restrict__ kT,
    float2* __restrict__ partial)
{
    extern __shared__ float2 smf[];
    float2* z   = smf;
    float2* tw  = smf + 2048;
    float2* acc = smf + 3072;
    int tid = threadIdx.x, dg = blockIdx.x, b = blockIdx.y;

    for (int j = tid; j < 1024; j += 256) {
        float sv, cv;
        sincosf(-6.283185307179586f * (float)j / 2048.0f, &sv, &cv);
        tw[j] = make_float2(cv, sv);
    }
    for (int f = tid; f < 2048; f += 256) acc[f] = make_float2(0.f, 0.f);
    __syncthreads();

    for (int j = 0; j < 8; j++) {
        int d = dg * 8 + j;
        const float* qr = qT + ((size_t)b * DD + d) * LL;
        const float* kr = kT + ((size_t)b * DD + d) * LL;
        for (int t = tid; t < 2048; t += 256) {
            int r = __brev((u32)t) >> 21;
            z[r] = make_float2(qr[t], kr[t]);
        }
        __syncthreads();
        fft2048(z, tw, tid);
        for (int f = tid; f < 2048; f += 256) {
            int m = (2048 - f) & 2047;
            float a = z[f].x, bb = z[f].y, c = z[m].x, d2 = z[m].y;
            float re = ((a + c) * (bb + d2) - (bb - d2) * (a - c)) * 0.25f;
            float im = -((a * a - c * c) + (bb * bb - d2 * d2)) * 0.25f;
            acc[f].x += re; acc[f].y += im;
        }
        __syncthreads();
    }
    float2* out = partial + ((size_t)b * 128 + dg) * 2048;
    for (int f = tid; f < 2048; f += 256) out[f] = acc[f];
}

__global__ void reduce_spec(const float2* __restrict__ partial, float2* __restrict__ S)
{
    int idx = blockIdx.x * 256 + threadIdx.x;
    int b = idx >> 11, f = idx & 2047;
    float sx = 0.f, sy = 0.f;
    for (int dg = 0; dg < 128; dg++) {
        float2 p = partial[((size_t)b * 128 + dg) * 2048 + f];
        sx += p.x; sy += p.y;
    }
    S[idx] = make_float2(sx, sy);
}

__global__ __launch_bounds__(256) void ifft_mv(const float2* __restrict__ S)
{
    extern __shared__ float2 smf[];
    float2* z  = smf;
    float2* tw = smf + 2048;
    int tid = threadIdx.x, b = blockIdx.x;
    for (int j = tid; j < 1024; j += 256) {
        float sv, cv;
        sincosf(-6.283185307179586f * (float)j / 2048.0f, &sv, &cv);
        tw[j] = make_float2(cv, sv);
    }
    for (int f = tid; f < 2048; f += 256) {
        int r = __brev((u32)f) >> 21;
        z[r] = S[b * 2048 + f];
    }
    __syncthreads();
    fft2048(z, tw, tid);
    const float sc = 1.0f / (2048.0f * 1024.0f);
    for (int l = tid; l < 2048; l += 256)
        g_mv[b * 2048 + l] = z[l].x * sc;
}

// ---------------- topk / roll / layernorm ---------------------------------
__global__ void topk_softmax()
{
    int b = blockIdx.x, tid = threadIdx.x;
    __shared__ float vals[LL];
    __shared__ float rv[256];
    __shared__ int   ri[256];
    __shared__ float topv[TOPK];
    __shared__ int   topi[TOPK];

    for (int i = tid; i < LL; i += 256) vals[i] = g_mv[b * LL + i];
    __syncthreads();
    for (int it = 0; it < TOPK; ++it) {
        float bv = -INFINITY; int bi = 0;
        for (int i = tid; i < LL; i += 256) {
            float v = vals[i];
            if (v > bv) { bv = v; bi = i; }
        }
        rv[tid] = bv; ri[tid] = bi;
        __syncthreads();
        for (int s = 128; s > 0; s >>= 1) {
            if (tid < s) {
                if (rv[tid+s] > rv[tid] ||
                    (rv[tid+s] == rv[tid] && ri[tid+s] < ri[tid])) {
                    rv[tid] = rv[tid+s]; ri[tid] = ri[tid+s];
                }
            }
            __syncthreads();
        }
        if (tid == 0) { topv[it] = rv[0]; topi[it] = ri[0]; vals[ri[0]] = -INFINITY; }
        __syncthreads();
    }
    if (tid == 0) {
        float mx = topv[0], e[TOPK], s = 0.f;
        #pragma unroll
        for (int i = 0; i < TOPK; i++) { e[i] = expf(topv[i] - mx); s += e[i]; }
        float inv = 1.f / s;
        #pragma unroll
        for (int i = 0; i < TOPK; i++) g_w[b * 8 + i] = e[i] * inv;
        if (b == 0)
            #pragma unroll
            for (int i = 0; i < TOPK; i++) g_delay[i] = topi[i];
    }
}

// rolled -> fp16 single (t_r_hi)
__global__ __launch_bounds__(128) void roll_combine()
{
    int l = blockIdx.x, b = blockIdx.y, tid = threadIdx.x;
    float w[TOPK]; int rows[TOPK];
    #pragma unroll
    for (int i = 0; i < TOPK; i++) {
        w[i] = g_w[b * 8 + i];
        rows[i] = (l + g_delay[i]) & LMASK;
    }
    int d0 = tid * 8;
    float acc[8] = {0,0,0,0,0,0,0,0};
    #pragma unroll
    for (int i = 0; i < TOPK; i++) {
        const float* vp = g_v + ((size_t)(b * LL + rows[i])) * DD + d0;
        float4 p0 = *(const float4*)vp, p1 = *(const float4*)(vp + 4);
        acc[0] = fmaf(w[i], p0.x, acc[0]); acc[1] = fmaf(w[i], p0.y, acc[1]);
        acc[2] = fmaf(w[i], p0.z, acc[2]); acc[3] = fmaf(w[i], p0.w, acc[3]);
        acc[4] = fmaf(w[i], p1.x, acc[4]); acc[5] = fmaf(w[i], p1.y, acc[5]);
        acc[6] = fmaf(w[i], p1.z, acc[6]); acc[7] = fmaf(w[i], p1.w, acc[7]);
    }
    size_t base = (size_t)(b * LL + l) * DD + d0;
    uint4 o;
    o.x = pack_h2(acc[0], acc[1]); o.y = pack_h2(acc[2], acc[3]);
    o.z = pack_h2(acc[4], acc[5]); o.w = pack_h2(acc[6], acc[7]);
    *(uint4*)(t_r_hi + base) = o;
}

// out = LN(A + B); SPLIT emits fp16 single too
template<int SPLIT>
__global__ __launch_bounds__(128) void add_ln(
    const float* __restrict__ A, const float* __restrict__ Bv,
    const float* __restrict__ g, const float* __restrict__ bt,
    float* __restrict__ out, u16* __restrict__ O16)
{
    int row = blockIdx.x, tid = threadIdx.x;
    const float* pa = A  + (size_t)row * DD;
    const float* pb = Bv + (size_t)row * DD;
    __shared__ float red[128];
    int c0 = tid * 8;

    float v[8];
    float4 a0 = *(const float4*)(pa + c0), a1 = *(const float4*)(pa + c0 + 4);
    float4 b0 = *(const float4*)(pb + c0), b1 = *(const float4*)(pb + c0 + 4);
    v[0]=a0.x+b0.x; v[1]=a0.y+b0.y; v[2]=a0.z+b0.z; v[3]=a0.w+b0.w;
    v[4]=a1.x+b1.x; v[5]=a1.y+b1.y; v[6]=a1.z+b1.z; v[7]=a1.w+b1.w;
    float s = 0.f;
    #pragma unroll
    for (int j = 0; j < 8; j++) s += v[j];
    red[tid] = s; __syncthreads();
    for (int st = 64; st > 0; st >>= 1) {
        if (tid < st) red[tid] += red[tid + st];
        __syncthreads();
    }
    float mean = red[0] * (1.f / (float)DD);
    __syncthreads();
    float vs = 0.f;
    #pragma unroll
    for (int j = 0; j < 8; j++) { float d = v[j] - mean; vs += d * d; }
    red[tid] = vs; __syncthreads();
    for (int st = 64; st > 0; st >>= 1) {
        if (tid < st) red[tid] += red[tid + st];
        __syncthreads();
    }
    float rstd = rsqrtf(red[0] * (1.f / (float)DD) + 1e-6f);

    float o[8];
    #pragma unroll
    for (int j = 0; j < 8; j++)
        o[j] = (v[j] - mean) * rstd * g[c0 + j] + bt[c0 + j];
    float* po = out + (size_t)row * DD;
    *(float4*)(po + c0)     = make_float4(o[0], o[1], o[2], o[3]);
    *(float4*)(po + c0 + 4) = make_float4(o[4], o[5], o[6], o[7]);

    if (SPLIT) {
        size_t base = (size_t)row * DD + c0;
        uint4 pk;
        pk.x = pack_h2(o[0], o[1]); pk.y = pack_h2(o[2], o[3]);
        pk.z = pack_h2(o[4], o[5]); pk.w = pack_h2(o[6], o[7]);
        *(uint4*)(O16 + base) = pk;
    }
}

// -------------------------------------------------------------------------
#define SYM(p, s) cudaGetSymbolAddress((void**)&p, s)

extern "C" void kernel_launch(void* const* d_in, const int* in_sizes, int n_in,
                              void* d_out, int out_size)
{
    const float* x    = (const float*)d_in[0];
    const float* Wq   = (const float*)d_in[1];
    const float* bq   = (const float*)d_in[2];
    const float* Wk   = (const float*)d_in[3];
    const float* bk   = (const float*)d_in[4];
    const float* Wv   = (const float*)d_in[5];
    const float* bv   = (const float*)d_in[6];
    const float* Wo   = (const float*)d_in[7];
    const float* bo   = (const float*)d_in[8];
    const float* ln1g = (const float*)d_in[9];
    const float* ln1b = (const float*)d_in[10];
    const float* c1w  = (const float*)d_in[11];
    const float* c1b  = (const float*)d_in[12];
    const float* c2w  = (const float*)d_in[13];
    const float* c2b  = (const float*)d_in[14];
    const float* ln2g = (const float*)d_in[15];
    const float* ln2b = (const float*)d_in[16];
    float* out = (float*)d_out;

    cudaFuncSetAttribute(gemm_bf3, cudaFuncAttributeMaxDynamicSharedMemorySize, GSMEM);
    cudaFuncSetAttribute(gemm_h2<0>, cudaFuncAttributeMaxDynamicSharedMemorySize, GSMEM_H);
    cudaFuncSetAttribute(gemm_h2<1>, cudaFuncAttributeMaxDynamicSharedMemorySize, GSMEM_H);
    cudaFuncSetAttribute(gemm_h2<2>, cudaFuncAttributeMaxDynamicSharedMemorySize, GSMEM_H);

    u16 *xh,*xl,*rh,*rl,*x1h,*hh;
    u16 *wqh,*wql,*wkh,*wkl,*wvh,*wvl,*woh,*wol,*c1h,*c1l,*c2h,*c2l;
    float *v, *G, *x1, *part;
    SYM(xh, t_x_hi);   SYM(xl, t_x_lo);
    SYM(rh, t_r_hi);   SYM(rl, t_r_lo);
    SYM(x1h, t_x1_hi);
    SYM(hh, t_h_hi);
    SYM(wqh, t_wq_hi); SYM(wql, t_wq_lo);
    SYM(wkh, t_wk_hi); SYM(wkl, t_wk_lo);
    SYM(wvh, t_wv_hi); SYM(wvl, t_wv_lo);
    SYM(woh, t_wo_hi); SYM(wol, t_wo_lo);
    SYM(c1h, t_c1_hi); SYM(c1l, t_c1_lo);
    SYM(c2h, t_c2_hi); SYM(c2l, t_c2_lo);
    SYM(v, g_v); SYM(G, g_G); SYM(x1, g_x1); SYM(part, g_part);

    float* fq = G;                         // fp32 q
    float* fk = G + (size_t)MM * DD;       // fp32 k
    u16* x16 = rl;                         // x fp16 single (aliases t_r_lo)
    float* qT = (float*)hh;                // transposed q (aliases t_h_hi)
    u16* hl16; SYM(hl16, t_h_lo);
    float* kT = (float*)hl16;              // transposed k (aliases t_h_lo)
    float2* partials = (float2*)x1;        // FFT partials (aliases g_x1)
    float2* S = (float2*)part;             // reduced spectrum

    // splits
    split_x<<<(MM*DD)/1024, 256>>>(x, xh, xl, x16);
    wsplit<0><<<dim3(DD/32, DD/32), 256>>>(Wq, wqh, wql, DD, DD);
    wsplit<0><<<dim3(DD/32, DD/32), 256>>>(Wk, wkh, wkl, DD, DD);
    wsplit<1><<<dim3(DD/32, DD/32), 256>>>(Wv, wvh, wvl, DD, DD);
    wsplit<1><<<dim3(DD/32, DD/32), 256>>>(Wo, woh, wol, DD, DD);
    wsplit<1><<<dim3(FF/32, DD/32), 256>>>(c1w, c1h, c1l, DD, FF);
    wsplit<1><<<dim3(DD/32, FF/32), 256>>>(c2w, c2h, c2l, FF, DD);

    // q,k: bf16 3-term (protects top-k); v: fp16 2-term
    gemm_bf3<<<dim3(8,128), 256, GSMEM>>>(xh, xl, wqh, wql, bq, fq, DD, DD);
    gemm_bf3<<<dim3(8,128), 256, GSMEM>>>(xh, xl, wkh, wkl, bk, fk, DD, DD);
    gemm_h2<0><<<dim3(8,128), 256, GSMEM_H>>>(x16, wvh, wvl, bv, v, nullptr, DD, DD);

    // mean_value via FFT correlation
    transpose_bt<<<dim3(DD/32, LL/32, BB), 256>>>(fq, qT);
    transpose_bt<<<dim3(DD/32, LL/32, BB), 256>>>(fk, kT);
    fft_corr<<<dim3(128, BB), 256, 5120 * sizeof(float2)>>>(qT, kT, partials);
    reduce_spec<<<(BB*LL)/256, 256>>>(partials, S);
    ifft_mv<<<BB, 256, 3072 * sizeof(float2)>>>(S);

    topk_softmax<<<BB, 256>>>();
    roll_combine<<<dim3(LL, BB), 128>>>();   // -> t_r_hi fp16

    // attn = rolled @ Wo + bo  (fp32 into g_v, reused)
    gemm_h2<0><<<dim3(8,128), 256, GSMEM_H>>>(rh, woh, wol, bo, v, nullptr, DD, DD);

    // x1 = LN(x + attn) (+ fp16 single)
    add_ln<1><<<MM, 128>>>(x, v, ln1g, ln1b, x1, x1h);

    // h = relu(x1 @ c1 + b)  -> fp16 into t_h_hi (qT dead)
    gemm_h2<2><<<dim3(32,128), 256, GSMEM_H>>>(x1h, c1h, c1l, c1b, nullptr, hh, DD, FF);

    // y = h @ c2 + b  (fp32 into G, dead)
    gemm_h2<0><<<dim3(8,128), 256, GSMEM_H>>>(hh, c2h, c2l, c2b, G, nullptr, FF, DD);

    // out = LN(x1 + y)
    add_ln<0><<<MM, 128>>>(x1, G, ln2g, ln2b, out, nullptr);
}

// round 14
// speedup vs baseline: 1.8372x; 1.0757x over previous
#include <cuda_runtime.h>
#include <cuda_bf16.h>
#include <cuda_fp16.h>
#include <math.h>

#define BB 8
#define LL 2048
#define DD 1024
#define FF 4096
#define MM 16384
#define TOPK 7
#define LMASK 2047

typedef unsigned short u16;
typedef unsigned int   u32;

// ---------------- device scratch (no allocation) --------------------------
__device__ u16 t_x16[(size_t)MM*DD];                            // x fp16
__device__ u16 t_r16[(size_t)MM*DD];                            // rolled fp16
__device__ u16 t_x116[(size_t)MM*DD];                           // x1 fp16
__device__ u16 t_h_hi[(size_t)MM*FF],  t_h_lo[(size_t)MM*FF];   // h fp16 / qT,kT fp32
__device__ u16 t_wq_hi[DD*DD], t_wq_lo[DD*DD];                  // fp16 hi/lo
__device__ u16 t_wk_hi[DD*DD], t_wk_lo[DD*DD];
__device__ u16 t_wv_hi[DD*DD], t_wv_lo[DD*DD];
__device__ u16 t_wo_hi[DD*DD], t_wo_lo[DD*DD];
__device__ u16 t_c1_hi[(size_t)FF*DD], t_c1_lo[(size_t)FF*DD];
__device__ u16 t_c2_hi[(size_t)DD*FF], t_c2_lo[(size_t)DD*FF];

__device__ float g_v[(size_t)MM*DD];     // v fp32; later attn
__device__ float g_G[(size_t)BB*LL*LL];  // fq | fk fp32; later y
__device__ float g_x1[(size_t)MM*DD];    // FFT partials early; x1 fp32 later
__device__ float g_part[BB*8*LL];        // reduced spectrum (float2)
__device__ float g_mv[BB*LL];
__device__ float g_w[BB*8];
__device__ int   g_delay[8];

// ---------------- helpers --------------------------------------------------
__device__ __forceinline__ u32 smem_u32(const void* p) {
    u32 a;
    asm("{ .reg .u64 t; cvta.to.shared.u64 t, %1; cvt.u32.u64 %0, t; }"
        : "=r"(a) : "l"(p));
    return a;
}

__device__ __forceinline__ u32 pack_h2(float v0, float v1) {
    __half2 p = __floats2half2_rn(v0, v1);
    return *reinterpret_cast<u32*>(&p);
}

#define CPA(sa, gp) \
    asm volatile("cp.async.cg.shared.global [%0], [%1], 16;" \
        :: "r"(sa), "l"(gp))

#define MMA_H(c, a, b) \
    asm volatile("mma.sync.aligned.m16n8k16.row.col.f32.f16.f16.f32 " \
        "{%0,%1,%2,%3},{%4,%5,%6,%7},{%8,%9},{%0,%1,%2,%3};" \
        : "+f"((c)[0]), "+f"((c)[1]), "+f"((c)[2]), "+f"((c)[3]) \
        : "r"((a)[0]), "r"((a)[1]), "r"((a)[2]), "r"((a)[3]), \
          "r"((b)[0]), "r"((b)[1]))

#define LDSM4(r, a) \
    asm volatile("ldmatrix.sync.aligned.m8n8.x4.shared.b16 {%0,%1,%2,%3}, [%4];" \
        : "=r"((r)[0]), "=r"((r)[1]), "=r"((r)[2]), "=r"((r)[3]) : "r"(a))
#define LDSM2(r, a) \
    asm volatile("ldmatrix.sync.aligned.m8n8.x2.shared.b16 {%0,%1}, [%2];" \
        : "=r"((r)[0]), "=r"((r)[1]) : "r"(a))

#define KC 32
#define PADH 40

// ---------------- fp16 2-term GEMM: C = A16 @ (Bhi+Blo)^T -----------------
// CTA 128x128, 8 warps (2x4) x (64x32), KC=32, 3-stage cp.async, 2 CTA/SM.
#define H_OFF_BH 10240u
#define H_OFF_BL 20480u
#define H_STAGE 30720u
#define GSMEM_H (3*30720)

template<int OMODE>  // 0 = fp32 out, 1 = fp16 out, 2 = fp16+relu out
__global__ __launch_bounds__(256, 2) void gemm_h2(
    const u16* __restrict__ A16,
    const u16* __restrict__ Bhi, const u16* __restrict__ Blo,
    const float* __restrict__ bias, float* __restrict__ C,
    u16* __restrict__ O16, int K, int ldc)
{
    extern __shared__ u16 sm[];
    const int tid = threadIdx.x;
    const int lane = tid & 31, warp = tid >> 5;
    const int wm = warp >> 2, wn = warp & 3;
    const int bx = blockIdx.x, by = blockIdx.y;

    const u16* Ap = A16 + (size_t)(by * 128) * K;
    const u16* Bh = Bhi + (size_t)(bx * 128) * K;
    const u16* Bl = Blo + (size_t)(bx * 128) * K;

    const u32 smBase = smem_u32(sm);
    const int nC = K >> 5;

    float acc[4][4][4];
    #pragma unroll
    for (int i = 0; i < 4; i++)
        #pragma unroll
        for (int j = 0; j < 4; j++)
            #pragma unroll
            for (int p = 0; p < 4; p++) acc[i][j][p] = 0.f;

    auto load_chunk = [&](int c, int s) {
        u32 st = smBase + (u32)s * H_STAGE;
        int k0 = c * KC;
        #pragma unroll
        for (int t = 0; t < 2; t++) {
            int idx = (t << 8) + tid;
            int row = idx >> 2, c16 = idx & 3;
            size_t go = (size_t)row * K + k0 + c16 * 8;
            u32 off = (u32)(row * PADH + c16 * 8) * 2;
            CPA(st + off, Ap + go);
            CPA(st + H_OFF_BH + off, Bh + go);
            CPA(st + H_OFF_BL + off, Bl + go);
        }
        asm volatile("cp.async.commit_group;" ::: "memory");
    };

    load_chunk(0, 0);
    if (nC > 1) load_chunk(1, 1);

    for (int c = 0; c < nC; c++) {
        if (c == nC - 1) asm volatile("cp.async.wait_group 0;" ::: "memory");
        else             asm volatile("cp.async.wait_group 1;" ::: "memory");
        __syncthreads();
        if (c + 2 < nC) load_chunk(c + 2, (c + 2) % 3);

        u32 st = smBase + (u32)(c % 3) * H_STAGE;
        #pragma unroll
        for (int ks = 0; ks < 2; ks++) {
            int ko = ks * 16;
            u32 b_h[4][2], b_l[4][2];
            #pragma unroll
            for (int ni = 0; ni < 4; ni++) {
                int r = wn * 32 + ni * 8 + (lane & 7);
                int kk = ko + (((lane >> 3) & 1) << 3);
                u32 ba = st + H_OFF_BH + (u32)(r * PADH + kk) * 2;
                LDSM2(b_h[ni], ba);
                LDSM2(b_l[ni], ba + (H_OFF_BL - H_OFF_BH));
            }
            #pragma unroll
            for (int mi = 0; mi < 4; mi++) {
                int r = wm * 64 + mi * 16 + (lane & 15);
                int kk = ko + ((lane >> 4) << 3);
                u32 a[4];
                LDSM4(a, st + (u32)(r * PADH + kk) * 2);
                #pragma unroll
                for (int ni = 0; ni < 4; ni++) {
                    MMA_H(acc[mi][ni], a, b_h[ni]);
                    MMA_H(acc[mi][ni], a, b_l[ni]);
                }
            }
        }
    }

    const int r0 = by * 128 + wm * 64;
    const int c0b = bx * 128 + wn * 32;
    #pragma unroll
    for (int mi = 0; mi < 4; mi++) {
        #pragma unroll
        for (int ni = 0; ni < 4; ni++) {
            int rA = r0 + mi * 16 + (lane >> 2);
            int cc = c0b + ni * 8 + (lane & 3) * 2;
            float v0 = acc[mi][ni][0], v1 = acc[mi][ni][1];
            float v2 = acc[mi][ni][2], v3 = acc[mi][ni][3];
            if (bias) {
                float bb0 = __ldg(bias + cc), bb1 = __ldg(bias + cc + 1);
                v0 += bb0; v1 += bb1; v2 += bb0; v3 += bb1;
            }
            if (OMODE == 2) {
                v0 = fmaxf(v0, 0.f); v1 = fmaxf(v1, 0.f);
                v2 = fmaxf(v2, 0.f); v3 = fmaxf(v3, 0.f);
            }
            if (OMODE == 0) {
                *(float2*)(C + (size_t)rA * ldc + cc)       = make_float2(v0, v1);
                *(float2*)(C + (size_t)(rA + 8) * ldc + cc) = make_float2(v2, v3);
            } else {
                *(u32*)(O16 + (size_t)rA * ldc + cc)       = pack_h2(v0, v1);
                *(u32*)(O16 + (size_t)(rA + 8) * ldc + cc) = pack_h2(v2, v3);
            }
        }
    }
}

// ---------------- splits ---------------------------------------------------
__global__ __launch_bounds__(256) void split_x(
    const float* __restrict__ s, u16* __restrict__ x16)
{
    size_t i = ((size_t)blockIdx.x * 256 + threadIdx.x) * 4;
    float4 v = *(const float4*)(s + i);
    *(uint2*)(x16 + i) = make_uint2(pack_h2(v.x, v.y), pack_h2(v.z, v.w));
}

// W[K,N] row-major -> [N,K] fp16 hi/lo (transpose + split)
__global__ __launch_bounds__(256) void wsplit(
    const float* __restrict__ W, u16* __restrict__ hi, u16* __restrict__ lo,
    int K, int N)
{
    __shared__ float t[32][33];
    int n0 = blockIdx.x * 32, k0 = blockIdx.y * 32;
    int tx = threadIdx.x & 31, ty = threadIdx.x >> 5;
    #pragma unroll
    for (int j = 0; j < 32; j += 8)
        t[ty + j][tx] = W[(size_t)(k0 + ty + j) * N + n0 + tx];
    __syncthreads();
    #pragma unroll
    for (int j = 0; j < 32; j += 8) {
        float v = t[tx][ty + j];
        size_t o = (size_t)(n0 + ty + j) * K + k0 + tx;
        __half h = __float2half_rn(v);
        __half l = __float2half_rn(v - __half2float(h));
        hi[o] = __half_as_ushort(h);
        lo[o] = __half_as_ushort(l);
    }
}

// ---------------- FFT path (round-11 proven) ------------------------------
__global__ __launch_bounds__(256) void transpose_bt(
    const float* __restrict__ in, float* __restrict__ out)
{
    __shared__ float t[32][33];
    int b = blockIdx.z;
    int d0 = blockIdx.x * 32, t0 = blockIdx.y * 32;
    int tx = threadIdx.x & 31, ty = threadIdx.x >> 5;
    #pragma unroll
    for (int j = 0; j < 32; j += 8)
        t[ty + j][tx] = in[((size_t)b * LL + t0 + ty + j) * DD + d0 + tx];
    __syncthreads();
    #pragma unroll
    for (int j = 0; j < 32; j += 8)
        out[((size_t)b * DD + d0 + ty + j) * LL + t0 + tx] = t[tx][ty + j];
}

__device__ __forceinline__ void fft2048(float2* z, const float2* tw, int tid)
{
    #pragma unroll
    for (int s = 1; s <= 11; s++) {
        int half = 1 << (s - 1);
        for (int i = tid; i < 1024; i += 256) {
            int pos  = i & (half - 1);
            int idx0 = ((i >> (s - 1)) << s) + pos;
            int idx1 = idx0 + half;
            float2 w = tw[pos << (11 - s)];
            float2 u = z[idx0], v = z[idx1];
            float vr = v.x * w.x - v.y * w.y;
            float vi = v.x * w.y + v.y * w.x;
            z[idx0] = make_float2(u.x + vr, u.y + vi);
            z[idx1] = make_float2(u.x - vr, u.y - vi);
        }
        __syncthreads();
    }
}

__global__ __launch_bounds__(256) void fft_corr(
    const float* __restrict__ qT, const float* __restrict__ kT,
    float2* __restrict__ partial)
{
    extern __shared__ float2 smf[];
    float2* z   = smf;
    float2* tw  = smf + 2048;
    float2* acc = smf + 3072;
    int tid = threadIdx.x, dg = blockIdx.x, b = blockIdx.y;

    for (int j = tid; j < 1024; j += 256) {
        float sv, cv;
        sincosf(-6.283185307179586f * (float)j / 2048.0f, &sv, &cv);
        tw[j] = make_float2(cv, sv);
    }
    for (int f = tid; f < 2048; f += 256) acc[f] = make_float2(0.f, 0.f);
    __syncthreads();

    for (int j = 0; j < 8; j++) {
        int d = dg * 8 + j;
        const float* qr = qT + ((size_t)b * DD + d) * LL;
        const float* kr = kT + ((size_t)b * DD + d) * LL;
        for (int t = tid; t < 2048; t += 256) {
            int r = __brev((u32)t) >> 21;
            z[r] = make_float2(qr[t], kr[t]);
        }
        __syncthreads();
        fft2048(z, tw, tid);
        for (int f = tid; f < 2048; f += 256) {
            int m = (2048 - f) & 2047;
            float a = z[f].x, bb = z[f].y, c = z[m].x, d2 = z[m].y;
            float re = ((a + c) * (bb + d2) - (bb - d2) * (a - c)) * 0.25f;
            float im = -((a * a - c * c) + (bb * bb - d2 * d2)) * 0.25f;
            acc[f].x += re; acc[f].y += im;
        }
        __syncthreads();
    }
    float2* out = partial + ((size_t)b * 128 + dg) * 2048;
    for (int f = tid; f < 2048; f += 256) out[f] = acc[f];
}

__global__ void reduce_spec(const float2* __restrict__ partial, float2* __restrict__ S)
{
    int idx = blockIdx.x * 256 + threadIdx.x;
    int b = idx >> 11, f = idx & 2047;
    float sx = 0.f, sy = 0.f;
    for (int dg = 0; dg < 128; dg++) {
        float2 p = partial[((size_t)b * 128 + dg) * 2048 + f];
        sx += p.x; sy += p.y;
    }
    S[idx] = make_float2(sx, sy);
}

__global__ __launch_bounds__(256) void ifft_mv(const float2* __restrict__ S)
{
    extern __shared__ float2 smf[];
    float2* z  = smf;
    float2* tw = smf + 2048;
    int tid = threadIdx.x, b = blockIdx.x;
    for (int j = tid; j < 1024; j += 256) {
        float sv, cv;
        sincosf(-6.283185307179586f * (float)j / 2048.0f, &sv, &cv);
        tw[j] = make_float2(cv, sv);
    }
    for (int f = tid; f < 2048; f += 256) {
        int r = __brev((u32)f) >> 21;
        z[r] = S[b * 2048 + f];
    }
    __syncthreads();
    fft2048(z, tw, tid);
    const float sc = 1.0f / (2048.0f * 1024.0f);
    for (int l = tid; l < 2048; l += 256)
        g_mv[b * 2048 + l] = z[l].x * sc;
}

// ---------------- topk / roll / layernorm ---------------------------------
__global__ void topk_softmax()
{
    int b = blockIdx.x, tid = threadIdx.x;
    __shared__ float vals[LL];
    __shared__ float rv[256];
    __shared__ int   ri[256];
    __shared__ float topv[TOPK];
    __shared__ int   topi[TOPK];

    for (int i = tid; i < LL; i += 256) vals[i] = g_mv[b * LL + i];
    __syncthreads();
    for (int it = 0; it < TOPK; ++it) {
        float bv = -INFINITY; int bi = 0;
        for (int i = tid; i < LL; i += 256) {
            float v = vals[i];
            if (v > bv) { bv = v; bi = i; }
        }
        rv[tid] = bv; ri[tid] = bi;
        __syncthreads();
        for (int s = 128; s > 0; s >>= 1) {
            if (tid < s) {
                if (rv[tid+s] > rv[tid] ||
                    (rv[tid+s] == rv[tid] && ri[tid+s] < ri[tid])) {
                    rv[tid] = rv[tid+s]; ri[tid] = ri[tid+s];
                }
            }
            __syncthreads();
        }
        if (tid == 0) { topv[it] = rv[0]; topi[it] = ri[0]; vals[ri[0]] = -INFINITY; }
        __syncthreads();
    }
    if (tid == 0) {
        float mx = topv[0], e[TOPK], s = 0.f;
        #pragma unroll
        for (int i = 0; i < TOPK; i++) { e[i] = expf(topv[i] - mx); s += e[i]; }
        float inv = 1.f / s;
        #pragma unroll
        for (int i = 0; i < TOPK; i++) g_w[b * 8 + i] = e[i] * inv;
        if (b == 0)
            #pragma unroll
            for (int i = 0; i < TOPK; i++) g_delay[i] = topi[i];
    }
}

// rolled -> fp16 single (t_r16)
__global__ __launch_bounds__(128) void roll_combine()
{
    int l = blockIdx.x, b = blockIdx.y, tid = threadIdx.x;
    float w[TOPK]; int rows[TOPK];
    #pragma unroll
    for (int i = 0; i < TOPK; i++) {
        w[i] = g_w[b * 8 + i];
        rows[i] = (l + g_delay[i]) & LMASK;
    }
    int d0 = tid * 8;
    float acc[8] = {0,0,0,0,0,0,0,0};
    #pragma unroll
    for (int i = 0; i < TOPK; i++) {
        const float* vp = g_v + ((size_t)(b * LL + rows[i])) * DD + d0;
        float4 p0 = *(const float4*)vp, p1 = *(const float4*)(vp + 4);
        acc[0] = fmaf(w[i], p0.x, acc[0]); acc[1] = fmaf(w[i], p0.y, acc[1]);
        acc[2] = fmaf(w[i], p0.z, acc[2]); acc[3] = fmaf(w[i], p0.w, acc[3]);
        acc[4] = fmaf(w[i], p1.x, acc[4]); acc[5] = fmaf(w[i], p1.y, acc[5]);
        acc[6] = fmaf(w[i], p1.z, acc[6]); acc[7] = fmaf(w[i], p1.w, acc[7]);
    }
    size_t base = (size_t)(b * LL + l) * DD + d0;
    uint4 o;
    o.x = pack_h2(acc[0], acc[1]); o.y = pack_h2(acc[2], acc[3]);
    o.z = pack_h2(acc[4], acc[5]); o.w = pack_h2(acc[6], acc[7]);
    *(uint4*)(t_r16 + base) = o;
}

// out = LN(A + B); SPLIT emits fp16 single too
template<int SPLIT>
__global__ __launch_bounds__(128) void add_ln(
    const float* __restrict__ A, const float* __restrict__ Bv,
    const float* __restrict__ g, const float* __restrict__ bt,
    float* __restrict__ out, u16* __restrict__ O16)
{
    int row = blockIdx.x, tid = threadIdx.x;
    const float* pa = A  + (size_t)row * DD;
    const float* pb = Bv + (size_t)row * DD;
    __shared__ float red[128];
    int c0 = tid * 8;

    float v[8];
    float4 a0 = *(const float4*)(pa + c0), a1 = *(const float4*)(pa + c0 + 4);
    float4 b0 = *(const float4*)(pb + c0), b1 = *(const float4*)(pb + c0 + 4);
    v[0]=a0.x+b0.x; v[1]=a0.y+b0.y; v[2]=a0.z+b0.z; v[3]=a0.w+b0.w;
    v[4]=a1.x+b1.x; v[5]=a1.y+b1.y; v[6]=a1.z+b1.z; v[7]=a1.w+b1.w;
    float s = 0.f;
    #pragma unroll
    for (int j = 0; j < 8; j++) s += v[j];
    red[tid] = s; __syncthreads();
    for (int st = 64; st > 0; st >>= 1) {
        if (tid < st) red[tid] += red[tid + st];
        __syncthreads();
    }
    float mean = red[0] * (1.f / (float)DD);
    __syncthreads();
    float vs = 0.f;
    #pragma unroll
    for (int j = 0; j < 8; j++) { float d = v[j] - mean; vs += d * d; }
    red[tid] = vs; __syncthreads();
    for (int st = 64; st > 0; st >>= 1) {
        if (tid < st) red[tid] += red[tid + st];
        __syncthreads();
    }
    float rstd = rsqrtf(red[0] * (1.f / (float)DD) + 1e-6f);

    float o[8];
    #pragma unroll
    for (int j = 0; j < 8; j++)
        o[j] = (v[j] - mean) * rstd * g[c0 + j] + bt[c0 + j];
    float* po = out + (size_t)row * DD;
    *(float4*)(po + c0)     = make_float4(o[0], o[1], o[2], o[3]);
    *(float4*)(po + c0 + 4) = make_float4(o[4], o[5], o[6], o[7]);

    if (SPLIT) {
        size_t base = (size_t)row * DD + c0;
        uint4 pk;
        pk.x = pack_h2(o[0], o[1]); pk.y = pack_h2(o[2], o[3]);
        pk.z = pack_h2(o[4], o[5]); pk.w = pack_h2(o[6], o[7]);
        *(uint4*)(O16 + base) = pk;
    }
}

// -------------------------------------------------------------------------
#define SYM(p, s) cudaGetSymbolAddress((void**)&p, s)

extern "C" void kernel_launch(void* const* d_in, const int* in_sizes, int n_in,
                              void* d_out, int out_size)
{
    const float* x    = (const float*)d_in[0];
    const float* Wq   = (const float*)d_in[1];
    const float* bq   = (const float*)d_in[2];
    const float* Wk   = (const float*)d_in[3];
    const float* bk   = (const float*)d_in[4];
    const float* Wv   = (const float*)d_in[5];
    const float* bv   = (const float*)d_in[6];
    const float* Wo   = (const float*)d_in[7];
    const float* bo   = (const float*)d_in[8];
    const float* ln1g = (const float*)d_in[9];
    const float* ln1b = (const float*)d_in[10];
    const float* c1w  = (const float*)d_in[11];
    const float* c1b  = (const float*)d_in[12];
    const float* c2w  = (const float*)d_in[13];
    const float* c2b  = (const float*)d_in[14];
    const float* ln2g = (const float*)d_in[15];
    const float* ln2b = (const float*)d_in[16];
    float* out = (float*)d_out;

    cudaFuncSetAttribute(gemm_h2<0>, cudaFuncAttributeMaxDynamicSharedMemorySize, GSMEM_H);
    cudaFuncSetAttribute(gemm_h2<1>, cudaFuncAttributeMaxDynamicSharedMemorySize, GSMEM_H);
    cudaFuncSetAttribute(gemm_h2<2>, cudaFuncAttributeMaxDynamicSharedMemorySize, GSMEM_H);

    u16 *x16, *r16, *x116, *hh, *hl;
    u16 *wqh,*wql,*wkh,*wkl,*wvh,*wvl,*woh,*wol,*c1h,*c1l,*c2h,*c2l;
    float *v, *G, *x1, *part;
    SYM(x16, t_x16);
    SYM(r16, t_r16);
    SYM(x116, t_x116);
    SYM(hh, t_h_hi);   SYM(hl, t_h_lo);
    SYM(wqh, t_wq_hi); SYM(wql, t_wq_lo);
    SYM(wkh, t_wk_hi); SYM(wkl, t_wk_lo);
    SYM(wvh, t_wv_hi); SYM(wvl, t_wv_lo);
    SYM(woh, t_wo_hi); SYM(wol, t_wo_lo);
    SYM(c1h, t_c1_hi); SYM(c1l, t_c1_lo);
    SYM(c2h, t_c2_hi); SYM(c2l, t_c2_lo);
    SYM(v, g_v); SYM(G, g_G); SYM(x1, g_x1); SYM(part, g_part);

    float* fq = G;                         // fp32 q
    float* fk = G + (size_t)MM * DD;       // fp32 k
    float* qT = (float*)hh;                // transposed q (aliases t_h_hi)
    float* kT = (float*)hl;                // transposed k (aliases t_h_lo)
    float2* partials = (float2*)x1;        // FFT partials (aliases g_x1)
    float2* S = (float2*)part;             // reduced spectrum

    // splits (all fp16)
    split_x<<<(MM*DD)/1024, 256>>>(x, x16);
    wsplit<<<dim3(DD/32, DD/32), 256>>>(Wq, wqh, wql, DD, DD);
    wsplit<<<dim3(DD/32, DD/32), 256>>>(Wk, wkh, wkl, DD, DD);
    wsplit<<<dim3(DD/32, DD/32), 256>>>(Wv, wvh, wvl, DD, DD);
    wsplit<<<dim3(DD/32, DD/32), 256>>>(Wo, woh, wol, DD, DD);
    wsplit<<<dim3(FF/32, DD/32), 256>>>(c1w, c1h, c1l, DD, FF);
    wsplit<<<dim3(DD/32, FF/32), 256>>>(c2w, c2h, c2l, FF, DD);

    // QKV: all fp16 2-term
    gemm_h2<0><<<dim3(8,128), 256, GSMEM_H>>>(x16, wqh, wql, bq, fq, nullptr, DD, DD);
    gemm_h2<0><<<dim3(8,128), 256, GSMEM_H>>>(x16, wkh, wkl, bk, fk, nullptr, DD, DD);
    gemm_h2<0><<<dim3(8,128), 256, GSMEM_H>>>(x16, wvh, wvl, bv, v, nullptr, DD, DD);

    // mean_value via FFT correlation
    transpose_bt<<<dim3(DD/32, LL/32, BB), 256>>>(fq, qT);
    transpose_bt<<<dim3(DD/32, LL/32, BB), 256>>>(fk, kT);
    fft_corr<<<dim3(128, BB), 256, 5120 * sizeof(float2)>>>(qT, kT, partials);
    reduce_spec<<<(BB*LL)/256, 256>>>(partials, S);
    ifft_mv<<<BB, 256, 3072 * sizeof(float2)>>>(S);

    topk_softmax<<<BB, 256>>>();
    roll_combine<<<dim3(LL, BB), 128>>>();   // -> t_r16 fp16

    // attn = rolled @ Wo + bo  (fp32 into g_v, reused)
    gemm_h2<0><<<dim3(8,128), 256, GSMEM_H>>>(r16, woh, wol, bo, v, nullptr, DD, DD);

    // x1 = LN(x + attn) (+ fp16 single)
    add_ln<1><<<MM, 128>>>(x, v, ln1g, ln1b, x1, x116);

    // h = relu(x1 @ c1 + b)  -> fp16 into t_h_hi (qT dead)
    gemm_h2<2><<<dim3(32,128), 256, GSMEM_H>>>(x116, c1h, c1l, c1b, nullptr, hh, DD, FF);

    // y = h @ c2 + b  (fp32 into G, dead)
    gemm_h2<0><<<dim3(8,128), 256, GSMEM_H>>>(hh, c2h, c2l, c2b, G, nullptr, FF, DD);

    // out = LN(x1 + y)
    add_ln<0><<<MM, 128>>>(x1, G, ln2g, ln2b, out, nullptr);
}

// round 15
// speedup vs baseline: 2.7932x; 1.5204x over previous
#include <cuda_runtime.h>
#include <cuda_fp16.h>
#include <math.h>

#define BB 8
#define LL 2048
#define DD 1024
#define FF 4096
#define MM 16384
#define TOPK 7
#define LMASK 2047

typedef unsigned short u16;
typedef unsigned int   u32;

// ---------------- device scratch (no allocation) --------------------------
__device__ u16 t_x16[(size_t)MM*DD];                            // x fp16
__device__ u16 t_r16[(size_t)MM*DD];                            // rolled fp16
__device__ u16 t_x116[(size_t)MM*DD];                           // x1 fp16
__device__ u16 t_h_hi[(size_t)MM*FF], t_h_lo[(size_t)MM*FF];    // h fp16 / qT,kT fp32
__device__ u16 t_wq[DD*DD], t_wk[DD*DD], t_wv[DD*DD], t_wo[DD*DD];  // fp16 [N,K]
__device__ u16 t_c1[(size_t)FF*DD], t_c2[(size_t)DD*FF];            // fp16 [N,K]

__device__ float g_v[(size_t)MM*DD];     // v fp32; later attn
__device__ float g_G[(size_t)BB*LL*LL];  // fq | fk fp32; later y
__device__ float g_x1[(size_t)MM*DD];    // FFT partials early; x1 fp32 later
__device__ float g_part[BB*8*LL];        // reduced spectrum (float2)
__device__ float g_mv[BB*LL];
__device__ float g_w[BB*8];
__device__ int   g_delay[8];

// ---------------- helpers --------------------------------------------------
__device__ __forceinline__ u32 smem_u32(const void* p) {
    u32 a;
    asm("{ .reg .u64 t; cvta.to.shared.u64 t, %1; cvt.u32.u64 %0, t; }"
        : "=r"(a) : "l"(p));
    return a;
}

__device__ __forceinline__ u32 pack_h2(float v0, float v1) {
    __half2 p = __floats2half2_rn(v0, v1);
    return *reinterpret_cast<u32*>(&p);
}

#define CPA(sa, gp) \
    asm volatile("cp.async.cg.shared.global [%0], [%1], 16;" \
        :: "r"(sa), "l"(gp))

#define MMA_H(c, a, b) \
    asm volatile("mma.sync.aligned.m16n8k16.row.col.f32.f16.f16.f32 " \
        "{%0,%1,%2,%3},{%4,%5,%6,%7},{%8,%9},{%0,%1,%2,%3};" \
        : "+f"((c)[0]), "+f"((c)[1]), "+f"((c)[2]), "+f"((c)[3]) \
        : "r"((a)[0]), "r"((a)[1]), "r"((a)[2]), "r"((a)[3]), \
          "r"((b)[0]), "r"((b)[1]))

#define LDSM4(r, a) \
    asm volatile("ldmatrix.sync.aligned.m8n8.x4.shared.b16 {%0,%1,%2,%3}, [%4];" \
        : "=r"((r)[0]), "=r"((r)[1]), "=r"((r)[2]), "=r"((r)[3]) : "r"(a))
#define LDSM2(r, a) \
    asm volatile("ldmatrix.sync.aligned.m8n8.x2.shared.b16 {%0,%1}, [%2];" \
        : "=r"((r)[0]), "=r"((r)[1]) : "r"(a))

#define KC 32
#define PADH 40

// ---------------- fp16 1-term GEMM: C = A16 @ B16^T (+bias,+relu) --------
// CTA 128x128, 8 warps (2x4) x (64x32), KC=32, 3-stage cp.async, 2 CTA/SM.
#define H_OFF_B 10240u
#define H_STAGE 20480u
#define GSMEM_H (3*20480)

template<int OMODE>  // 0 = fp32 out, 1 = fp16 out, 2 = fp16+relu out
__global__ __launch_bounds__(256, 2) void gemm_h1(
    const u16* __restrict__ A16, const u16* __restrict__ B16,
    const float* __restrict__ bias, float* __restrict__ C,
    u16* __restrict__ O16, int K, int ldc)
{
    extern __shared__ u16 sm[];
    const int tid = threadIdx.x;
    const int lane = tid & 31, warp = tid >> 5;
    const int wm = warp >> 2, wn = warp & 3;
    const int bx = blockIdx.x, by = blockIdx.y;

    const u16* Ap = A16 + (size_t)(by * 128) * K;
    const u16* Bp = B16 + (size_t)(bx * 128) * K;

    const u32 smBase = smem_u32(sm);
    const int nC = K >> 5;

    float acc[4][4][4];
    #pragma unroll
    for (int i = 0; i < 4; i++)
        #pragma unroll
        for (int j = 0; j < 4; j++)
            #pragma unroll
            for (int p = 0; p < 4; p++) acc[i][j][p] = 0.f;

    auto load_chunk = [&](int c, int s) {
        u32 st = smBase + (u32)s * H_STAGE;
        int k0 = c * KC;
        #pragma unroll
        for (int t = 0; t < 2; t++) {
            int idx = (t << 8) + tid;
            int row = idx >> 2, c16 = idx & 3;
            size_t go = (size_t)row * K + k0 + c16 * 8;
            u32 off = (u32)(row * PADH + c16 * 8) * 2;
            CPA(st + off, Ap + go);
            CPA(st + H_OFF_B + off, Bp + go);
        }
        asm volatile("cp.async.commit_group;" ::: "memory");
    };

    load_chunk(0, 0);
    if (nC > 1) load_chunk(1, 1);

    for (int c = 0; c < nC; c++) {
        if (c == nC - 1) asm volatile("cp.async.wait_group 0;" ::: "memory");
        else             asm volatile("cp.async.wait_group 1;" ::: "memory");
        __syncthreads();
        if (c + 2 < nC) load_chunk(c + 2, (c + 2) % 3);

        u32 st = smBase + (u32)(c % 3) * H_STAGE;
        #pragma unroll
        for (int ks = 0; ks < 2; ks++) {
            int ko = ks * 16;
            u32 b_f[4][2];
            #pragma unroll
            for (int ni = 0; ni < 4; ni++) {
                int r = wn * 32 + ni * 8 + (lane & 7);
                int kk = ko + (((lane >> 3) & 1) << 3);
                LDSM2(b_f[ni], st + H_OFF_B + (u32)(r * PADH + kk) * 2);
            }
            #pragma unroll
            for (int mi = 0; mi < 4; mi++) {
                int r = wm * 64 + mi * 16 + (lane & 15);
                int kk = ko + ((lane >> 4) << 3);
                u32 a[4];
                LDSM4(a, st + (u32)(r * PADH + kk) * 2);
                #pragma unroll
                for (int ni = 0; ni < 4; ni++)
                    MMA_H(acc[mi][ni], a, b_f[ni]);
            }
        }
    }

    const int r0 = by * 128 + wm * 64;
    const int c0b = bx * 128 + wn * 32;
    #pragma unroll
    for (int mi = 0; mi < 4; mi++) {
        #pragma unroll
        for (int ni = 0; ni < 4; ni++) {
            int rA = r0 + mi * 16 + (lane >> 2);
            int cc = c0b + ni * 8 + (lane & 3) * 2;
            float v0 = acc[mi][ni][0], v1 = acc[mi][ni][1];
            float v2 = acc[mi][ni][2], v3 = acc[mi][ni][3];
            if (bias) {
                float bb0 = __ldg(bias + cc), bb1 = __ldg(bias + cc + 1);
                v0 += bb0; v1 += bb1; v2 += bb0; v3 += bb1;
            }
            if (OMODE == 2) {
                v0 = fmaxf(v0, 0.f); v1 = fmaxf(v1, 0.f);
                v2 = fmaxf(v2, 0.f); v3 = fmaxf(v3, 0.f);
            }
            if (OMODE == 0) {
                *(float2*)(C + (size_t)rA * ldc + cc)       = make_float2(v0, v1);
                *(float2*)(C + (size_t)(rA + 8) * ldc + cc) = make_float2(v2, v3);
            } else {
                *(u32*)(O16 + (size_t)rA * ldc + cc)       = pack_h2(v0, v1);
                *(u32*)(O16 + (size_t)(rA + 8) * ldc + cc) = pack_h2(v2, v3);
            }
        }
    }
}

// ---------------- splits ---------------------------------------------------
__global__ __launch_bounds__(256) void split_x(
    const float* __restrict__ s, u16* __restrict__ x16)
{
    size_t i = ((size_t)blockIdx.x * 256 + threadIdx.x) * 4;
    float4 v = *(const float4*)(s + i);
    *(uint2*)(x16 + i) = make_uint2(pack_h2(v.x, v.y), pack_h2(v.z, v.w));
}

// W[K,N] row-major -> [N,K] fp16 (transpose + round)
__global__ __launch_bounds__(256) void wsplit(
    const float* __restrict__ W, u16* __restrict__ O, int K, int N)
{
    __shared__ float t[32][33];
    int n0 = blockIdx.x * 32, k0 = blockIdx.y * 32;
    int tx = threadIdx.x & 31, ty = threadIdx.x >> 5;
    #pragma unroll
    for (int j = 0; j < 32; j += 8)
        t[ty + j][tx] = W[(size_t)(k0 + ty + j) * N + n0 + tx];
    __syncthreads();
    #pragma unroll
    for (int j = 0; j < 32; j += 8) {
        float v = t[tx][ty + j];
        O[(size_t)(n0 + ty + j) * K + k0 + tx] =
            __half_as_ushort(__float2half_rn(v));
    }
}

// ---------------- FFT path (round-11 proven) ------------------------------
__global__ __launch_bounds__(256) void transpose_bt(
    const float* __restrict__ in, float* __restrict__ out)
{
    __shared__ float t[32][33];
    int b = blockIdx.z;
    int d0 = blockIdx.x * 32, t0 = blockIdx.y * 32;
    int tx = threadIdx.x & 31, ty = threadIdx.x >> 5;
    #pragma unroll
    for (int j = 0; j < 32; j += 8)
        t[ty + j][tx] = in[((size_t)b * LL + t0 + ty + j) * DD + d0 + tx];
    __syncthreads();
    #pragma unroll
    for (int j = 0; j < 32; j += 8)
        out[((size_t)b * DD + d0 + ty + j) * LL + t0 + tx] = t[tx][ty + j];
}

__device__ __forceinline__ void fft2048(float2* z, const float2* tw, int tid)
{
    #pragma unroll
    for (int s = 1; s <= 11; s++) {
        int half = 1 << (s - 1);
        for (int i = tid; i < 1024; i += 256) {
            int pos  = i & (half - 1);
            int idx0 = ((i >> (s - 1)) << s) + pos;
            int idx1 = idx0 + half;
            float2 w = tw[pos << (11 - s)];
            float2 u = z[idx0], v = z[idx1];
            float vr = v.x * w.x - v.y * w.y;
            float vi = v.x * w.y + v.y * w.x;
            z[idx0] = make_float2(u.x + vr, u.y + vi);
            z[idx1] = make_float2(u.x - vr, u.y - vi);
        }
        __syncthreads();
    }
}

__global__ __launch_bounds__(256) void fft_corr(
    const float* __restrict__ qT, const float* __restrict__ kT,
    float2* __restrict__ partial)
{
    extern __shared__ float2 smf[];
    float2* z   = smf;
    float2* tw  = smf + 2048;
    float2* acc = smf + 3072;
    int tid = threadIdx.x, dg = blockIdx.x, b = blockIdx.y;

    for (int j = tid; j < 1024; j += 256) {
        float sv, cv;
        sincosf(-6.283185307179586f * (float)j / 2048.0f, &sv, &cv);
        tw[j] = make_float2(cv, sv);
    }
    for (int f = tid; f < 2048; f += 256) acc[f] = make_float2(0.f, 0.f);
    __syncthreads();

    for (int j = 0; j < 8; j++) {
        int d = dg * 8 + j;
        const float* qr = qT + ((size_t)b * DD + d) * LL;
        const float* kr = kT + ((size_t)b * DD + d) * LL;
        for (int t = tid; t < 2048; t += 256) {
            int r = __brev((u32)t) >> 21;
            z[r] = make_float2(qr[t], kr[t]);
        }
        __syncthreads();
        fft2048(z, tw, tid);
        for (int f = tid; f < 2048; f += 256) {
            int m = (2048 - f) & 2047;
            float a = z[f].x, bb = z[f].y, c = z[m].x, d2 = z[m].y;
            float re = ((a + c) * (bb + d2) - (bb - d2) * (a - c)) * 0.25f;
            float im = -((a * a - c * c) + (bb * bb - d2 * d2)) * 0.25f;
            acc[f].x += re; acc[f].y += im;
        }
        __syncthreads();
    }
    float2* out = partial + ((size_t)b * 128 + dg) * 2048;
    for (int f = tid; f < 2048; f += 256) out[f] = acc[f];
}

__global__ void reduce_spec(const float2* __restrict__ partial, float2* __restrict__ S)
{
    int idx = blockIdx.x * 256 + threadIdx.x;
    int b = idx >> 11, f = idx & 2047;
    float sx = 0.f, sy = 0.f;
    for (int dg = 0; dg < 128; dg++) {
        float2 p = partial[((size_t)b * 128 + dg) * 2048 + f];
        sx += p.x; sy += p.y;
    }
    S[idx] = make_float2(sx, sy);
}

__global__ __launch_bounds__(256) void ifft_mv(const float2* __restrict__ S)
{
    extern __shared__ float2 smf[];
    float2* z  = smf;
    float2* tw = smf + 2048;
    int tid = threadIdx.x, b = blockIdx.x;
    for (int j = tid; j < 1024; j += 256) {
        float sv, cv;
        sincosf(-6.283185307179586f * (float)j / 2048.0f, &sv, &cv);
        tw[j] = make_float2(cv, sv);
    }
    for (int f = tid; f < 2048; f += 256) {
        int r = __brev((u32)f) >> 21;
        z[r] = S[b * 2048 + f];
    }
    __syncthreads();
    fft2048(z, tw, tid);
    const float sc = 1.0f / (2048.0f * 1024.0f);
    for (int l = tid; l < 2048; l += 256)
        g_mv[b * 2048 + l] = z[l].x * sc;
}

// ---------------- topk / roll / layernorm ---------------------------------
__global__ void topk_softmax()
{
    int b = blockIdx.x, tid = threadIdx.x;
    __shared__ float vals[LL];
    __shared__ float rv[256];
    __shared__ int   ri[256];
    __shared__ float topv[TOPK];
    __shared__ int   topi[TOPK];

    for (int i = tid; i < LL; i += 256) vals[i] = g_mv[b * LL + i];
    __syncthreads();
    for (int it = 0; it < TOPK; ++it) {
        float bv = -INFINITY; int bi = 0;
        for (int i = tid; i < LL; i += 256) {
            float v = vals[i];
            if (v > bv) { bv = v; bi = i; }
        }
        rv[tid] = bv; ri[tid] = bi;
        __syncthreads();
        for (int s = 128; s > 0; s >>= 1) {
            if (tid < s) {
                if (rv[tid+s] > rv[tid] ||
                    (rv[tid+s] == rv[tid] && ri[tid+s] < ri[tid])) {
                    rv[tid] = rv[tid+s]; ri[tid] = ri[tid+s];
                }
            }
            __syncthreads();
        }
        if (tid == 0) { topv[it] = rv[0]; topi[it] = ri[0]; vals[ri[0]] = -INFINITY; }
        __syncthreads();
    }
    if (tid == 0) {
        float mx = topv[0], e[TOPK], s = 0.f;
        #pragma unroll
        for (int i = 0; i < TOPK; i++) { e[i] = expf(topv[i] - mx); s += e[i]; }
        float inv = 1.f / s;
        #pragma unroll
        for (int i = 0; i < TOPK; i++) g_w[b * 8 + i] = e[i] * inv;
        if (b == 0)
            #pragma unroll
            for (int i = 0; i < TOPK; i++) g_delay[i] = topi[i];
    }
}

// rolled -> fp16 single (t_r16)
__global__ __launch_bounds__(128) void roll_combine()
{
    int l = blockIdx.x, b = blockIdx.y, tid = threadIdx.x;
    float w[TOPK]; int rows[TOPK];
    #pragma unroll
    for (int i = 0; i < TOPK; i++) {
        w[i] = g_w[b * 8 + i];
        rows[i] = (l + g_delay[i]) & LMASK;
    }
    int d0 = tid * 8;
    float acc[8] = {0,0,0,0,0,0,0,0};
    #pragma unroll
    for (int i = 0; i < TOPK; i++) {
        const float* vp = g_v + ((size_t)(b * LL + rows[i])) * DD + d0;
        float4 p0 = *(const float4*)vp, p1 = *(const float4*)(vp + 4);
        acc[0] = fmaf(w[i], p0.x, acc[0]); acc[1] = fmaf(w[i], p0.y, acc[1]);
        acc[2] = fmaf(w[i], p0.z, acc[2]); acc[3] = fmaf(w[i], p0.w, acc[3]);
        acc[4] = fmaf(w[i], p1.x, acc[4]); acc[5] = fmaf(w[i], p1.y, acc[5]);
        acc[6] = fmaf(w[i], p1.z, acc[6]); acc[7] = fmaf(w[i], p1.w, acc[7]);
    }
    size_t base = (size_t)(b * LL + l) * DD + d0;
    uint4 o;
    o.x = pack_h2(acc[0], acc[1]); o.y = pack_h2(acc[2], acc[3]);
    o.z = pack_h2(acc[4], acc[5]); o.w = pack_h2(acc[6], acc[7]);
    *(uint4*)(t_r16 + base) = o;
}

// out = LN(A + B); SPLIT emits fp16 single too
template<int SPLIT>
__global__ __launch_bounds__(128) void add_ln(
    const float* __restrict__ A, const float* __restrict__ Bv,
    const float* __restrict__ g, const float* __restrict__ bt,
    float* __restrict__ out, u16* __restrict__ O16)
{
    int row = blockIdx.x, tid = threadIdx.x;
    const float* pa = A  + (size_t)row * DD;
    const float* pb = Bv + (size_t)row * DD;
    __shared__ float red[128];
    int c0 = tid * 8;

    float v[8];
    float4 a0 = *(const float4*)(pa + c0), a1 = *(const float4*)(pa + c0 + 4);
    float4 b0 = *(const float4*)(pb + c0), b1 = *(const float4*)(pb + c0 + 4);
    v[0]=a0.x+b0.x; v[1]=a0.y+b0.y; v[2]=a0.z+b0.z; v[3]=a0.w+b0.w;
    v[4]=a1.x+b1.x; v[5]=a1.y+b1.y; v[6]=a1.z+b1.z; v[7]=a1.w+b1.w;
    float s = 0.f;
    #pragma unroll
    for (int j = 0; j < 8; j++) s += v[j];
    red[tid] = s; __syncthreads();
    for (int st = 64; st > 0; st >>= 1) {
        if (tid < st) red[tid] += red[tid + st];
        __syncthreads();
    }
    float mean = red[0] * (1.f / (float)DD);
    __syncthreads();
    float vs = 0.f;
    #pragma unroll
    for (int j = 0; j < 8; j++) { float d = v[j] - mean; vs += d * d; }
    red[tid] = vs; __syncthreads();
    for (int st = 64; st > 0; st >>= 1) {
        if (tid < st) red[tid] += red[tid + st];
        __syncthreads();
    }
    float rstd = rsqrtf(red[0] * (1.f / (float)DD) + 1e-6f);

    float o[8];
    #pragma unroll
    for (int j = 0; j < 8; j++)
        o[j] = (v[j] - mean) * rstd * g[c0 + j] + bt[c0 + j];
    float* po = out + (size_t)row * DD;
    *(float4*)(po + c0)     = make_float4(o[0], o[1], o[2], o[3]);
    *(float4*)(po + c0 + 4) = make_float4(o[4], o[5], o[6], o[7]);

    if (SPLIT) {
        size_t base = (size_t)row * DD + c0;
        uint4 pk;
        pk.x = pack_h2(o[0], o[1]); pk.y = pack_h2(o[2], o[3]);
        pk.z = pack_h2(o[4], o[5]); pk.w = pack_h2(o[6], o[7]);
        *(uint4*)(O16 + base) = pk;
    }
}

// -------------------------------------------------------------------------
#define SYM(p, s) cudaGetSymbolAddress((void**)&p, s)

extern "C" void kernel_launch(void* const* d_in, const int* in_sizes, int n_in,
                              void* d_out, int out_size)
{
    const float* x    = (const float*)d_in[0];
    const float* Wq   = (const float*)d_in[1];
    const float* bq   = (const float*)d_in[2];
    const float* Wk   = (const float*)d_in[3];
    const float* bk   = (const float*)d_in[4];
    const float* Wv   = (const float*)d_in[5];
    const float* bv   = (const float*)d_in[6];
    const float* Wo   = (const float*)d_in[7];
    const float* bo   = (const float*)d_in[8];
    const float* ln1g = (const float*)d_in[9];
    const float* ln1b = (const float*)d_in[10];
    const float* c1w  = (const float*)d_in[11];
    const float* c1b  = (const float*)d_in[12];
    const float* c2w  = (const float*)d_in[13];
    const float* c2b  = (const float*)d_in[14];
    const float* ln2g = (const float*)d_in[15];
    const float* ln2b = (const float*)d_in[16];
    float* out = (float*)d_out;

    cudaFuncSetAttribute(gemm_h1<0>, cudaFuncAttributeMaxDynamicSharedMemorySize, GSMEM_H);
    cudaFuncSetAttribute(gemm_h1<1>, cudaFuncAttributeMaxDynamicSharedMemorySize, GSMEM_H);
    cudaFuncSetAttribute(gemm_h1<2>, cudaFuncAttributeMaxDynamicSharedMemorySize, GSMEM_H);

    u16 *x16, *r16, *x116, *hh, *hl;
    u16 *wq16, *wk16, *wv16, *wo16, *c116, *c216;
    float *v, *G, *x1, *part;
    SYM(x16, t_x16);
    SYM(r16, t_r16);
    SYM(x116, t_x116);
    SYM(hh, t_h_hi);  SYM(hl, t_h_lo);
    SYM(wq16, t_wq);  SYM(wk16, t_wk);
    SYM(wv16, t_wv);  SYM(wo16, t_wo);
    SYM(c116, t_c1);  SYM(c216, t_c2);
    SYM(v, g_v); SYM(G, g_G); SYM(x1, g_x1); SYM(part, g_part);

    float* fq = G;                         // fp32 q
    float* fk = G + (size_t)MM * DD;       // fp32 k
    float* qT = (float*)hh;                // transposed q (aliases t_h_hi)
    float* kT = (float*)hl;                // transposed k (aliases t_h_lo)
    float2* partials = (float2*)x1;        // FFT partials (aliases g_x1)
    float2* S = (float2*)part;             // reduced spectrum

    // splits (all single fp16)
    split_x<<<(MM*DD)/1024, 256>>>(x, x16);
    wsplit<<<dim3(DD/32, DD/32), 256>>>(Wq, wq16, DD, DD);
    wsplit<<<dim3(DD/32, DD/32), 256>>>(Wk, wk16, DD, DD);
    wsplit<<<dim3(DD/32, DD/32), 256>>>(Wv, wv16, DD, DD);
    wsplit<<<dim3(DD/32, DD/32), 256>>>(Wo, wo16, DD, DD);
    wsplit<<<dim3(FF/32, DD/32), 256>>>(c1w, c116, DD, FF);
    wsplit<<<dim3(DD/32, FF/32), 256>>>(c2w, c216, FF, DD);

    // QKV: fp16 1-term
    gemm_h1<0><<<dim3(8,128), 256, GSMEM_H>>>(x16, wq16, bq, fq, nullptr, DD, DD);
    gemm_h1<0><<<dim3(8,128), 256, GSMEM_H>>>(x16, wk16, bk, fk, nullptr, DD, DD);
    gemm_h1<0><<<dim3(8,128), 256, GSMEM_H>>>(x16, wv16, bv, v, nullptr, DD, DD);

    // mean_value via FFT correlation
    transpose_bt<<<dim3(DD/32, LL/32, BB), 256>>>(fq, qT);
    transpose_bt<<<dim3(DD/32, LL/32, BB), 256>>>(fk, kT);
    fft_corr<<<dim3(128, BB), 256, 5120 * sizeof(float2)>>>(qT, kT, partials);
    reduce_spec<<<(BB*LL)/256, 256>>>(partials, S);
    ifft_mv<<<BB, 256, 3072 * sizeof(float2)>>>(S);

    topk_softmax<<<BB, 256>>>();
    roll_combine<<<dim3(LL, BB), 128>>>();   // -> t_r16 fp16

    // attn = rolled @ Wo + bo  (fp32 into g_v, reused)
    gemm_h1<0><<<dim3(8,128), 256, GSMEM_H>>>(r16, wo16, bo, v, nullptr, DD, DD);

    // x1 = LN(x + attn) (+ fp16 single)
    add_ln<1><<<MM, 128>>>(x, v, ln1g, ln1b, x1, x116);

    // h = relu(x1 @ c1 + b)  -> fp16 into t_h_hi (qT dead)
    gemm_h1<2><<<dim3(32,128), 256, GSMEM_H>>>(x116, c116, c1b, nullptr, hh, DD, FF);

    // y = h @ c2 + b  (fp32 into G, dead)
    gemm_h1<0><<<dim3(8,128), 256, GSMEM_H>>>(hh, c216, c2b, G, nullptr, FF, DD);

    // out = LN(x1 + y)
    add_ln<0><<<MM, 128>>>(x1, G, ln2g, ln2b, out, nullptr);
}

// round 16
// speedup vs baseline: 3.0330x; 1.0859x over previous
#include <cuda_runtime.h>
#include <cuda_fp16.h>
#include <math.h>

#define BB 8
#define LL 2048
#define DD 1024
#define FF 4096
#define MM 16384
#define TOPK 7
#define LMASK 2047

typedef unsigned short u16;
typedef unsigned int   u32;

// ---------------- device scratch (no allocation) --------------------------
__device__ u16 t_x16[(size_t)MM*DD];                            // x fp16
__device__ u16 t_v16[(size_t)MM*DD];                            // v fp16
__device__ u16 t_r16[(size_t)MM*DD];                            // rolled fp16
__device__ u16 t_x116[(size_t)MM*DD];                           // x1 fp16
__device__ u16 t_h_hi[(size_t)MM*FF], t_h_lo[(size_t)MM*FF];    // h fp16 / qT,kT fp32
__device__ u16 t_wq[DD*DD], t_wk[DD*DD], t_wv[DD*DD], t_wo[DD*DD];  // fp16 [N,K]
__device__ u16 t_c1[(size_t)FF*DD], t_c2[(size_t)DD*FF];            // fp16 [N,K]

__device__ float g_v[(size_t)MM*DD];     // attn fp32
__device__ float g_G[(size_t)BB*LL*LL];  // fq | fk fp32; later y
__device__ float g_x1[(size_t)MM*DD];    // FFT partials early; x1 fp32 later
__device__ float g_part[BB*8*LL];        // reduced spectrum (float2)
__device__ float g_mv[BB*LL];
__device__ float g_w[BB*8];
__device__ int   g_delay[8];
__device__ float2 g_twid[1024];          // FFT twiddle table

// ---------------- helpers --------------------------------------------------
__device__ __forceinline__ u32 smem_u32(const void* p) {
    u32 a;
    asm("{ .reg .u64 t; cvta.to.shared.u64 t, %1; cvt.u32.u64 %0, t; }"
        : "=r"(a) : "l"(p));
    return a;
}

__device__ __forceinline__ u32 pack_h2(float v0, float v1) {
    __half2 p = __floats2half2_rn(v0, v1);
    return *reinterpret_cast<u32*>(&p);
}

#define CPA(sa, gp) \
    asm volatile("cp.async.cg.shared.global [%0], [%1], 16;" \
        :: "r"(sa), "l"(gp))

#define MMA_H(c, a, b) \
    asm volatile("mma.sync.aligned.m16n8k16.row.col.f32.f16.f16.f32 " \
        "{%0,%1,%2,%3},{%4,%5,%6,%7},{%8,%9},{%0,%1,%2,%3};" \
        : "+f"((c)[0]), "+f"((c)[1]), "+f"((c)[2]), "+f"((c)[3]) \
        : "r"((a)[0]), "r"((a)[1]), "r"((a)[2]), "r"((a)[3]), \
          "r"((b)[0]), "r"((b)[1]))

#define LDSM4(r, a) \
    asm volatile("ldmatrix.sync.aligned.m8n8.x4.shared.b16 {%0,%1,%2,%3}, [%4];" \
        : "=r"((r)[0]), "=r"((r)[1]), "=r"((r)[2]), "=r"((r)[3]) : "r"(a))
#define LDSM2(r, a) \
    asm volatile("ldmatrix.sync.aligned.m8n8.x2.shared.b16 {%0,%1}, [%2];" \
        : "=r"((r)[0]), "=r"((r)[1]) : "r"(a))

// ---------------- fp16 1-term GEMM: C = A16 @ B16^T (+bias,+relu) --------
// CTA 128x128, 8 warps (2x4) x (64x32), KC=64, 3-stage cp.async, 2 CTA/SM.
#define KC 64
#define PADH 72
#define H_OFF_B 18432u           // 128*72*2
#define H_STAGE 36864u
#define GSMEM_H (3*36864)

template<int OMODE>  // 0 = fp32 out, 1 = fp16 out, 2 = fp16+relu out
__global__ __launch_bounds__(256, 2) void gemm_h1(
    const u16* __restrict__ A16, const u16* __restrict__ B16,
    const float* __restrict__ bias, float* __restrict__ C,
    u16* __restrict__ O16, int K, int ldc)
{
    extern __shared__ u16 sm[];
    const int tid = threadIdx.x;
    const int lane = tid & 31, warp = tid >> 5;
    const int wm = warp >> 2, wn = warp & 3;
    const int bx = blockIdx.x, by = blockIdx.y;

    const u16* Ap = A16 + (size_t)(by * 128) * K;
    const u16* Bp = B16 + (size_t)(bx * 128) * K;

    const u32 smBase = smem_u32(sm);
    const int nC = K >> 6;

    float acc[4][4][4];
    #pragma unroll
    for (int i = 0; i < 4; i++)
        #pragma unroll
        for (int j = 0; j < 4; j++)
            #pragma unroll
            for (int p = 0; p < 4; p++) acc[i][j][p] = 0.f;

    auto load_chunk = [&](int c, int s) {
        u32 st = smBase + (u32)s * H_STAGE;
        int k0 = c * KC;
        #pragma unroll
        for (int t = 0; t < 4; t++) {
            int idx = (t << 8) + tid;
            int row = idx >> 3, c16 = idx & 7;
            size_t go = (size_t)row * K + k0 + c16 * 8;
            u32 off = (u32)(row * PADH + c16 * 8) * 2;
            CPA(st + off, Ap + go);
            CPA(st + H_OFF_B + off, Bp + go);
        }
        asm volatile("cp.async.commit_group;" ::: "memory");
    };

    load_chunk(0, 0);
    if (nC > 1) load_chunk(1, 1);

    for (int c = 0; c < nC; c++) {
        if (c == nC - 1) asm volatile("cp.async.wait_group 0;" ::: "memory");
        else             asm volatile("cp.async.wait_group 1;" ::: "memory");
        __syncthreads();
        if (c + 2 < nC) load_chunk(c + 2, (c + 2) % 3);

        u32 st = smBase + (u32)(c % 3) * H_STAGE;
        #pragma unroll
        for (int ks = 0; ks < 4; ks++) {
            int ko = ks * 16;
            u32 b_f[4][2];
            #pragma unroll
            for (int ni = 0; ni < 4; ni++) {
                int r = wn * 32 + ni * 8 + (lane & 7);
                int kk = ko + (((lane >> 3) & 1) << 3);
                LDSM2(b_f[ni], st + H_OFF_B + (u32)(r * PADH + kk) * 2);
            }
            #pragma unroll
            for (int mi = 0; mi < 4; mi++) {
                int r = wm * 64 + mi * 16 + (lane & 15);
                int kk = ko + ((lane >> 4) << 3);
                u32 a[4];
                LDSM4(a, st + (u32)(r * PADH + kk) * 2);
                #pragma unroll
                for (int ni = 0; ni < 4; ni++)
                    MMA_H(acc[mi][ni], a, b_f[ni]);
            }
        }
    }

    const int r0 = by * 128 + wm * 64;
    const int c0b = bx * 128 + wn * 32;
    #pragma unroll
    for (int mi = 0; mi < 4; mi++) {
        #pragma unroll
        for (int ni = 0; ni < 4; ni++) {
            int rA = r0 + mi * 16 + (lane >> 2);
            int cc = c0b + ni * 8 + (lane & 3) * 2;
            float v0 = acc[mi][ni][0], v1 = acc[mi][ni][1];
            float v2 = acc[mi][ni][2], v3 = acc[mi][ni][3];
            if (bias) {
                float bb0 = __ldg(bias + cc), bb1 = __ldg(bias + cc + 1);
                v0 += bb0; v1 += bb1; v2 += bb0; v3 += bb1;
            }
            if (OMODE == 2) {
                v0 = fmaxf(v0, 0.f); v1 = fmaxf(v1, 0.f);
                v2 = fmaxf(v2, 0.f); v3 = fmaxf(v3, 0.f);
            }
            if (OMODE == 0) {
                *(float2*)(C + (size_t)rA * ldc + cc)       = make_float2(v0, v1);
                *(float2*)(C + (size_t)(rA + 8) * ldc + cc) = make_float2(v2, v3);
            } else {
                *(u32*)(O16 + (size_t)rA * ldc + cc)       = pack_h2(v0, v1);
                *(u32*)(O16 + (size_t)(rA + 8) * ldc + cc) = pack_h2(v2, v3);
            }
        }
    }
}

// ---------------- splits ---------------------------------------------------
__global__ __launch_bounds__(256) void split_x(
    const float* __restrict__ s, u16* __restrict__ x16)
{
    size_t i = ((size_t)blockIdx.x * 256 + threadIdx.x) * 4;
    float4 v = *(const float4*)(s + i);
    *(uint2*)(x16 + i) = make_uint2(pack_h2(v.x, v.y), pack_h2(v.z, v.w));
}

__global__ __launch_bounds__(256) void wsplit(
    const float* __restrict__ W, u16* __restrict__ O, int K, int N)
{
    __shared__ float t[32][33];
    int n0 = blockIdx.x * 32, k0 = blockIdx.y * 32;
    int tx = threadIdx.x & 31, ty = threadIdx.x >> 5;
    #pragma unroll
    for (int j = 0; j < 32; j += 8)
        t[ty + j][tx] = W[(size_t)(k0 + ty + j) * N + n0 + tx];
    __syncthreads();
    #pragma unroll
    for (int j = 0; j < 32; j += 8) {
        float v = t[tx][ty + j];
        O[(size_t)(n0 + ty + j) * K + k0 + tx] =
            __half_as_ushort(__float2half_rn(v));
    }
}

// ---------------- FFT path -------------------------------------------------
__global__ void fill_tw()
{
    int j = blockIdx.x * 256 + threadIdx.x;
    if (j < 1024) {
        float sv, cv;
        sincosf(-6.283185307179586f * (float)j / 2048.0f, &sv, &cv);
        g_twid[j] = make_float2(cv, sv);
    }
}

__global__ __launch_bounds__(256) void transpose_bt(
    const float* __restrict__ in, float* __restrict__ out)
{
    __shared__ float t[32][33];
    int b = blockIdx.z;
    int d0 = blockIdx.x * 32, t0 = blockIdx.y * 32;
    int tx = threadIdx.x & 31, ty = threadIdx.x >> 5;
    #pragma unroll
    for (int j = 0; j < 32; j += 8)
        t[ty + j][tx] = in[((size_t)b * LL + t0 + ty + j) * DD + d0 + tx];
    __syncthreads();
    #pragma unroll
    for (int j = 0; j < 32; j += 8)
        out[((size_t)b * DD + d0 + ty + j) * LL + t0 + tx] = t[tx][ty + j];
}

__device__ __forceinline__ void fft2048(float2* z, const float2* tw, int tid)
{
    #pragma unroll
    for (int s = 1; s <= 11; s++) {
        int half = 1 << (s - 1);
        for (int i = tid; i < 1024; i += 256) {
            int pos  = i & (half - 1);
            int idx0 = ((i >> (s - 1)) << s) + pos;
            int idx1 = idx0 + half;
            float2 w = tw[pos << (11 - s)];
            float2 u = z[idx0], v = z[idx1];
            float vr = v.x * w.x - v.y * w.y;
            float vi = v.x * w.y + v.y * w.x;
            z[idx0] = make_float2(u.x + vr, u.y + vi);
            z[idx1] = make_float2(u.x - vr, u.y - vi);
        }
        __syncthreads();
    }
}

// per (b, group of 4 channels): FFT(q + i k), accumulate T = conj(Qf)*Kf
#define CPB 4
__global__ __launch_bounds__(256) void fft_corr(
    const float* __restrict__ qT, const float* __restrict__ kT,
    float2* __restrict__ partial)
{
    extern __shared__ float2 smf[];
    float2* z   = smf;          // 2048
    float2* tw  = smf + 2048;   // 1024
    float2* acc = smf + 3072;   // 2048
    int tid = threadIdx.x, dg = blockIdx.x, b = blockIdx.y;

    for (int j = tid; j < 1024; j += 256) tw[j] = g_twid[j];
    for (int f = tid; f < 2048; f += 256) acc[f] = make_float2(0.f, 0.f);
    __syncthreads();

    for (int j = 0; j < CPB; j++) {
        int d = dg * CPB + j;
        const float* qr = qT + ((size_t)b * DD + d) * LL;
        const float* kr = kT + ((size_t)b * DD + d) * LL;
        for (int t = tid; t < 2048; t += 256) {
            int r = __brev((u32)t) >> 21;
            z[r] = make_float2(qr[t], kr[t]);
        }
        __syncthreads();
        fft2048(z, tw, tid);
        for (int f = tid; f < 2048; f += 256) {
            int m = (2048 - f) & 2047;
            float a = z[f].x, bb = z[f].y, c = z[m].x, d2 = z[m].y;
            float re = ((a + c) * (bb + d2) - (bb - d2) * (a - c)) * 0.25f;
            float im = -((a * a - c * c) + (bb * bb - d2 * d2)) * 0.25f;
            acc[f].x += re; acc[f].y += im;
        }
        __syncthreads();
    }
    float2* out = partial + ((size_t)b * (DD / CPB) + dg) * 2048;
    for (int f = tid; f < 2048; f += 256) out[f] = acc[f];
}

__global__ void reduce_spec(const float2* __restrict__ partial, float2* __restrict__ S)
{
    int idx = blockIdx.x * 256 + threadIdx.x;
    int b = idx >> 11, f = idx & 2047;
    float sx = 0.f, sy = 0.f;
    for (int dg = 0; dg < DD / CPB; dg++) {
        float2 p = partial[((size_t)b * (DD / CPB) + dg) * 2048 + f];
        sx += p.x; sy += p.y;
    }
    S[idx] = make_float2(sx, sy);
}

__global__ __launch_bounds__(256) void ifft_mv(const float2* __restrict__ S)
{
    extern __shared__ float2 smf[];
    float2* z  = smf;          // 2048
    float2* tw = smf + 2048;   // 1024
    int tid = threadIdx.x, b = blockIdx.x;
    for (int j = tid; j < 1024; j += 256) tw[j] = g_twid[j];
    for (int f = tid; f < 2048; f += 256) {
        int r = __brev((u32)f) >> 21;
        z[r] = S[b * 2048 + f];
    }
    __syncthreads();
    fft2048(z, tw, tid);
    const float sc = 1.0f / (2048.0f * 1024.0f);
    for (int l = tid; l < 2048; l += 256)
        g_mv[b * 2048 + l] = z[l].x * sc;
}

// ---------------- topk / roll / layernorm ---------------------------------
__global__ void topk_softmax()
{
    int b = blockIdx.x, tid = threadIdx.x;
    __shared__ float vals[LL];
    __shared__ float rv[256];
    __shared__ int   ri[256];
    __shared__ float topv[TOPK];
    __shared__ int   topi[TOPK];

    for (int i = tid; i < LL; i += 256) vals[i] = g_mv[b * LL + i];
    __syncthreads();
    for (int it = 0; it < TOPK; ++it) {
        float bv = -INFINITY; int bi = 0;
        for (int i = tid; i < LL; i += 256) {
            float v = vals[i];
            if (v > bv) { bv = v; bi = i; }
        }
        rv[tid] = bv; ri[tid] = bi;
        __syncthreads();
        for (int s = 128; s > 0; s >>= 1) {
            if (tid < s) {
                if (rv[tid+s] > rv[tid] ||
                    (rv[tid+s] == rv[tid] && ri[tid+s] < ri[tid])) {
                    rv[tid] = rv[tid+s]; ri[tid] = ri[tid+s];
                }
            }
            __syncthreads();
        }
        if (tid == 0) { topv[it] = rv[0]; topi[it] = ri[0]; vals[ri[0]] = -INFINITY; }
        __syncthreads();
    }
    if (tid == 0) {
        float mx = topv[0], e[TOPK], s = 0.f;
        #pragma unroll
        for (int i = 0; i < TOPK; i++) { e[i] = expf(topv[i] - mx); s += e[i]; }
        float inv = 1.f / s;
        #pragma unroll
        for (int i = 0; i < TOPK; i++) g_w[b * 8 + i] = e[i] * inv;
        if (b == 0)
            #pragma unroll
            for (int i = 0; i < TOPK; i++) g_delay[i] = topi[i];
    }
}

// rolled[b,l,:] = sum_i w[b,i]*v16[b,(l+d_i)%L,:] -> fp16 (t_r16)
__global__ __launch_bounds__(128) void roll_combine()
{
    int l = blockIdx.x, b = blockIdx.y, tid = threadIdx.x;
    float w[TOPK]; int rows[TOPK];
    #pragma unroll
    for (int i = 0; i < TOPK; i++) {
        w[i] = g_w[b * 8 + i];
        rows[i] = (l + g_delay[i]) & LMASK;
    }
    int d0 = tid * 8;
    float acc[8] = {0,0,0,0,0,0,0,0};
    #pragma unroll
    for (int i = 0; i < TOPK; i++) {
        const u16* vp = t_v16 + ((size_t)(b * LL + rows[i])) * DD + d0;
        uint4 pk = *(const uint4*)vp;
        __half2 h0 = *reinterpret_cast<__half2*>(&pk.x);
        __half2 h1 = *reinterpret_cast<__half2*>(&pk.y);
        __half2 h2 = *reinterpret_cast<__half2*>(&pk.z);
        __half2 h3 = *reinterpret_cast<__half2*>(&pk.w);
        float2 f0 = __half22float2(h0), f1 = __half22float2(h1);
        float2 f2 = __half22float2(h2), f3 = __half22float2(h3);
        acc[0] = fmaf(w[i], f0.x, acc[0]); acc[1] = fmaf(w[i], f0.y, acc[1]);
        acc[2] = fmaf(w[i], f1.x, acc[2]); acc[3] = fmaf(w[i], f1.y, acc[3]);
        acc[4] = fmaf(w[i], f2.x, acc[4]); acc[5] = fmaf(w[i], f2.y, acc[5]);
        acc[6] = fmaf(w[i], f3.x, acc[6]); acc[7] = fmaf(w[i], f3.y, acc[7]);
    }
    size_t base = (size_t)(b * LL + l) * DD + d0;
    uint4 o;
    o.x = pack_h2(acc[0], acc[1]); o.y = pack_h2(acc[2], acc[3]);
    o.z = pack_h2(acc[4], acc[5]); o.w = pack_h2(acc[6], acc[7]);
    *(uint4*)(t_r16 + base) = o;
}

// out = LN(A + B); SPLIT emits fp16 single too
template<int SPLIT>
__global__ __launch_bounds__(128) void add_ln(
    const float* __restrict__ A, const float* __restrict__ Bv,
    const float* __restrict__ g, const float* __restrict__ bt,
    float* __restrict__ out, u16* __restrict__ O16)
{
    int row = blockIdx.x, tid = threadIdx.x;
    const float* pa = A  + (size_t)row * DD;
    const float* pb = Bv + (size_t)row * DD;
    __shared__ float red[128];
    int c0 = tid * 8;

    float v[8];
    float4 a0 = *(const float4*)(pa + c0), a1 = *(const float4*)(pa + c0 + 4);
    float4 b0 = *(const float4*)(pb + c0), b1 = *(const float4*)(pb + c0 + 4);
    v[0]=a0.x+b0.x; v[1]=a0.y+b0.y; v[2]=a0.z+b0.z; v[3]=a0.w+b0.w;
    v[4]=a1.x+b1.x; v[5]=a1.y+b1.y; v[6]=a1.z+b1.z; v[7]=a1.w+b1.w;
    float s = 0.f;
    #pragma unroll
    for (int j = 0; j < 8; j++) s += v[j];
    red[tid] = s; __syncthreads();
    for (int st = 64; st > 0; st >>= 1) {
        if (tid < st) red[tid] += red[tid + st];
        __syncthreads();
    }
    float mean = red[0] * (1.f / (float)DD);
    __syncthreads();
    float vs = 0.f;
    #pragma unroll
    for (int j = 0; j < 8; j++) { float d = v[j] - mean; vs += d * d; }
    red[tid] = vs; __syncthreads();
    for (int st = 64; st > 0; st >>= 1) {
        if (tid < st) red[tid] += red[tid + st];
        __syncthreads();
    }
    float rstd = rsqrtf(red[0] * (1.f / (float)DD) + 1e-6f);

    float o[8];
    #pragma unroll
    for (int j = 0; j < 8; j++)
        o[j] = (v[j] - mean) * rstd * g[c0 + j] + bt[c0 + j];
    float* po = out + (size_t)row * DD;
    *(float4*)(po + c0)     = make_float4(o[0], o[1], o[2], o[3]);
    *(float4*)(po + c0 + 4) = make_float4(o[4], o[5], o[6], o[7]);

    if (SPLIT) {
        size_t base = (size_t)row * DD + c0;
        uint4 pk;
        pk.x = pack_h2(o[0], o[1]); pk.y = pack_h2(o[2], o[3]);
        pk.z = pack_h2(o[4], o[5]); pk.w = pack_h2(o[6], o[7]);
        *(uint4*)(O16 + base) = pk;
    }
}

// -------------------------------------------------------------------------
#define SYM(p, s) cudaGetSymbolAddress((void**)&p, s)

extern "C" void kernel_launch(void* const* d_in, const int* in_sizes, int n_in,
                              void* d_out, int out_size)
{
    const float* x    = (const float*)d_in[0];
    const float* Wq   = (const float*)d_in[1];
    const float* bq   = (const float*)d_in[2];
    const float* Wk   = (const float*)d_in[3];
    const float* bk   = (const float*)d_in[4];
    const float* Wv   = (const float*)d_in[5];
    const float* bv   = (const float*)d_in[6];
    const float* Wo   = (const float*)d_in[7];
    const float* bo   = (const float*)d_in[8];
    const float* ln1g = (const float*)d_in[9];
    const float* ln1b = (const float*)d_in[10];
    const float* c1w  = (const float*)d_in[11];
    const float* c1b  = (const float*)d_in[12];
    const float* c2w  = (const float*)d_in[13];
    const float* c2b  = (const float*)d_in[14];
    const float* ln2g = (const float*)d_in[15];
    const float* ln2b = (const float*)d_in[16];
    float* out = (float*)d_out;

    cudaFuncSetAttribute(gemm_h1<0>, cudaFuncAttributeMaxDynamicSharedMemorySize, GSMEM_H);
    cudaFuncSetAttribute(gemm_h1<1>, cudaFuncAttributeMaxDynamicSharedMemorySize, GSMEM_H);
    cudaFuncSetAttribute(gemm_h1<2>, cudaFuncAttributeMaxDynamicSharedMemorySize, GSMEM_H);

    u16 *x16, *v16, *r16, *x116, *hh, *hl;
    u16 *wq16, *wk16, *wv16, *wo16, *c116, *c216;
    float *v, *G, *x1, *part;
    SYM(x16, t_x16);
    SYM(v16, t_v16);
    SYM(r16, t_r16);
    SYM(x116, t_x116);
    SYM(hh, t_h_hi);  SYM(hl, t_h_lo);
    SYM(wq16, t_wq);  SYM(wk16, t_wk);
    SYM(wv16, t_wv);  SYM(wo16, t_wo);
    SYM(c116, t_c1);  SYM(c216, t_c2);
    SYM(v, g_v); SYM(G, g_G); SYM(x1, g_x1); SYM(part, g_part);

    float* fq = G;                         // fp32 q
    float* fk = G + (size_t)MM * DD;       // fp32 k
    float* qT = (float*)hh;                // transposed q (aliases t_h_hi)
    float* kT = (float*)hl;                // transposed k (aliases t_h_lo)
    float2* partials = (float2*)x1;        // FFT partials (aliases g_x1; 32MB fits)
    float2* S = (float2*)part;             // reduced spectrum

    // splits + twiddle table
    fill_tw<<<4, 256>>>();
    split_x<<<(MM*DD)/1024, 256>>>(x, x16);
    wsplit<<<dim3(DD/32, DD/32), 256>>>(Wq, wq16, DD, DD);
    wsplit<<<dim3(DD/32, DD/32), 256>>>(Wk, wk16, DD, DD);
    wsplit<<<dim3(DD/32, DD/32), 256>>>(Wv, wv16, DD, DD);
    wsplit<<<dim3(DD/32, DD/32), 256>>>(Wo, wo16, DD, DD);
    wsplit<<<dim3(FF/32, DD/32), 256>>>(c1w, c116, DD, FF);
    wsplit<<<dim3(DD/32, FF/32), 256>>>(c2w, c216, FF, DD);

    // QKV: fp16 1-term (q,k fp32 out for FFT; v fp16 out)
    gemm_h1<0><<<dim3(8,128), 256, GSMEM_H>>>(x16, wq16, bq, fq, nullptr, DD, DD);
    gemm_h1<0><<<dim3(8,128), 256, GSMEM_H>>>(x16, wk16, bk, fk, nullptr, DD, DD);
    gemm_h1<1><<<dim3(8,128), 256, GSMEM_H>>>(x16, wv16, bv, nullptr, v16, DD, DD);

    // mean_value via FFT correlation
    transpose_bt<<<dim3(DD/32, LL/32, BB), 256>>>(fq, qT);
    transpose_bt<<<dim3(DD/32, LL/32, BB), 256>>>(fk, kT);
    fft_corr<<<dim3(DD/CPB, BB), 256, 5120 * sizeof(float2)>>>(qT, kT, partials);
    reduce_spec<<<(BB*LL)/256, 256>>>(partials, S);
    ifft_mv<<<BB, 256, 3072 * sizeof(float2)>>>(S);

    topk_softmax<<<BB, 256>>>();
    roll_combine<<<dim3(LL, BB), 128>>>();   // v16 -> t_r16 fp16

    // attn = rolled @ Wo + bo  (fp32 into g_v)
    gemm_h1<0><<<dim3(8,128), 256, GSMEM_H>>>(r16, wo16, bo, v, nullptr, DD, DD);

    // x1 = LN(x + attn) (+ fp16 single)
    add_ln<1><<<MM, 128>>>(x, v, ln1g, ln1b, x1, x116);

    // h = relu(x1 @ c1 + b)  -> fp16 into t_h_hi (qT dead)
    gemm_h1<2><<<dim3(32,128), 256, GSMEM_H>>>(x116, c116, c1b, nullptr, hh, DD, FF);

    // y = h @ c2 + b  (fp32 into G, dead)
    gemm_h1<0><<<dim3(8,128), 256, GSMEM_H>>>(hh, c216, c2b, G, nullptr, FF, DD);

    // out = LN(x1 + y)
    add_ln<0><<<MM, 128>>>(x1, G, ln2g, ln2b, out, nullptr);
}

// round 17
// speedup vs baseline: 3.1448x; 1.0369x over previous
#include <cuda_runtime.h>
#include <cuda_fp16.h>
#include <math.h>

#define BB 8
#define LL 2048
#define DD 1024
#define FF 4096
#define MM 16384
#define TOPK 7
#define LMASK 2047

typedef unsigned short u16;
typedef unsigned int   u32;

// ---------------- device scratch (no allocation) --------------------------
__device__ u16 t_x16[(size_t)MM*DD];                            // x fp16
__device__ u16 t_v16[(size_t)MM*DD];                            // v fp16
__device__ u16 t_r16[(size_t)MM*DD];                            // rolled fp16
__device__ u16 t_x116[(size_t)MM*DD];                           // x1 fp16
__device__ u16 t_h_hi[(size_t)MM*FF], t_h_lo[(size_t)MM*FF];    // h fp16 / qT,kT fp16
__device__ u16 t_wq[DD*DD], t_wk[DD*DD], t_wv[DD*DD], t_wo[DD*DD];  // fp16 [N,K]
__device__ u16 t_c1[(size_t)FF*DD], t_c2[(size_t)DD*FF];            // fp16 [N,K]

__device__ float g_v[(size_t)MM*DD];     // attn fp32
__device__ float g_G[(size_t)BB*LL*LL];  // y fp32 (tail); plenty spare
__device__ float g_x1[(size_t)MM*DD];    // FFT partials early; x1 fp32 later
__device__ float g_part[BB*8*LL];        // reduced spectrum (float2)
__device__ float g_mv[BB*LL];
__device__ float g_w[BB*8];
__device__ int   g_delay[8];
__device__ float2 g_twid[1024];          // FFT twiddle table

// ---------------- helpers --------------------------------------------------
__device__ __forceinline__ u32 smem_u32(const void* p) {
    u32 a;
    asm("{ .reg .u64 t; cvta.to.shared.u64 t, %1; cvt.u32.u64 %0, t; }"
        : "=r"(a) : "l"(p));
    return a;
}

__device__ __forceinline__ u32 pack_h2(float v0, float v1) {
    __half2 p = __floats2half2_rn(v0, v1);
    return *reinterpret_cast<u32*>(&p);
}

#define CPA(sa, gp) \
    asm volatile("cp.async.cg.shared.global [%0], [%1], 16;" \
        :: "r"(sa), "l"(gp))

#define MMA_H(c, a, b) \
    asm volatile("mma.sync.aligned.m16n8k16.row.col.f32.f16.f16.f32 " \
        "{%0,%1,%2,%3},{%4,%5,%6,%7},{%8,%9},{%0,%1,%2,%3};" \
        : "+f"((c)[0]), "+f"((c)[1]), "+f"((c)[2]), "+f"((c)[3]) \
        : "r"((a)[0]), "r"((a)[1]), "r"((a)[2]), "r"((a)[3]), \
          "r"((b)[0]), "r"((b)[1]))

#define LDSM4(r, a) \
    asm volatile("ldmatrix.sync.aligned.m8n8.x4.shared.b16 {%0,%1,%2,%3}, [%4];" \
        : "=r"((r)[0]), "=r"((r)[1]), "=r"((r)[2]), "=r"((r)[3]) : "r"(a))
#define LDSM2(r, a) \
    asm volatile("ldmatrix.sync.aligned.m8n8.x2.shared.b16 {%0,%1}, [%2];" \
        : "=r"((r)[0]), "=r"((r)[1]) : "r"(a))

// ---------------- fp16 1-term GEMM: C = A16 @ B16^T (+bias,+relu) --------
// CTA 128x128, 8 warps (2x4) x (64x32), KC=64, 3-stage cp.async, 2 CTA/SM.
#define KC 64
#define PADH 72
#define H_OFF_B 18432u           // 128*72*2
#define H_STAGE 36864u
#define GSMEM_H (3*36864)
#define PADT 136                 // transposed-stage row stride (u16)

// OMODE: 0 = fp32 out, 1 = fp16 out, 2 = fp16+relu out,
//        3 = fp16 TRANSPOSED out: O16[(b*DD + n)*LL + t], rows = b*LL + t
template<int OMODE>
__global__ __launch_bounds__(256, 2) void gemm_h1(
    const u16* __restrict__ A16, const u16* __restrict__ B16,
    const float* __restrict__ bias, float* __restrict__ C,
    u16* __restrict__ O16, int K, int ldc)
{
    extern __shared__ u16 sm[];
    const int tid = threadIdx.x;
    const int lane = tid & 31, warp = tid >> 5;
    const int wm = warp >> 2, wn = warp & 3;
    const int bx = blockIdx.x, by = blockIdx.y;

    const u16* Ap = A16 + (size_t)(by * 128) * K;
    const u16* Bp = B16 + (size_t)(bx * 128) * K;

    const u32 smBase = smem_u32(sm);
    const int nC = K >> 6;

    float acc[4][4][4];
    #pragma unroll
    for (int i = 0; i < 4; i++)
        #pragma unroll
        for (int j = 0; j < 4; j++)
            #pragma unroll
            for (int p = 0; p < 4; p++) acc[i][j][p] = 0.f;

    auto load_chunk = [&](int c, int s) {
        u32 st = smBase + (u32)s * H_STAGE;
        int k0 = c * KC;
        #pragma unroll
        for (int t = 0; t < 4; t++) {
            int idx = (t << 8) + tid;
            int row = idx >> 3, c16 = idx & 7;
            size_t go = (size_t)row * K + k0 + c16 * 8;
            u32 off = (u32)(row * PADH + c16 * 8) * 2;
            CPA(st + off, Ap + go);
            CPA(st + H_OFF_B + off, Bp + go);
        }
        asm volatile("cp.async.commit_group;" ::: "memory");
    };

    load_chunk(0, 0);
    if (nC > 1) load_chunk(1, 1);

    for (int c = 0; c < nC; c++) {
        if (c == nC - 1) asm volatile("cp.async.wait_group 0;" ::: "memory");
        else             asm volatile("cp.async.wait_group 1;" ::: "memory");
        __syncthreads();
        if (c + 2 < nC) load_chunk(c + 2, (c + 2) % 3);

        u32 st = smBase + (u32)(c % 3) * H_STAGE;
        #pragma unroll
        for (int ks = 0; ks < 4; ks++) {
            int ko = ks * 16;
            u32 b_f[4][2];
            #pragma unroll
            for (int ni = 0; ni < 4; ni++) {
                int r = wn * 32 + ni * 8 + (lane & 7);
                int kk = ko + (((lane >> 3) & 1) << 3);
                LDSM2(b_f[ni], st + H_OFF_B + (u32)(r * PADH + kk) * 2);
            }
            #pragma unroll
            for (int mi = 0; mi < 4; mi++) {
                int r = wm * 64 + mi * 16 + (lane & 15);
                int kk = ko + ((lane >> 4) << 3);
                u32 a[4];
                LDSM4(a, st + (u32)(r * PADH + kk) * 2);
                #pragma unroll
                for (int ni = 0; ni < 4; ni++)
                    MMA_H(acc[mi][ni], a, b_f[ni]);
            }
        }
    }

    if (OMODE == 3) {
        // stage fp16 transposed tile [channel][time] then coalesced write
        __syncthreads();
        #pragma unroll
        for (int mi = 0; mi < 4; mi++) {
            #pragma unroll
            for (int ni = 0; ni < 4; ni++) {
                int rl = wm * 64 + mi * 16 + (lane >> 2);
                int cl = wn * 32 + ni * 8 + (lane & 3) * 2;
                float v0 = acc[mi][ni][0], v1 = acc[mi][ni][1];
                float v2 = acc[mi][ni][2], v3 = acc[mi][ni][3];
                if (bias) {
                    int cc = bx * 128 + cl;
                    float bb0 = __ldg(bias + cc), bb1 = __ldg(bias + cc + 1);
                    v0 += bb0; v1 += bb1; v2 += bb0; v3 += bb1;
                }
                sm[(u32)cl * PADT + rl]           = __half_as_ushort(__float2half_rn(v0));
                sm[(u32)(cl + 1) * PADT + rl]     = __half_as_ushort(__float2half_rn(v1));
                sm[(u32)cl * PADT + rl + 8]       = __half_as_ushort(__float2half_rn(v2));
                sm[(u32)(cl + 1) * PADT + rl + 8] = __half_as_ushort(__float2half_rn(v3));
            }
        }
        __syncthreads();
        int bb = (by * 128) >> 11;           // batch (tile never crosses)
        int t0 = (by * 128) & LMASK;         // time base
        for (int idx = tid; idx < 2048; idx += 256) {
            int ch = idx >> 4, tc = (idx & 15) * 8;
            uint4 val = *(uint4*)&sm[(u32)ch * PADT + tc];
            *(uint4*)(O16 + ((size_t)(bb * DD + bx * 128 + ch)) * LL + t0 + tc) = val;
        }
        return;
    }

    const int r0 = by * 128 + wm * 64;
    const int c0b = bx * 128 + wn * 32;
    #pragma unroll
    for (int mi = 0; mi < 4; mi++) {
        #pragma unroll
        for (int ni = 0; ni < 4; ni++) {
            int rA = r0 + mi * 16 + (lane >> 2);
            int cc = c0b + ni * 8 + (lane & 3) * 2;
            float v0 = acc[mi][ni][0], v1 = acc[mi][ni][1];
            float v2 = acc[mi][ni][2], v3 = acc[mi][ni][3];
            if (bias) {
                float bb0 = __ldg(bias + cc), bb1 = __ldg(bias + cc + 1);
                v0 += bb0; v1 += bb1; v2 += bb0; v3 += bb1;
            }
            if (OMODE == 2) {
                v0 = fmaxf(v0, 0.f); v1 = fmaxf(v1, 0.f);
                v2 = fmaxf(v2, 0.f); v3 = fmaxf(v3, 0.f);
            }
            if (OMODE == 0) {
                *(float2*)(C + (size_t)rA * ldc + cc)       = make_float2(v0, v1);
                *(float2*)(C + (size_t)(rA + 8) * ldc + cc) = make_float2(v2, v3);
            } else {
                *(u32*)(O16 + (size_t)rA * ldc + cc)       = pack_h2(v0, v1);
                *(u32*)(O16 + (size_t)(rA + 8) * ldc + cc) = pack_h2(v2, v3);
            }
        }
    }
}

// ---------------- splits ---------------------------------------------------
__global__ __launch_bounds__(256) void split_x(
    const float* __restrict__ s, u16* __restrict__ x16)
{
    size_t i = ((size_t)blockIdx.x * 256 + threadIdx.x) * 4;
    float4 v = *(const float4*)(s + i);
    *(uint2*)(x16 + i) = make_uint2(pack_h2(v.x, v.y), pack_h2(v.z, v.w));
}

__global__ __launch_bounds__(256) void wsplit(
    const float* __restrict__ W, u16* __restrict__ O, int K, int N)
{
    __shared__ float t[32][33];
    int n0 = blockIdx.x * 32, k0 = blockIdx.y * 32;
    int tx = threadIdx.x & 31, ty = threadIdx.x >> 5;
    #pragma unroll
    for (int j = 0; j < 32; j += 8)
        t[ty + j][tx] = W[(size_t)(k0 + ty + j) * N + n0 + tx];
    __syncthreads();
    #pragma unroll
    for (int j = 0; j < 32; j += 8) {
        float v = t[tx][ty + j];
        O[(size_t)(n0 + ty + j) * K + k0 + tx] =
            __half_as_ushort(__float2half_rn(v));
    }
}

// ---------------- FFT path -------------------------------------------------
__global__ void fill_tw()
{
    int j = blockIdx.x * 256 + threadIdx.x;
    if (j < 1024) {
        float sv, cv;
        sincosf(-6.283185307179586f * (float)j / 2048.0f, &sv, &cv);
        g_twid[j] = make_float2(cv, sv);
    }
}

__device__ __forceinline__ void fft2048(float2* z, const float2* tw, int tid)
{
    #pragma unroll
    for (int s = 1; s <= 11; s++) {
        int half = 1 << (s - 1);
        for (int i = tid; i < 1024; i += 256) {
            int pos  = i & (half - 1);
            int idx0 = ((i >> (s - 1)) << s) + pos;
            int idx1 = idx0 + half;
            float2 w = tw[pos << (11 - s)];
            float2 u = z[idx0], v = z[idx1];
            float vr = v.x * w.x - v.y * w.y;
            float vi = v.x * w.y + v.y * w.x;
            z[idx0] = make_float2(u.x + vr, u.y + vi);
            z[idx1] = make_float2(u.x - vr, u.y - vi);
        }
        __syncthreads();
    }
}

// per (b, group of 4 channels): FFT(q + i k), accumulate T = conj(Qf)*Kf
#define CPB 4
__global__ __launch_bounds__(256) void fft_corr(
    const u16* __restrict__ qT, const u16* __restrict__ kT,
    float2* __restrict__ partial)
{
    extern __shared__ float2 smf[];
    float2* z   = smf;          // 2048
    float2* tw  = smf + 2048;   // 1024
    float2* acc = smf + 3072;   // 2048
    int tid = threadIdx.x, dg = blockIdx.x, b = blockIdx.y;

    for (int j = tid; j < 1024; j += 256) tw[j] = g_twid[j];
    for (int f = tid; f < 2048; f += 256) acc[f] = make_float2(0.f, 0.f);
    __syncthreads();

    for (int j = 0; j < CPB; j++) {
        int d = dg * CPB + j;
        const u16* qr = qT + ((size_t)b * DD + d) * LL;
        const u16* kr = kT + ((size_t)b * DD + d) * LL;
        for (int i = tid; i < 1024; i += 256) {
            u32 qw = *(const u32*)(qr + 2 * i);
            u32 kw = *(const u32*)(kr + 2 * i);
            float2 qf = __half22float2(*reinterpret_cast<__half2*>(&qw));
            float2 kf = __half22float2(*reinterpret_cast<__half2*>(&kw));
            int r0 = __brev((u32)(2 * i)) >> 21;
            int r1 = __brev((u32)(2 * i + 1)) >> 21;
            z[r0] = make_float2(qf.x, kf.x);
            z[r1] = make_float2(qf.y, kf.y);
        }
        __syncthreads();
        fft2048(z, tw, tid);
        for (int f = tid; f < 2048; f += 256) {
            int m = (2048 - f) & 2047;
            float a = z[f].x, bb = z[f].y, c = z[m].x, d2 = z[m].y;
            float re = ((a + c) * (bb + d2) - (bb - d2) * (a - c)) * 0.25f;
            float im = -((a * a - c * c) + (bb * bb - d2 * d2)) * 0.25f;
            acc[f].x += re; acc[f].y += im;
        }
        __syncthreads();
    }
    float2* out = partial + ((size_t)b * (DD / CPB) + dg) * 2048;
    for (int f = tid; f < 2048; f += 256) out[f] = acc[f];
}

__global__ void reduce_spec(const float2* __restrict__ partial, float2* __restrict__ S)
{
    int idx = blockIdx.x * 256 + threadIdx.x;
    int b = idx >> 11, f = idx & 2047;
    float sx = 0.f, sy = 0.f;
    for (int dg = 0; dg < DD / CPB; dg++) {
        float2 p = partial[((size_t)b * (DD / CPB) + dg) * 2048 + f];
        sx += p.x; sy += p.y;
    }
    S[idx] = make_float2(sx, sy);
}

__global__ __launch_bounds__(256) void ifft_mv(const float2* __restrict__ S)
{
    extern __shared__ float2 smf[];
    float2* z  = smf;          // 2048
    float2* tw = smf + 2048;   // 1024
    int tid = threadIdx.x, b = blockIdx.x;
    for (int j = tid; j < 1024; j += 256) tw[j] = g_twid[j];
    for (int f = tid; f < 2048; f += 256) {
        int r = __brev((u32)f) >> 21;
        z[r] = S[b * 2048 + f];
    }
    __syncthreads();
    fft2048(z, tw, tid);
    const float sc = 1.0f / (2048.0f * 1024.0f);
    for (int l = tid; l < 2048; l += 256)
        g_mv[b * 2048 + l] = z[l].x * sc;
}

// ---------------- topk / roll / layernorm ---------------------------------
__global__ void topk_softmax()
{
    int b = blockIdx.x, tid = threadIdx.x;
    __shared__ float vals[LL];
    __shared__ float rv[256];
    __shared__ int   ri[256];
    __shared__ float topv[TOPK];
    __shared__ int   topi[TOPK];

    for (int i = tid; i < LL; i += 256) vals[i] = g_mv[b * LL + i];
    __syncthreads();
    for (int it = 0; it < TOPK; ++it) {
        float bv = -INFINITY; int bi = 0;
        for (int i = tid; i < LL; i += 256) {
            float v = vals[i];
            if (v > bv) { bv = v; bi = i; }
        }
        rv[tid] = bv; ri[tid] = bi;
        __syncthreads();
        for (int s = 128; s > 0; s >>= 1) {
            if (tid < s) {
                if (rv[tid+s] > rv[tid] ||
                    (rv[tid+s] == rv[tid] && ri[tid+s] < ri[tid])) {
                    rv[tid] = rv[tid+s]; ri[tid] = ri[tid+s];
                }
            }
            __syncthreads();
        }
        if (tid == 0) { topv[it] = rv[0]; topi[it] = ri[0]; vals[ri[0]] = -INFINITY; }
        __syncthreads();
    }
    if (tid == 0) {
        float mx = topv[0], e[TOPK], s = 0.f;
        #pragma unroll
        for (int i = 0; i < TOPK; i++) { e[i] = expf(topv[i] - mx); s += e[i]; }
        float inv = 1.f / s;
        #pragma unroll
        for (int i = 0; i < TOPK; i++) g_w[b * 8 + i] = e[i] * inv;
        if (b == 0)
            #pragma unroll
            for (int i = 0; i < TOPK; i++) g_delay[i] = topi[i];
    }
}

// rolled[b,l,:] = sum_i w[b,i]*v16[b,(l+d_i)%L,:] -> fp16 (t_r16)
__global__ __launch_bounds__(128) void roll_combine()
{
    int l = blockIdx.x, b = blockIdx.y, tid = threadIdx.x;
    float w[TOPK]; int rows[TOPK];
    #pragma unroll
    for (int i = 0; i < TOPK; i++) {
        w[i] = g_w[b * 8 + i];
        rows[i] = (l + g_delay[i]) & LMASK;
    }
    int d0 = tid * 8;
    float acc[8] = {0,0,0,0,0,0,0,0};
    #pragma unroll
    for (int i = 0; i < TOPK; i++) {
        const u16* vp = t_v16 + ((size_t)(b * LL + rows[i])) * DD + d0;
        uint4 pk = *(const uint4*)vp;
        __half2 h0 = *reinterpret_cast<__half2*>(&pk.x);
        __half2 h1 = *reinterpret_cast<__half2*>(&pk.y);
        __half2 h2 = *reinterpret_cast<__half2*>(&pk.z);
        __half2 h3 = *reinterpret_cast<__half2*>(&pk.w);
        float2 f0 = __half22float2(h0), f1 = __half22float2(h1);
        float2 f2 = __half22float2(h2), f3 = __half22float2(h3);
        acc[0] = fmaf(w[i], f0.x, acc[0]); acc[1] = fmaf(w[i], f0.y, acc[1]);
        acc[2] = fmaf(w[i], f1.x, acc[2]); acc[3] = fmaf(w[i], f1.y, acc[3]);
        acc[4] = fmaf(w[i], f2.x, acc[4]); acc[5] = fmaf(w[i], f2.y, acc[5]);
        acc[6] = fmaf(w[i], f3.x, acc[6]); acc[7] = fmaf(w[i], f3.y, acc[7]);
    }
    size_t base = (size_t)(b * LL + l) * DD + d0;
    uint4 o;
    o.x = pack_h2(acc[0], acc[1]); o.y = pack_h2(acc[2], acc[3]);
    o.z = pack_h2(acc[4], acc[5]); o.w = pack_h2(acc[6], acc[7]);
    *(uint4*)(t_r16 + base) = o;
}

// out = LN(A + B); SPLIT emits fp16 single too
template<int SPLIT>
__global__ __launch_bounds__(128) void add_ln(
    const float* __restrict__ A, const float* __restrict__ Bv,
    const float* __restrict__ g, const float* __restrict__ bt,
    float* __restrict__ out, u16* __restrict__ O16)
{
    int row = blockIdx.x, tid = threadIdx.x;
    const float* pa = A  + (size_t)row * DD;
    const float* pb = Bv + (size_t)row * DD;
    __shared__ float red[128];
    int c0 = tid * 8;

    float v[8];
    float4 a0 = *(const float4*)(pa + c0), a1 = *(const float4*)(pa + c0 + 4);
    float4 b0 = *(const float4*)(pb + c0), b1 = *(const float4*)(pb + c0 + 4);
    v[0]=a0.x+b0.x; v[1]=a0.y+b0.y; v[2]=a0.z+b0.z; v[3]=a0.w+b0.w;
    v[4]=a1.x+b1.x; v[5]=a1.y+b1.y; v[6]=a1.z+b1.z; v[7]=a1.w+b1.w;
    float s = 0.f;
    #pragma unroll
    for (int j = 0; j < 8; j++) s += v[j];
    red[tid] = s; __syncthreads();
    for (int st = 64; st > 0; st >>= 1) {
        if (tid < st) red[tid] += red[tid + st];
        __syncthreads();
    }
    float mean = red[0] * (1.f / (float)DD);
    __syncthreads();
    float vs = 0.f;
    #pragma unroll
    for (int j = 0; j < 8; j++) { float d = v[j] - mean; vs += d * d; }
    red[tid] = vs; __syncthreads();
    for (int st = 64; st > 0; st >>= 1) {
        if (tid < st) red[tid] += red[tid + st];
        __syncthreads();
    }
    float rstd = rsqrtf(red[0] * (1.f / (float)DD) + 1e-6f);

    float o[8];
    #pragma unroll
    for (int j = 0; j < 8; j++)
        o[j] = (v[j] - mean) * rstd * g[c0 + j] + bt[c0 + j];
    float* po = out + (size_t)row * DD;
    *(float4*)(po + c0)     = make_float4(o[0], o[1], o[2], o[3]);
    *(float4*)(po + c0 + 4) = make_float4(o[4], o[5], o[6], o[7]);

    if (SPLIT) {
        size_t base = (size_t)row * DD + c0;
        uint4 pk;
        pk.x = pack_h2(o[0], o[1]); pk.y = pack_h2(o[2], o[3]);
        pk.z = pack_h2(o[4], o[5]); pk.w = pack_h2(o[6], o[7]);
        *(uint4*)(O16 + base) = pk;
    }
}

// -------------------------------------------------------------------------
#define SYM(p, s) cudaGetSymbolAddress((void**)&p, s)

extern "C" void kernel_launch(void* const* d_in, const int* in_sizes, int n_in,
                              void* d_out, int out_size)
{
    const float* x    = (const float*)d_in[0];
    const float* Wq   = (const float*)d_in[1];
    const float* bq   = (const float*)d_in[2];
    const float* Wk   = (const float*)d_in[3];
    const float* bk   = (const float*)d_in[4];
    const float* Wv   = (const float*)d_in[5];
    const float* bv   = (const float*)d_in[6];
    const float* Wo   = (const float*)d_in[7];
    const float* bo   = (const float*)d_in[8];
    const float* ln1g = (const float*)d_in[9];
    const float* ln1b = (const float*)d_in[10];
    const float* c1w  = (const float*)d_in[11];
    const float* c1b  = (const float*)d_in[12];
    const float* c2w  = (const float*)d_in[13];
    const float* c2b  = (const float*)d_in[14];
    const float* ln2g = (const float*)d_in[15];
    const float* ln2b = (const float*)d_in[16];
    float* out = (float*)d_out;

    cudaFuncSetAttribute(gemm_h1<0>, cudaFuncAttributeMaxDynamicSharedMemorySize, GSMEM_H);
    cudaFuncSetAttribute(gemm_h1<1>, cudaFuncAttributeMaxDynamicSharedMemorySize, GSMEM_H);
    cudaFuncSetAttribute(gemm_h1<2>, cudaFuncAttributeMaxDynamicSharedMemorySize, GSMEM_H);
    cudaFuncSetAttribute(gemm_h1<3>, cudaFuncAttributeMaxDynamicSharedMemorySize, GSMEM_H);

    u16 *x16, *v16, *r16, *x116, *hh, *hl;
    u16 *wq16, *wk16, *wv16, *wo16, *c116, *c216;
    float *v, *G, *x1, *part;
    SYM(x16, t_x16);
    SYM(v16, t_v16);
    SYM(r16, t_r16);
    SYM(x116, t_x116);
    SYM(hh, t_h_hi);  SYM(hl, t_h_lo);
    SYM(wq16, t_wq);  SYM(wk16, t_wk);
    SYM(wv16, t_wv);  SYM(wo16, t_wo);
    SYM(c116, t_c1);  SYM(c216, t_c2);
    SYM(v, g_v); SYM(G, g_G); SYM(x1, g_x1); SYM(part, g_part);

    u16* qT = hh;                          // fp16 qT[b*DD+d][t] (aliases t_h_hi)
    u16* kT = hl;                          // fp16 kT (aliases t_h_lo)
    float2* partials = (float2*)x1;        // FFT partials (aliases g_x1)
    float2* S = (float2*)part;             // reduced spectrum

    // splits + twiddle table
    fill_tw<<<4, 256>>>();
    split_x<<<(MM*DD)/1024, 256>>>(x, x16);
    wsplit<<<dim3(DD/32, DD/32), 256>>>(Wq, wq16, DD, DD);
    wsplit<<<dim3(DD/32, DD/32), 256>>>(Wk, wk16, DD, DD);
    wsplit<<<dim3(DD/32, DD/32), 256>>>(Wv, wv16, DD, DD);
    wsplit<<<dim3(DD/32, DD/32), 256>>>(Wo, wo16, DD, DD);
    wsplit<<<dim3(FF/32, DD/32), 256>>>(c1w, c116, DD, FF);
    wsplit<<<dim3(DD/32, FF/32), 256>>>(c2w, c216, FF, DD);

    // QKV: q,k write fp16 TRANSPOSED for FFT; v fp16 row-major
    gemm_h1<3><<<dim3(8,128), 256, GSMEM_H>>>(x16, wq16, bq, nullptr, qT, DD, DD);
    gemm_h1<3><<<dim3(8,128), 256, GSMEM_H>>>(x16, wk16, bk, nullptr, kT, DD, DD);
    gemm_h1<1><<<dim3(8,128), 256, GSMEM_H>>>(x16, wv16, bv, nullptr, v16, DD, DD);

    // mean_value via FFT correlation (no transpose kernels anymore)
    fft_corr<<<dim3(DD/CPB, BB), 256, 5120 * sizeof(float2)>>>(qT, kT, partials);
    reduce_spec<<<(BB*LL)/256, 256>>>(partials, S);
    ifft_mv<<<BB, 256, 3072 * sizeof(float2)>>>(S);

    topk_softmax<<<BB, 256>>>();
    roll_combine<<<dim3(LL, BB), 128>>>();   // v16 -> t_r16 fp16

    // attn = rolled @ Wo + bo  (fp32 into g_v)
    gemm_h1<0><<<dim3(8,128), 256, GSMEM_H>>>(r16, wo16, bo, v, nullptr, DD, DD);

    // x1 = LN(x + attn) (+ fp16 single)
    add_ln<1><<<MM, 128>>>(x, v, ln1g, ln1b, x1, x116);

    // h = relu(x1 @ c1 + b)  -> fp16 into t_h_hi (qT dead)
    gemm_h1<2><<<dim3(32,128), 256, GSMEM_H>>>(x116, c116, c1b, nullptr, hh, DD, FF);

    // y = h @ c2 + b  (fp32 into G)
    gemm_h1<0><<<dim3(8,128), 256, GSMEM_H>>>(hh, c216, c2b, G, nullptr, FF, DD);

    // out = LN(x1 + y)
    add_ln<0><<<MM, 128>>>(x1, G, ln2g, ln2b, out, nullptr);
}